// round 7
// baseline (speedup 1.0000x reference)
#include <cuda_runtime.h>
#include <cuda_fp16.h>
#include <math.h>
#include <stdint.h>

// ---------------- problem constants ----------------
#define S_TOK   4096
#define CDIM    1024
#define EXP     64
#define TOPK    8
#define NGRP    8
#define EPG     8
#define TGRP    4
#define HDIM    512
#define HSHARED 2048
#define NROWS   (S_TOK * TOPK)   // 32768
#define MAX_TILES 320

// ---------------- scratch (static device globals) ----------------
struct TileDesc { int e; int row_start; int rows; };

__device__ int      g_counts[EXP];
__device__ int      g_offsets[EXP + 1];
__device__ int      g_cursor[EXP];
__device__ TileDesc g_tiles[MAX_TILES];
__device__ int      g_ntiles;
__device__ int      g_rowmap[NROWS];
__device__ int      g_topk_idx[NROWS];
__device__ float    g_topk_w[NROWS];

__device__ __half   g_hbuf[(size_t)NROWS * HDIM];       // fused swiglu output (routed)
__device__ float    g_rows_out[(size_t)NROWS * CDIM];
__device__ __half   g_sh_h[(size_t)S_TOK * HSHARED];    // fused swiglu output (shared)
__device__ float    g_shared_out[(size_t)S_TOK * CDIM];
__device__ __half   g_x_r[(size_t)S_TOK * CDIM];

// fp16 weight copies (native [K][N] layouts preserved)
__device__ __half   g_w_gate[(size_t)EXP * CDIM * HDIM];
__device__ __half   g_w_up[(size_t)EXP * CDIM * HDIM];
__device__ __half   g_w_down[(size_t)EXP * HDIM * CDIM];
__device__ __half   g_w_shg[(size_t)CDIM * HSHARED];
__device__ __half   g_w_shu[(size_t)CDIM * HSHARED];
__device__ __half   g_w_shd[(size_t)HSHARED * CDIM];

// ---------------- helpers ----------------
__device__ __forceinline__ void mma_f16(float* c, const uint32_t* a, const uint32_t* b) {
    asm volatile(
        "mma.sync.aligned.m16n8k16.row.col.f32.f16.f16.f32 "
        "{%0,%1,%2,%3}, {%4,%5,%6,%7}, {%8,%9}, {%0,%1,%2,%3};"
        : "+f"(c[0]), "+f"(c[1]), "+f"(c[2]), "+f"(c[3])
        : "r"(a[0]), "r"(a[1]), "r"(a[2]), "r"(a[3]), "r"(b[0]), "r"(b[1]));
}
__device__ __forceinline__ void ldmatrix_x4(uint32_t* r, uint32_t addr) {
    asm volatile("ldmatrix.sync.aligned.m8n8.x4.shared.b16 {%0,%1,%2,%3}, [%4];"
                 : "=r"(r[0]), "=r"(r[1]), "=r"(r[2]), "=r"(r[3]) : "r"(addr));
}
__device__ __forceinline__ void ldmatrix_x4_trans(uint32_t* r, uint32_t addr) {
    asm volatile("ldmatrix.sync.aligned.m8n8.x4.trans.shared.b16 {%0,%1,%2,%3}, [%4];"
                 : "=r"(r[0]), "=r"(r[1]), "=r"(r[2]), "=r"(r[3]) : "r"(addr));
}
__device__ __forceinline__ void cp_async16(uint32_t dst, const void* src, int srcbytes) {
    asm volatile("cp.async.cg.shared.global [%0], [%1], 16, %2;"
                 :: "r"(dst), "l"(src), "r"(srcbytes));
}

// ---------------- prep: f32 -> f16 convert copy ----------------
__global__ void half_copy(const float4* __restrict__ src, __half2* __restrict__ dst,
                          long long n4) {
    long long i = (long long)blockIdx.x * blockDim.x + threadIdx.x;
    if (i >= n4) return;
    float4 v = src[i];
    dst[i * 2 + 0] = __floats2half2_rn(v.x, v.y);
    dst[i * 2 + 1] = __floats2half2_rn(v.z, v.w);
}

// ---------------- routing kernels (verified correct) ----------------
__global__ void zero_counts_kernel() {
    if (threadIdx.x < EXP) g_counts[threadIdx.x] = 0;
}

__global__ void router_kernel(const float* __restrict__ x,
                              const float* __restrict__ rw,
                              const float* __restrict__ ebias) {
    int t = blockIdx.x;
    __shared__ float xs[CDIM];
    __shared__ float sc[EXP];

    const float* xrow = x + (size_t)t * CDIM;
    for (int c = threadIdx.x * 4; c < CDIM; c += blockDim.x * 4)
        *(float4*)&xs[c] = *(const float4*)&xrow[c];
    __syncthreads();

    int wid = threadIdx.x >> 5, lane = threadIdx.x & 31;
    for (int i = 0; i < 8; i++) {
        int e = wid * 8 + i;
        const float* w = rw + (size_t)e * CDIM;
        float s = 0.f;
        for (int c = lane; c < CDIM; c += 32) s += xs[c] * w[c];
        #pragma unroll
        for (int o = 16; o > 0; o >>= 1) s += __shfl_xor_sync(0xffffffffu, s, o);
        if (lane == 0) sc[e] = 1.f / (1.f + expf(-s));
    }
    __syncthreads();

    if (threadIdx.x == 0) {
        float sb[EXP];
        for (int e = 0; e < EXP; e++) sb[e] = sc[e] + ebias[e];
        float grp[NGRP];
        for (int g = 0; g < NGRP; g++) {
            float m1 = -1e30f, m2 = -1e30f;
            for (int j = 0; j < EPG; j++) {
                float v = sb[g * EPG + j];
                if (v > m1) { m2 = m1; m1 = v; }
                else if (v > m2) m2 = v;
            }
            grp[g] = m1 + m2;
        }
        bool gsel[NGRP] = {};
        for (int it = 0; it < TGRP; it++) {
            float best = -1e30f; int bi = 0;
            for (int g = 0; g < NGRP; g++)
                if (!gsel[g] && grp[g] > best) { best = grp[g]; bi = g; }
            gsel[bi] = true;
        }
        bool eused[EXP] = {};
        int idx[TOPK]; float wv[TOPK]; float wsum = 0.f;
        for (int it = 0; it < TOPK; it++) {
            float best = -1e30f; int bi = 0;
            for (int e = 0; e < EXP; e++)
                if (gsel[e / EPG] && !eused[e] && sb[e] > best) { best = sb[e]; bi = e; }
            eused[bi] = true; idx[it] = bi;
            wv[it] = sc[bi]; wsum += sc[bi];
        }
        float inv = 1.f / (wsum + 1e-20f);
        for (int it = 0; it < TOPK; it++) {
            g_topk_idx[t * TOPK + it] = idx[it];
            g_topk_w[t * TOPK + it]   = wv[it] * inv;
            atomicAdd(&g_counts[idx[it]], 1);
        }
    }
}

__global__ void setup_kernel() {
    int off = 0, nt = 0;
    for (int e = 0; e < EXP; e++) {
        g_offsets[e] = off;
        g_cursor[e]  = off;
        int c = g_counts[e];
        for (int r = 0; r < c; r += 128) {
            g_tiles[nt].e = e;
            g_tiles[nt].row_start = off + r;
            g_tiles[nt].rows = min(128, c - r);
            nt++;
        }
        off += c;
    }
    g_offsets[EXP] = off;
    g_ntiles = nt;
}

__global__ void assign_kernel() {
    int d = blockIdx.x * blockDim.x + threadIdx.x;
    if (d >= NROWS) return;
    int e = g_topk_idx[d];
    int pos = atomicAdd(&g_cursor[e], 1);
    g_rowmap[pos] = d;
}

// ---------------- GEMM tiling constants ----------------
#define GEMM_THREADS 256
#define STAGES 4
#define A_STRIDE_H 40
#define B_STRIDE_H 264
#define A_SZ_H (128 * A_STRIDE_H)           // 5120 halfs
#define B_SZ_H (32 * B_STRIDE_H)            // 8448 halfs
#define PIPE_BYTES (STAGES * (A_SZ_H + B_SZ_H) * 2)     // 108,544 B
#define GU_SMEM_BYTES (PIPE_BYTES + 512)                // + token table
#define E_STRIDE 132                                    // epilogue exchange stride (floats)

// ================= fused gate|up GEMM + SwiGLU epilogue =================
// For hidden block n0 = blockIdx.x*128: computes g = A@B0[:, n0:n0+128],
// u = A@B1[:, n0:n0+128], writes fp16 silu(g)*u to Hout[row][n0 + c] (row stride Nh).
// GROUPED: m-tiles from g_tiles; A rows gathered via g_rowmap from x_r (A = x base).
template <bool GROUPED>
__global__ void __launch_bounds__(GEMM_THREADS, 1) gu_gemm(
    const __half* __restrict__ A, const __half* __restrict__ B0,
    const __half* __restrict__ B1, __half* __restrict__ Hout,
    int Kd, int Nh, long long strideB) {
    extern __shared__ __half smem_h[];
    int* tokmap = (int*)(smem_h + PIPE_BYTES / 2);

    int row_start, rows, e;
    if (GROUPED) {
        if ((int)blockIdx.y >= g_ntiles) return;
        TileDesc td = g_tiles[blockIdx.y];
        e = td.e; row_start = td.row_start; rows = td.rows;
    } else {
        e = 0; row_start = blockIdx.y * 128; rows = 128;
    }
    int n0 = blockIdx.x * 128;
    const __half* B0p = B0 + (long long)e * strideB + n0;
    const __half* B1p = B1 + (long long)e * strideB + n0;

    int tid = threadIdx.x;
    int lane = tid & 31, wid = tid >> 5;
    int g = lane >> 2, tig = lane & 3;
    int wmb = (wid >> 2) * 64;
    int wnb = (wid & 3) * 64;   // 0,64 = gate cols; 128,192 = up cols

    if (GROUPED) {
        if (tid < 128)
            tokmap[tid] = (tid < rows) ? (g_rowmap[row_start + tid] / TOPK) : -1;
        __syncthreads();
    }

    uint32_t sb = (uint32_t)__cvta_generic_to_shared(smem_h);

    float acc[4][8][4];
    #pragma unroll
    for (int mi = 0; mi < 4; mi++)
        #pragma unroll
        for (int ni = 0; ni < 8; ni++)
            #pragma unroll
            for (int q = 0; q < 4; q++) acc[mi][ni][q] = 0.f;

    const int T = Kd >> 5;

    auto issue = [&](int stage, int it) {
        int kk = it * 32;
        uint32_t abase = sb + (uint32_t)(stage * A_SZ_H) * 2u;
        uint32_t bbase = sb + (uint32_t)(STAGES * A_SZ_H + stage * B_SZ_H) * 2u;
        #pragma unroll
        for (int i = 0; i < 2; i++) {
            int c = tid + i * 256;
            int r = c >> 2, j = c & 3;
            const __half* src;
            int vb = 16;
            if (GROUPED) {
                int tok = tokmap[r];
                if (tok < 0) { vb = 0; src = A; }
                else src = A + (long long)tok * Kd + kk + j * 8;
            } else {
                src = A + (long long)(row_start + r) * Kd + kk + j * 8;
            }
            cp_async16(abase + (uint32_t)(r * A_STRIDE_H + j * 8) * 2u, src, vb);
        }
        // B tile: 32 rows x 32 chunks; chunks 0-15 gate, 16-31 up
        #pragma unroll
        for (int i = 0; i < 4; i++) {
            int c = tid + i * 256;
            int r = c >> 5, j = c & 31;
            const __half* src = (j < 16)
                ? B0p + (long long)(kk + r) * Nh + j * 8
                : B1p + (long long)(kk + r) * Nh + (j - 16) * 8;
            cp_async16(bbase + (uint32_t)(r * B_STRIDE_H + j * 8) * 2u, src, 16);
        }
        asm volatile("cp.async.commit_group;" ::: "memory");
    };

    issue(0, 0);
    issue(1, 1);
    issue(2, 2);

    int lhalf = lane & 15, lsel8 = (lane >> 4) << 3;
    for (int it = 0; it < T; it++) {
        int stage = it & 3;
        asm volatile("cp.async.wait_group 2;" ::: "memory");
        __syncthreads();
        if (it + 3 < T) issue((it + 3) & 3, it + 3);

        uint32_t abase = sb + (uint32_t)(stage * A_SZ_H) * 2u;
        uint32_t bbase = sb + (uint32_t)(STAGES * A_SZ_H + stage * B_SZ_H) * 2u;

        #pragma unroll
        for (int ks = 0; ks < 2; ks++) {
            int k0 = ks * 16;
            uint32_t af[4][4], bf[4][4];
            #pragma unroll
            for (int mi = 0; mi < 4; mi++)
                ldmatrix_x4(af[mi], abase +
                    (uint32_t)((wmb + mi * 16 + lhalf) * A_STRIDE_H + k0 + lsel8) * 2u);
            #pragma unroll
            for (int nc = 0; nc < 4; nc++)
                ldmatrix_x4_trans(bf[nc], bbase +
                    (uint32_t)((k0 + lhalf) * B_STRIDE_H + wnb + nc * 16 + lsel8) * 2u);
            #pragma unroll
            for (int mi = 0; mi < 4; mi++)
                #pragma unroll
                for (int nc = 0; nc < 4; nc++) {
                    mma_f16(acc[mi][2 * nc + 0], af[mi], &bf[nc][0]);
                    mma_f16(acc[mi][2 * nc + 1], af[mi], &bf[nc][2]);
                }
        }
    }

    // ---- fused SwiGLU epilogue ----
    // make sure all warps finished reading pipeline smem before reuse
    asm volatile("cp.async.wait_group 0;" ::: "memory");
    __syncthreads();
    float* ex = (float*)smem_h;   // [128][E_STRIDE] exchange buffer

    if (wnb >= 128) {
        // up warps: stash accs
        int ub = wnb - 128;
        #pragma unroll
        for (int mi = 0; mi < 4; mi++)
            #pragma unroll
            for (int h = 0; h < 2; h++) {
                int rl = wmb + mi * 16 + g + 8 * h;
                #pragma unroll
                for (int ni = 0; ni < 8; ni++) {
                    int uc = ub + ni * 8 + 2 * tig;
                    ex[rl * E_STRIDE + uc]     = acc[mi][ni][2 * h + 0];
                    ex[rl * E_STRIDE + uc + 1] = acc[mi][ni][2 * h + 1];
                }
            }
    }
    __syncthreads();
    if (wnb < 128) {
        // gate warps: silu(g)*u, write fp16
        #pragma unroll
        for (int mi = 0; mi < 4; mi++)
            #pragma unroll
            for (int h = 0; h < 2; h++) {
                int rl = wmb + mi * 16 + g + 8 * h;
                if (GROUPED && rl >= rows) continue;
                __half* dst = Hout + (size_t)(row_start + rl) * Nh + n0;
                #pragma unroll
                for (int ni = 0; ni < 8; ni++) {
                    int gc = wnb + ni * 8 + 2 * tig;
                    float g0 = acc[mi][ni][2 * h + 0];
                    float g1 = acc[mi][ni][2 * h + 1];
                    float u0 = ex[rl * E_STRIDE + gc];
                    float u1 = ex[rl * E_STRIDE + gc + 1];
                    float r0 = g0 / (1.f + expf(-g0)) * u0;
                    float r1 = g1 / (1.f + expf(-g1)) * u1;
                    *(__half2*)(dst + gc) = __floats2half2_rn(r0, r1);
                }
            }
    }
}

// ================= plain fp16 GEMM (down projections) =================
template <bool GROUPED, bool SCATTER>
__global__ void __launch_bounds__(GEMM_THREADS, 1) mma_gemm(
    const __half* __restrict__ A, const __half* __restrict__ B0,
    float* __restrict__ Cout, int Kd, int N, long long strideB,
    const int* __restrict__ rowmap, const float* __restrict__ rowscale) {
    extern __shared__ __half smem_h[];

    int row_start, rows, e;
    if (GROUPED) {
        if ((int)blockIdx.y >= g_ntiles) return;
        TileDesc td = g_tiles[blockIdx.y];
        e = td.e; row_start = td.row_start; rows = td.rows;
    } else {
        e = 0; row_start = blockIdx.y * 128; rows = 128;
    }
    int nstart = blockIdx.x * 256;
    const __half* Bptr = B0 + (long long)e * strideB + nstart;
    const __half* Aptr = A + (long long)row_start * Kd;

    int tid = threadIdx.x;
    int lane = tid & 31, wid = tid >> 5;
    int g = lane >> 2, tig = lane & 3;
    int wmb = (wid >> 2) * 64;
    int wnb = (wid & 3) * 64;

    uint32_t sb = (uint32_t)__cvta_generic_to_shared(smem_h);

    float acc[4][8][4];
    #pragma unroll
    for (int mi = 0; mi < 4; mi++)
        #pragma unroll
        for (int ni = 0; ni < 8; ni++)
            #pragma unroll
            for (int q = 0; q < 4; q++) acc[mi][ni][q] = 0.f;

    const int T = Kd >> 5;

    auto issue = [&](int stage, int it) {
        int kk = it * 32;
        uint32_t abase = sb + (uint32_t)(stage * A_SZ_H) * 2u;
        uint32_t bbase = sb + (uint32_t)(STAGES * A_SZ_H + stage * B_SZ_H) * 2u;
        #pragma unroll
        for (int i = 0; i < 2; i++) {
            int c = tid + i * 256;
            int r = c >> 2, j = c & 3;
            const __half* src = Aptr + (long long)r * Kd + kk + j * 8;
            int vb = 16;
            if (GROUPED && r >= rows) { vb = 0; src = Aptr; }
            cp_async16(abase + (uint32_t)(r * A_STRIDE_H + j * 8) * 2u, src, vb);
        }
        #pragma unroll
        for (int i = 0; i < 4; i++) {
            int c = tid + i * 256;
            int r = c >> 5, j = c & 31;
            cp_async16(bbase + (uint32_t)(r * B_STRIDE_H + j * 8) * 2u,
                       Bptr + (long long)(kk + r) * N + j * 8, 16);
        }
        asm volatile("cp.async.commit_group;" ::: "memory");
    };

    issue(0, 0);
    issue(1, 1);
    issue(2, 2);

    int lhalf = lane & 15, lsel8 = (lane >> 4) << 3;
    for (int it = 0; it < T; it++) {
        int stage = it & 3;
        asm volatile("cp.async.wait_group 2;" ::: "memory");
        __syncthreads();
        if (it + 3 < T) issue((it + 3) & 3, it + 3);

        uint32_t abase = sb + (uint32_t)(stage * A_SZ_H) * 2u;
        uint32_t bbase = sb + (uint32_t)(STAGES * A_SZ_H + stage * B_SZ_H) * 2u;

        #pragma unroll
        for (int ks = 0; ks < 2; ks++) {
            int k0 = ks * 16;
            uint32_t af[4][4], bf[4][4];
            #pragma unroll
            for (int mi = 0; mi < 4; mi++)
                ldmatrix_x4(af[mi], abase +
                    (uint32_t)((wmb + mi * 16 + lhalf) * A_STRIDE_H + k0 + lsel8) * 2u);
            #pragma unroll
            for (int nc = 0; nc < 4; nc++)
                ldmatrix_x4_trans(bf[nc], bbase +
                    (uint32_t)((k0 + lhalf) * B_STRIDE_H + wnb + nc * 16 + lsel8) * 2u);
            #pragma unroll
            for (int mi = 0; mi < 4; mi++)
                #pragma unroll
                for (int nc = 0; nc < 4; nc++) {
                    mma_f16(acc[mi][2 * nc + 0], af[mi], &bf[nc][0]);
                    mma_f16(acc[mi][2 * nc + 1], af[mi], &bf[nc][2]);
                }
        }
    }

    #pragma unroll
    for (int mi = 0; mi < 4; mi++) {
        #pragma unroll
        for (int h = 0; h < 2; h++) {
            int rl = wmb + mi * 16 + g + 8 * h;
            if (GROUPED && rl >= rows) continue;
            float scale = 1.f;
            float* dst;
            if (SCATTER) {
                int d = rowmap[row_start + rl];
                scale = rowscale[d];
                dst = Cout + (size_t)d * N;
            } else {
                dst = Cout + (size_t)(row_start + rl) * N;
            }
            #pragma unroll
            for (int ni = 0; ni < 8; ni++) {
                int col = nstart + wnb + ni * 8 + 2 * tig;
                float2 v;
                v.x = acc[mi][ni][2 * h + 0] * scale;
                v.y = acc[mi][ni][2 * h + 1] * scale;
                *(float2*)(dst + col) = v;
            }
        }
    }
}

// ---------------- combine ----------------
__global__ void combine_kernel(float* __restrict__ out) {
    int t = blockIdx.x;
    int c = threadIdx.x * 4;
    float4 acc = *(const float4*)(g_shared_out + (size_t)t * CDIM + c);
    #pragma unroll
    for (int k = 0; k < TOPK; k++) {
        float4 v = *(const float4*)(g_rows_out + (size_t)(t * TOPK + k) * CDIM + c);
        acc.x += v.x; acc.y += v.y; acc.z += v.z; acc.w += v.w;
    }
    *(float4*)(out + (size_t)t * CDIM + c) = acc;
}

// ---------------- launch ----------------
extern "C" void kernel_launch(void* const* d_in, const int* in_sizes, int n_in,
                              void* d_out, int out_size) {
    const float* x        = (const float*)d_in[0];
    const float* router_w = (const float*)d_in[1];
    const float* e_bias   = (const float*)d_in[2];
    const float* gate_w   = (const float*)d_in[3];
    const float* up_w     = (const float*)d_in[4];
    const float* down_w   = (const float*)d_in[5];
    const float* sh_gate  = (const float*)d_in[6];
    const float* sh_up    = (const float*)d_in[7];
    const float* sh_down  = (const float*)d_in[8];
    float* out = (float*)d_out;

    __half *p_hbuf, *p_sh_h, *p_x_r;
    __half *p_w_gate, *p_w_up, *p_w_down, *p_w_shg, *p_w_shu, *p_w_shd;
    float *p_rows_out, *p_shared_out, *p_topk_w;
    int* p_rowmap;
    cudaGetSymbolAddress((void**)&p_hbuf,       g_hbuf);
    cudaGetSymbolAddress((void**)&p_rows_out,   g_rows_out);
    cudaGetSymbolAddress((void**)&p_sh_h,       g_sh_h);
    cudaGetSymbolAddress((void**)&p_shared_out, g_shared_out);
    cudaGetSymbolAddress((void**)&p_topk_w,     g_topk_w);
    cudaGetSymbolAddress((void**)&p_rowmap,     g_rowmap);
    cudaGetSymbolAddress((void**)&p_x_r,        g_x_r);
    cudaGetSymbolAddress((void**)&p_w_gate,     g_w_gate);
    cudaGetSymbolAddress((void**)&p_w_up,       g_w_up);
    cudaGetSymbolAddress((void**)&p_w_down,     g_w_down);
    cudaGetSymbolAddress((void**)&p_w_shg,      g_w_shg);
    cudaGetSymbolAddress((void**)&p_w_shu,      g_w_shu);
    cudaGetSymbolAddress((void**)&p_w_shd,      g_w_shd);

    cudaFuncSetAttribute(gu_gemm<false>,
                         cudaFuncAttributeMaxDynamicSharedMemorySize, GU_SMEM_BYTES);
    cudaFuncSetAttribute(gu_gemm<true>,
                         cudaFuncAttributeMaxDynamicSharedMemorySize, GU_SMEM_BYTES);
    cudaFuncSetAttribute(mma_gemm<false, false>,
                         cudaFuncAttributeMaxDynamicSharedMemorySize, PIPE_BYTES);
    cudaFuncSetAttribute(mma_gemm<true, true>,
                         cudaFuncAttributeMaxDynamicSharedMemorySize, PIPE_BYTES);

    long long n4;

    // launches 0-2: prep for shared expert
    n4 = (long long)S_TOK * CDIM / 4;
    half_copy<<<(unsigned)((n4 + 255) / 256), 256>>>((const float4*)x, (__half2*)p_x_r, n4);
    n4 = (long long)CDIM * HSHARED / 4;
    half_copy<<<(unsigned)((n4 + 255) / 256), 256>>>((const float4*)sh_gate, (__half2*)p_w_shg, n4);
    half_copy<<<(unsigned)((n4 + 255) / 256), 256>>>((const float4*)sh_up,   (__half2*)p_w_shu, n4);

    // launches 3-4: routing part 1
    zero_counts_kernel<<<1, 64>>>();
    router_kernel<<<S_TOK, 256>>>(x, router_w, e_bias);

    // launch 5: fused shared gu GEMM + swiglu (profiled)
    gu_gemm<false><<<dim3(HSHARED / 128, S_TOK / 128), GEMM_THREADS, GU_SMEM_BYTES>>>(
        p_x_r, p_w_shg, p_w_shu, p_sh_h, CDIM, HSHARED, 0);

    n4 = (long long)CDIM * HSHARED / 4;
    half_copy<<<(unsigned)((n4 + 255) / 256), 256>>>((const float4*)sh_down, (__half2*)p_w_shd, n4);
    mma_gemm<false, false><<<dim3(CDIM / 256, S_TOK / 128), GEMM_THREADS, PIPE_BYTES>>>(
        p_sh_h, p_w_shd, p_shared_out, HSHARED, CDIM, 0, nullptr, nullptr);

    // expert weight prep + routing part 2
    n4 = (long long)EXP * CDIM * HDIM / 4;
    half_copy<<<(unsigned)((n4 + 255) / 256), 256>>>((const float4*)gate_w, (__half2*)p_w_gate, n4);
    half_copy<<<(unsigned)((n4 + 255) / 256), 256>>>((const float4*)up_w,   (__half2*)p_w_up,   n4);
    half_copy<<<(unsigned)((n4 + 255) / 256), 256>>>((const float4*)down_w, (__half2*)p_w_down, n4);
    setup_kernel<<<1, 1>>>();
    assign_kernel<<<NROWS / 256, 256>>>();

    // routed experts: fused gu GEMM (indirect A gather from x_r) + swiglu
    gu_gemm<true><<<dim3(HDIM / 128, MAX_TILES), GEMM_THREADS, GU_SMEM_BYTES>>>(
        p_x_r, p_w_gate, p_w_up, p_hbuf, CDIM, HDIM, (long long)CDIM * HDIM);

    // routed down: scatter + scale
    mma_gemm<true, true><<<dim3(CDIM / 256, MAX_TILES), GEMM_THREADS, PIPE_BYTES>>>(
        p_hbuf, p_w_down, p_rows_out, HDIM, CDIM, (long long)HDIM * CDIM,
        p_rowmap, p_topk_w);

    // combine
    combine_kernel<<<S_TOK, 256>>>(out);
}

// round 8
// speedup vs baseline: 1.0333x; 1.0333x over previous
#include <cuda_runtime.h>
#include <cuda_fp16.h>
#include <math.h>
#include <stdint.h>

// ---------------- problem constants ----------------
#define S_TOK   4096
#define CDIM    1024
#define EXP     64
#define TOPK    8
#define NGRP    8
#define EPG     8
#define TGRP    4
#define HDIM    512
#define HSHARED 2048
#define NROWS   (S_TOK * TOPK)   // 32768
#define MAX_TILES 320

// ---------------- scratch (static device globals) ----------------
struct TileDesc { int e; int row_start; int rows; };

__device__ int      g_counts[EXP];
__device__ int      g_offsets[EXP + 1];
__device__ int      g_cursor[EXP];
__device__ TileDesc g_tiles[MAX_TILES];
__device__ int      g_ntiles;
__device__ int      g_rowmap[NROWS];
__device__ int      g_topk_idx[NROWS];
__device__ float    g_topk_w[NROWS];

__device__ __half   g_sorted_x[(size_t)NROWS * CDIM];
__device__ __half   g_gu_h[(size_t)NROWS * 1024];       // fp16 [gate 0:512 | up 512:1024]
__device__ __half   g_hbuf[(size_t)NROWS * HDIM];
__device__ __half   g_sh_gu[(size_t)S_TOK * 4096];      // fp16 [shgate | shup]
__device__ __half   g_sh_h[(size_t)S_TOK * HSHARED];
__device__ __half   g_x_r[(size_t)S_TOK * CDIM];

// fp16 weight copies (native [K][N] layouts preserved)
__device__ __half   g_w_gate[(size_t)EXP * CDIM * HDIM];
__device__ __half   g_w_up[(size_t)EXP * CDIM * HDIM];
__device__ __half   g_w_down[(size_t)EXP * HDIM * CDIM];
__device__ __half   g_w_shg[(size_t)CDIM * HSHARED];
__device__ __half   g_w_shu[(size_t)CDIM * HSHARED];
__device__ __half   g_w_shd[(size_t)HSHARED * CDIM];

// ---------------- helpers ----------------
__device__ __forceinline__ void mma_f16(float* c, const uint32_t* a, const uint32_t* b) {
    asm volatile(
        "mma.sync.aligned.m16n8k16.row.col.f32.f16.f16.f32 "
        "{%0,%1,%2,%3}, {%4,%5,%6,%7}, {%8,%9}, {%0,%1,%2,%3};"
        : "+f"(c[0]), "+f"(c[1]), "+f"(c[2]), "+f"(c[3])
        : "r"(a[0]), "r"(a[1]), "r"(a[2]), "r"(a[3]), "r"(b[0]), "r"(b[1]));
}
__device__ __forceinline__ void ldmatrix_x4(uint32_t* r, uint32_t addr) {
    asm volatile("ldmatrix.sync.aligned.m8n8.x4.shared.b16 {%0,%1,%2,%3}, [%4];"
                 : "=r"(r[0]), "=r"(r[1]), "=r"(r[2]), "=r"(r[3]) : "r"(addr));
}
__device__ __forceinline__ void ldmatrix_x4_trans(uint32_t* r, uint32_t addr) {
    asm volatile("ldmatrix.sync.aligned.m8n8.x4.trans.shared.b16 {%0,%1,%2,%3}, [%4];"
                 : "=r"(r[0]), "=r"(r[1]), "=r"(r[2]), "=r"(r[3]) : "r"(addr));
}
__device__ __forceinline__ void cp_async16(uint32_t dst, const void* src, int srcbytes) {
    asm volatile("cp.async.cg.shared.global [%0], [%1], 16, %2;"
                 :: "r"(dst), "l"(src), "r"(srcbytes));
}

// ---------------- prep: f32 -> f16 convert copy ----------------
__global__ void half_copy(const float4* __restrict__ src, __half2* __restrict__ dst,
                          long long n4) {
    long long i = (long long)blockIdx.x * blockDim.x + threadIdx.x;
    if (i >= n4) return;
    float4 v = src[i];
    dst[i * 2 + 0] = __floats2half2_rn(v.x, v.y);
    dst[i * 2 + 1] = __floats2half2_rn(v.z, v.w);
}

// ---------------- routing kernels (verified correct) ----------------
__global__ void zero_counts_kernel() {
    if (threadIdx.x < EXP) g_counts[threadIdx.x] = 0;
}

__global__ void router_kernel(const float* __restrict__ x,
                              const float* __restrict__ rw,
                              const float* __restrict__ ebias) {
    int t = blockIdx.x;
    __shared__ float xs[CDIM];
    __shared__ float sc[EXP];

    const float* xrow = x + (size_t)t * CDIM;
    for (int c = threadIdx.x * 4; c < CDIM; c += blockDim.x * 4)
        *(float4*)&xs[c] = *(const float4*)&xrow[c];
    __syncthreads();

    int wid = threadIdx.x >> 5, lane = threadIdx.x & 31;
    for (int i = 0; i < 8; i++) {
        int e = wid * 8 + i;
        const float* w = rw + (size_t)e * CDIM;
        float s = 0.f;
        for (int c = lane; c < CDIM; c += 32) s += xs[c] * w[c];
        #pragma unroll
        for (int o = 16; o > 0; o >>= 1) s += __shfl_xor_sync(0xffffffffu, s, o);
        if (lane == 0) sc[e] = 1.f / (1.f + expf(-s));
    }
    __syncthreads();

    if (threadIdx.x == 0) {
        float sb[EXP];
        for (int e = 0; e < EXP; e++) sb[e] = sc[e] + ebias[e];
        float grp[NGRP];
        for (int g = 0; g < NGRP; g++) {
            float m1 = -1e30f, m2 = -1e30f;
            for (int j = 0; j < EPG; j++) {
                float v = sb[g * EPG + j];
                if (v > m1) { m2 = m1; m1 = v; }
                else if (v > m2) m2 = v;
            }
            grp[g] = m1 + m2;
        }
        bool gsel[NGRP] = {};
        for (int it = 0; it < TGRP; it++) {
            float best = -1e30f; int bi = 0;
            for (int g = 0; g < NGRP; g++)
                if (!gsel[g] && grp[g] > best) { best = grp[g]; bi = g; }
            gsel[bi] = true;
        }
        bool eused[EXP] = {};
        int idx[TOPK]; float wv[TOPK]; float wsum = 0.f;
        for (int it = 0; it < TOPK; it++) {
            float best = -1e30f; int bi = 0;
            for (int e = 0; e < EXP; e++)
                if (gsel[e / EPG] && !eused[e] && sb[e] > best) { best = sb[e]; bi = e; }
            eused[bi] = true; idx[it] = bi;
            wv[it] = sc[bi]; wsum += sc[bi];
        }
        float inv = 1.f / (wsum + 1e-20f);
        for (int it = 0; it < TOPK; it++) {
            g_topk_idx[t * TOPK + it] = idx[it];
            g_topk_w[t * TOPK + it]   = wv[it] * inv;
            atomicAdd(&g_counts[idx[it]], 1);
        }
    }
}

__global__ void setup_kernel() {
    int off = 0, nt = 0;
    for (int e = 0; e < EXP; e++) {
        g_offsets[e] = off;
        g_cursor[e]  = off;
        int c = g_counts[e];
        for (int r = 0; r < c; r += 128) {
            g_tiles[nt].e = e;
            g_tiles[nt].row_start = off + r;
            g_tiles[nt].rows = min(128, c - r);
            nt++;
        }
        off += c;
    }
    g_offsets[EXP] = off;
    g_ntiles = nt;
}

__global__ void assign_kernel() {
    int d = blockIdx.x * blockDim.x + threadIdx.x;
    if (d >= NROWS) return;
    int e = g_topk_idx[d];
    int pos = atomicAdd(&g_cursor[e], 1);
    g_rowmap[pos] = d;
}

// gather + fp16 convert into sorted order
__global__ void gather_kernel(const float* __restrict__ x) {
    int row = blockIdx.x;
    int d = g_rowmap[row];
    int t = d / TOPK;
    const float4* src = (const float4*)(x + (size_t)t * CDIM);
    __half2* dst = (__half2*)(g_sorted_x + (size_t)row * CDIM);
    for (int i = threadIdx.x; i < CDIM / 4; i += blockDim.x) {
        float4 v = src[i];
        dst[i * 2 + 0] = __floats2half2_rn(v.x, v.y);
        dst[i * 2 + 1] = __floats2half2_rn(v.z, v.w);
    }
}

// ================= fp16 tensor-core GEMM (cp.async 4-stage, ldmatrix) =================
// C[M,N] = A[M,Kd] @ B[Kd,N]; fp16 operands, fp32 accum.
// MODE 0: fp32 store to CoutF. MODE 1: fp16 store to CoutH.
// MODE 2: atomicAdd scaled rows into CoutF[token] (token = rowmap[row]/TOPK).
// Dual-B fusion: n-tiles with nstart < Nb read B0, else B1.
#define GEMM_THREADS 256
#define STAGES 4
#define A_STRIDE_H 40
#define B_STRIDE_H 264
#define A_SZ_H (128 * A_STRIDE_H)
#define B_SZ_H (32 * B_STRIDE_H)
#define GEMM_SMEM_BYTES (STAGES * (A_SZ_H + B_SZ_H) * 2)   // 108,544 B

template <bool GROUPED, int MODE>
__global__ void __launch_bounds__(GEMM_THREADS, 1) mma_gemm(
    const __half* __restrict__ A, const __half* __restrict__ B0,
    const __half* __restrict__ B1, float* __restrict__ CoutF,
    __half* __restrict__ CoutH,
    int Kd, int Nb, int N, long long strideB,
    const int* __restrict__ rowmap, const float* __restrict__ rowscale) {
    extern __shared__ __half smem_h[];

    int row_start, rows, e;
    if (GROUPED) {
        if ((int)blockIdx.y >= g_ntiles) return;
        TileDesc td = g_tiles[blockIdx.y];
        e = td.e; row_start = td.row_start; rows = td.rows;
    } else {
        e = 0; row_start = blockIdx.y * 128; rows = 128;
    }
    int nstart = blockIdx.x * 256;
    const __half* Bm = (nstart < Nb) ? B0 : B1;
    int ncol0 = (nstart < Nb) ? nstart : nstart - Nb;
    const __half* Bptr = Bm + (long long)e * strideB + ncol0;
    const __half* Aptr = A + (long long)row_start * Kd;

    int tid = threadIdx.x;
    int lane = tid & 31, wid = tid >> 5;
    int g = lane >> 2, tig = lane & 3;
    int wmb = (wid >> 2) * 64;
    int wnb = (wid & 3) * 64;

    uint32_t sb = (uint32_t)__cvta_generic_to_shared(smem_h);

    float acc[4][8][4];
    #pragma unroll
    for (int mi = 0; mi < 4; mi++)
        #pragma unroll
        for (int ni = 0; ni < 8; ni++)
            #pragma unroll
            for (int q = 0; q < 4; q++) acc[mi][ni][q] = 0.f;

    const int T = Kd >> 5;

    auto issue = [&](int stage, int it) {
        int kk = it * 32;
        uint32_t abase = sb + (uint32_t)(stage * A_SZ_H) * 2u;
        uint32_t bbase = sb + (uint32_t)(STAGES * A_SZ_H + stage * B_SZ_H) * 2u;
        #pragma unroll
        for (int i = 0; i < 2; i++) {
            int c = tid + i * 256;
            int r = c >> 2, j = c & 3;
            const __half* src = Aptr + (long long)r * Kd + kk + j * 8;
            int vb = 16;
            if (GROUPED && r >= rows) { vb = 0; src = Aptr; }
            cp_async16(abase + (uint32_t)(r * A_STRIDE_H + j * 8) * 2u, src, vb);
        }
        #pragma unroll
        for (int i = 0; i < 4; i++) {
            int c = tid + i * 256;
            int r = c >> 5, j = c & 31;
            cp_async16(bbase + (uint32_t)(r * B_STRIDE_H + j * 8) * 2u,
                       Bptr + (long long)(kk + r) * Nb + j * 8, 16);
        }
        asm volatile("cp.async.commit_group;" ::: "memory");
    };

    issue(0, 0);
    issue(1, 1);
    issue(2, 2);

    int lhalf = lane & 15, lsel8 = (lane >> 4) << 3;
    for (int it = 0; it < T; it++) {
        int stage = it & 3;
        asm volatile("cp.async.wait_group 2;" ::: "memory");
        __syncthreads();
        if (it + 3 < T) issue((it + 3) & 3, it + 3);

        uint32_t abase = sb + (uint32_t)(stage * A_SZ_H) * 2u;
        uint32_t bbase = sb + (uint32_t)(STAGES * A_SZ_H + stage * B_SZ_H) * 2u;

        #pragma unroll
        for (int ks = 0; ks < 2; ks++) {
            int k0 = ks * 16;
            uint32_t af[4][4], bf[4][4];
            #pragma unroll
            for (int mi = 0; mi < 4; mi++)
                ldmatrix_x4(af[mi], abase +
                    (uint32_t)((wmb + mi * 16 + lhalf) * A_STRIDE_H + k0 + lsel8) * 2u);
            #pragma unroll
            for (int nc = 0; nc < 4; nc++)
                ldmatrix_x4_trans(bf[nc], bbase +
                    (uint32_t)((k0 + lhalf) * B_STRIDE_H + wnb + nc * 16 + lsel8) * 2u);
            #pragma unroll
            for (int mi = 0; mi < 4; mi++)
                #pragma unroll
                for (int nc = 0; nc < 4; nc++) {
                    mma_f16(acc[mi][2 * nc + 0], af[mi], &bf[nc][0]);
                    mma_f16(acc[mi][2 * nc + 1], af[mi], &bf[nc][2]);
                }
        }
    }

    // ---- epilogue ----
    #pragma unroll
    for (int mi = 0; mi < 4; mi++) {
        #pragma unroll
        for (int h = 0; h < 2; h++) {
            int rl = wmb + mi * 16 + g + 8 * h;
            if (GROUPED && rl >= rows) continue;
            if (MODE == 2) {
                int d = rowmap[row_start + rl];
                float scale = rowscale[d];
                float* dst = CoutF + (size_t)(d / TOPK) * N;
                #pragma unroll
                for (int ni = 0; ni < 8; ni++) {
                    int col = nstart + wnb + ni * 8 + 2 * tig;
                    atomicAdd(dst + col,     acc[mi][ni][2 * h + 0] * scale);
                    atomicAdd(dst + col + 1, acc[mi][ni][2 * h + 1] * scale);
                }
            } else if (MODE == 1) {
                __half* dst = CoutH + (size_t)(row_start + rl) * N;
                #pragma unroll
                for (int ni = 0; ni < 8; ni++) {
                    int col = nstart + wnb + ni * 8 + 2 * tig;
                    *(__half2*)(dst + col) =
                        __floats2half2_rn(acc[mi][ni][2 * h + 0], acc[mi][ni][2 * h + 1]);
                }
            } else {
                float* dst = CoutF + (size_t)(row_start + rl) * N;
                #pragma unroll
                for (int ni = 0; ni < 8; ni++) {
                    int col = nstart + wnb + ni * 8 + 2 * tig;
                    float2 v;
                    v.x = acc[mi][ni][2 * h + 0];
                    v.y = acc[mi][ni][2 * h + 1];
                    *(float2*)(dst + col) = v;
                }
            }
        }
    }
}

// ---------------- swiglu on fp16 gu buffer: h = silu(g) * u ----------------
// gu rows: [g 0:off | u off:2*off] (halfs); h rows: off halfs.
__global__ void swiglu_h(const __half* __restrict__ gu, __half* __restrict__ h,
                         long long total8, int jshift, int guStride, int off) {
    long long i = (long long)blockIdx.x * blockDim.x + threadIdx.x;
    if (i >= total8) return;
    long long row = i >> jshift;
    int j = (int)(i & ((1LL << jshift) - 1)) * 8;
    const __half2* gp = (const __half2*)(gu + row * guStride + j);
    const __half2* up = (const __half2*)(gu + row * guStride + off + j);
    __half2* hp = (__half2*)(h + row * (long long)off + j);
    #pragma unroll
    for (int q = 0; q < 4; q++) {
        float2 g2 = __half22float2(gp[q]);
        float2 u2 = __half22float2(up[q]);
        float r0 = g2.x / (1.f + expf(-g2.x)) * u2.x;
        float r1 = g2.y / (1.f + expf(-g2.y)) * u2.y;
        hp[q] = __floats2half2_rn(r0, r1);
    }
}

// ---------------- launch ----------------
extern "C" void kernel_launch(void* const* d_in, const int* in_sizes, int n_in,
                              void* d_out, int out_size) {
    const float* x        = (const float*)d_in[0];
    const float* router_w = (const float*)d_in[1];
    const float* e_bias   = (const float*)d_in[2];
    const float* gate_w   = (const float*)d_in[3];
    const float* up_w     = (const float*)d_in[4];
    const float* down_w   = (const float*)d_in[5];
    const float* sh_gate  = (const float*)d_in[6];
    const float* sh_up    = (const float*)d_in[7];
    const float* sh_down  = (const float*)d_in[8];
    float* out = (float*)d_out;

    __half *p_sorted_x, *p_gu_h, *p_hbuf, *p_sh_gu, *p_sh_h, *p_x_r;
    __half *p_w_gate, *p_w_up, *p_w_down, *p_w_shg, *p_w_shu, *p_w_shd;
    float *p_topk_w;
    int* p_rowmap;
    cudaGetSymbolAddress((void**)&p_sorted_x, g_sorted_x);
    cudaGetSymbolAddress((void**)&p_gu_h,     g_gu_h);
    cudaGetSymbolAddress((void**)&p_hbuf,     g_hbuf);
    cudaGetSymbolAddress((void**)&p_sh_gu,    g_sh_gu);
    cudaGetSymbolAddress((void**)&p_sh_h,     g_sh_h);
    cudaGetSymbolAddress((void**)&p_topk_w,   g_topk_w);
    cudaGetSymbolAddress((void**)&p_rowmap,   g_rowmap);
    cudaGetSymbolAddress((void**)&p_x_r,      g_x_r);
    cudaGetSymbolAddress((void**)&p_w_gate,   g_w_gate);
    cudaGetSymbolAddress((void**)&p_w_up,     g_w_up);
    cudaGetSymbolAddress((void**)&p_w_down,   g_w_down);
    cudaGetSymbolAddress((void**)&p_w_shg,    g_w_shg);
    cudaGetSymbolAddress((void**)&p_w_shu,    g_w_shu);
    cudaGetSymbolAddress((void**)&p_w_shd,    g_w_shd);

    cudaFuncSetAttribute(mma_gemm<false, 0>,
                         cudaFuncAttributeMaxDynamicSharedMemorySize, GEMM_SMEM_BYTES);
    cudaFuncSetAttribute(mma_gemm<false, 1>,
                         cudaFuncAttributeMaxDynamicSharedMemorySize, GEMM_SMEM_BYTES);
    cudaFuncSetAttribute(mma_gemm<true, 1>,
                         cudaFuncAttributeMaxDynamicSharedMemorySize, GEMM_SMEM_BYTES);
    cudaFuncSetAttribute(mma_gemm<true, 2>,
                         cudaFuncAttributeMaxDynamicSharedMemorySize, GEMM_SMEM_BYTES);

    long long n4;

    // launches 0-2: prep for shared expert
    n4 = (long long)S_TOK * CDIM / 4;
    half_copy<<<(unsigned)((n4 + 255) / 256), 256>>>((const float4*)x, (__half2*)p_x_r, n4);
    n4 = (long long)CDIM * HSHARED / 4;
    half_copy<<<(unsigned)((n4 + 255) / 256), 256>>>((const float4*)sh_gate, (__half2*)p_w_shg, n4);
    half_copy<<<(unsigned)((n4 + 255) / 256), 256>>>((const float4*)sh_up,   (__half2*)p_w_shu, n4);

    // launches 3-4: routing part 1
    zero_counts_kernel<<<1, 64>>>();
    router_kernel<<<S_TOK, 256>>>(x, router_w, e_bias);

    // launch 5: shared gu GEMM (fp16 out, dual-B) — profiled
    mma_gemm<false, 1><<<dim3(4096 / 256, S_TOK / 128), GEMM_THREADS, GEMM_SMEM_BYTES>>>(
        p_x_r, p_w_shg, p_w_shu, nullptr, p_sh_gu, 1024, 2048, 4096, 0, nullptr, nullptr);
    {
        long long total8 = (long long)S_TOK * (HSHARED / 8);
        swiglu_h<<<(unsigned)((total8 + 255) / 256), 256>>>(
            p_sh_gu, p_sh_h, total8, 8, 4096, 2048);
    }
    n4 = (long long)CDIM * HSHARED / 4;
    half_copy<<<(unsigned)((n4 + 255) / 256), 256>>>((const float4*)sh_down, (__half2*)p_w_shd, n4);
    // shared down: writes fp32 directly into out (full coverage)
    mma_gemm<false, 0><<<dim3(CDIM / 256, S_TOK / 128), GEMM_THREADS, GEMM_SMEM_BYTES>>>(
        p_sh_h, p_w_shd, nullptr, out, nullptr, 2048, 1024, 1024, 0, nullptr, nullptr);

    // expert weight prep + routing part 2
    n4 = (long long)EXP * CDIM * HDIM / 4;
    half_copy<<<(unsigned)((n4 + 255) / 256), 256>>>((const float4*)gate_w, (__half2*)p_w_gate, n4);
    half_copy<<<(unsigned)((n4 + 255) / 256), 256>>>((const float4*)up_w,   (__half2*)p_w_up,   n4);
    half_copy<<<(unsigned)((n4 + 255) / 256), 256>>>((const float4*)down_w, (__half2*)p_w_down, n4);
    setup_kernel<<<1, 1>>>();
    assign_kernel<<<NROWS / 256, 256>>>();
    gather_kernel<<<NROWS, 256>>>(x);

    // routed gu GEMM (fp16 out, dual-B, grouped)
    mma_gemm<true, 1><<<dim3(1024 / 256, MAX_TILES), GEMM_THREADS, GEMM_SMEM_BYTES>>>(
        p_sorted_x, p_w_gate, p_w_up, nullptr, p_gu_h, 1024, 512, 1024,
        (long long)CDIM * HDIM, nullptr, nullptr);
    {
        long long total8 = (long long)NROWS * (HDIM / 8);
        swiglu_h<<<(unsigned)((total8 + 255) / 256), 256>>>(
            p_gu_h, p_hbuf, total8, 6, 1024, 512);
    }
    // routed down: atomicAdd scaled rows directly into out (after shared down wrote it)
    mma_gemm<true, 2><<<dim3(CDIM / 256, MAX_TILES), GEMM_THREADS, GEMM_SMEM_BYTES>>>(
        p_hbuf, p_w_down, nullptr, out, nullptr, 512, 1024, 1024,
        (long long)HDIM * CDIM, p_rowmap, p_topk_w);
}

// round 9
// speedup vs baseline: 1.2072x; 1.1683x over previous
#include <cuda_runtime.h>
#include <cuda_fp16.h>
#include <math.h>
#include <stdint.h>

// ---------------- problem constants ----------------
#define S_TOK   4096
#define CDIM    1024
#define EXP     64
#define TOPK    8
#define NGRP    8
#define EPG     8
#define TGRP    4
#define HDIM    512
#define HSHARED 2048
#define NROWS   (S_TOK * TOPK)   // 32768
#define MAX_TILES 320

// ---------------- scratch (static device globals) ----------------
struct TileDesc { int e; int row_start; int rows; };

__device__ int      g_counts[EXP];
__device__ int      g_offsets[EXP + 1];
__device__ int      g_cursor[EXP];
__device__ TileDesc g_tiles[MAX_TILES];
__device__ int      g_ntiles;
__device__ int      g_rowmap[NROWS];
__device__ int      g_topk_idx[NROWS];
__device__ float    g_topk_w[NROWS];

__device__ __half   g_gu_h[(size_t)NROWS * 1024];       // fp16 [gate 0:512 | up 512:1024]
__device__ __half   g_hbuf[(size_t)NROWS * HDIM];
__device__ __half   g_sh_gu[(size_t)S_TOK * 4096];      // fp16 [shgate | shup]
__device__ __half   g_sh_h[(size_t)S_TOK * HSHARED];
__device__ __half   g_x_r[(size_t)S_TOK * CDIM];

// fp16 weight copies (native [K][N] layouts preserved)
__device__ __half   g_w_gate[(size_t)EXP * CDIM * HDIM];
__device__ __half   g_w_up[(size_t)EXP * CDIM * HDIM];
__device__ __half   g_w_down[(size_t)EXP * HDIM * CDIM];
__device__ __half   g_w_shg[(size_t)CDIM * HSHARED];
__device__ __half   g_w_shu[(size_t)CDIM * HSHARED];
__device__ __half   g_w_shd[(size_t)HSHARED * CDIM];

// ---------------- helpers ----------------
__device__ __forceinline__ void mma_f16(float* c, const uint32_t* a, const uint32_t* b) {
    asm volatile(
        "mma.sync.aligned.m16n8k16.row.col.f32.f16.f16.f32 "
        "{%0,%1,%2,%3}, {%4,%5,%6,%7}, {%8,%9}, {%0,%1,%2,%3};"
        : "+f"(c[0]), "+f"(c[1]), "+f"(c[2]), "+f"(c[3])
        : "r"(a[0]), "r"(a[1]), "r"(a[2]), "r"(a[3]), "r"(b[0]), "r"(b[1]));
}
__device__ __forceinline__ void ldmatrix_x4(uint32_t* r, uint32_t addr) {
    asm volatile("ldmatrix.sync.aligned.m8n8.x4.shared.b16 {%0,%1,%2,%3}, [%4];"
                 : "=r"(r[0]), "=r"(r[1]), "=r"(r[2]), "=r"(r[3]) : "r"(addr));
}
__device__ __forceinline__ void ldmatrix_x4_trans(uint32_t* r, uint32_t addr) {
    asm volatile("ldmatrix.sync.aligned.m8n8.x4.trans.shared.b16 {%0,%1,%2,%3}, [%4];"
                 : "=r"(r[0]), "=r"(r[1]), "=r"(r[2]), "=r"(r[3]) : "r"(addr));
}
__device__ __forceinline__ void cp_async16(uint32_t dst, const void* src, int srcbytes) {
    asm volatile("cp.async.cg.shared.global [%0], [%1], 16, %2;"
                 :: "r"(dst), "l"(src), "r"(srcbytes));
}

// ---------------- prep: f32 -> f16 convert copy ----------------
__global__ void half_copy(const float4* __restrict__ src, __half2* __restrict__ dst,
                          long long n4) {
    long long i = (long long)blockIdx.x * blockDim.x + threadIdx.x;
    if (i >= n4) return;
    float4 v = src[i];
    dst[i * 2 + 0] = __floats2half2_rn(v.x, v.y);
    dst[i * 2 + 1] = __floats2half2_rn(v.z, v.w);
}

// ---------------- routing kernels (verified correct) ----------------
__global__ void zero_counts_kernel() {
    if (threadIdx.x < EXP) g_counts[threadIdx.x] = 0;
}

__global__ void router_kernel(const float* __restrict__ x,
                              const float* __restrict__ rw,
                              const float* __restrict__ ebias) {
    int t = blockIdx.x;
    __shared__ float xs[CDIM];
    __shared__ float sc[EXP];

    const float* xrow = x + (size_t)t * CDIM;
    for (int c = threadIdx.x * 4; c < CDIM; c += blockDim.x * 4)
        *(float4*)&xs[c] = *(const float4*)&xrow[c];
    __syncthreads();

    int wid = threadIdx.x >> 5, lane = threadIdx.x & 31;
    for (int i = 0; i < 8; i++) {
        int e = wid * 8 + i;
        const float* w = rw + (size_t)e * CDIM;
        float s = 0.f;
        for (int c = lane; c < CDIM; c += 32) s += xs[c] * w[c];
        #pragma unroll
        for (int o = 16; o > 0; o >>= 1) s += __shfl_xor_sync(0xffffffffu, s, o);
        if (lane == 0) sc[e] = 1.f / (1.f + expf(-s));
    }
    __syncthreads();

    if (threadIdx.x == 0) {
        float sb[EXP];
        for (int e = 0; e < EXP; e++) sb[e] = sc[e] + ebias[e];
        float grp[NGRP];
        for (int g = 0; g < NGRP; g++) {
            float m1 = -1e30f, m2 = -1e30f;
            for (int j = 0; j < EPG; j++) {
                float v = sb[g * EPG + j];
                if (v > m1) { m2 = m1; m1 = v; }
                else if (v > m2) m2 = v;
            }
            grp[g] = m1 + m2;
        }
        bool gsel[NGRP] = {};
        for (int it = 0; it < TGRP; it++) {
            float best = -1e30f; int bi = 0;
            for (int g = 0; g < NGRP; g++)
                if (!gsel[g] && grp[g] > best) { best = grp[g]; bi = g; }
            gsel[bi] = true;
        }
        bool eused[EXP] = {};
        int idx[TOPK]; float wv[TOPK]; float wsum = 0.f;
        for (int it = 0; it < TOPK; it++) {
            float best = -1e30f; int bi = 0;
            for (int e = 0; e < EXP; e++)
                if (gsel[e / EPG] && !eused[e] && sb[e] > best) { best = sb[e]; bi = e; }
            eused[bi] = true; idx[it] = bi;
            wv[it] = sc[bi]; wsum += sc[bi];
        }
        float inv = 1.f / (wsum + 1e-20f);
        for (int it = 0; it < TOPK; it++) {
            g_topk_idx[t * TOPK + it] = idx[it];
            g_topk_w[t * TOPK + it]   = wv[it] * inv;
            atomicAdd(&g_counts[idx[it]], 1);
        }
    }
}

__global__ void setup_kernel() {
    int off = 0, nt = 0;
    for (int e = 0; e < EXP; e++) {
        g_offsets[e] = off;
        g_cursor[e]  = off;
        int c = g_counts[e];
        for (int r = 0; r < c; r += 128) {
            g_tiles[nt].e = e;
            g_tiles[nt].row_start = off + r;
            g_tiles[nt].rows = min(128, c - r);
            nt++;
        }
        off += c;
    }
    g_offsets[EXP] = off;
    g_ntiles = nt;
}

__global__ void assign_kernel() {
    int d = blockIdx.x * blockDim.x + threadIdx.x;
    if (d >= NROWS) return;
    int e = g_topk_idx[d];
    int pos = atomicAdd(&g_cursor[e], 1);
    g_rowmap[pos] = d;
}

// ================= fp16 tensor-core GEMM v3 =================
// 128 threads (4 warps, 2x2), BM=BN=128, BK=32, 4-stage cp.async, 2 CTAs/SM.
// Warp tile 64x64 (identical fragment code/numerics to the 256-thread version).
// MODE 0: fp32 store. MODE 1: fp16 store. MODE 2: atomicAdd scaled rows into
// CoutF[rowmap[row]/TOPK]. Dual-B: tile n0 < Nb reads B0, else B1 at n0-Nb.
// INDIRECT: A rows gathered via g_rowmap (tokens in A base = x_r).
#define GEMM_THREADS 128
#define STAGES 4
#define A_STRIDE_H 40
#define B_STRIDE_H 136
#define A_SZ_H (128 * A_STRIDE_H)           // 5120 halfs
#define B_SZ_H (32 * B_STRIDE_H)            // 4352 halfs
#define PIPE_H (STAGES * (A_SZ_H + B_SZ_H)) // 37888 halfs = 75776 B
#define GEMM_SMEM_BYTES (PIPE_H * 2 + 512)  // + tokmap

template <bool GROUPED, bool INDIRECT, int MODE>
__global__ void __launch_bounds__(GEMM_THREADS, 2) mma_gemm(
    const __half* __restrict__ A, const __half* __restrict__ B0,
    const __half* __restrict__ B1, float* __restrict__ CoutF,
    __half* __restrict__ CoutH,
    int Kd, int Nb, int N, long long strideB,
    const int* __restrict__ rowmap, const float* __restrict__ rowscale) {
    extern __shared__ __half smem_h[];
    int* tokmap = (int*)(smem_h + PIPE_H);

    int row_start, rows, e;
    if (GROUPED) {
        if ((int)blockIdx.y >= g_ntiles) return;
        TileDesc td = g_tiles[blockIdx.y];
        e = td.e; row_start = td.row_start; rows = td.rows;
    } else {
        e = 0; row_start = blockIdx.y * 128; rows = 128;
    }
    int n0 = blockIdx.x * 128;
    const __half* Bm = (n0 < Nb) ? B0 : B1;
    int ncol0 = (n0 < Nb) ? n0 : n0 - Nb;
    const __half* Bptr = Bm + (long long)e * strideB + ncol0;
    const __half* Aptr = A + (long long)row_start * Kd;

    int tid = threadIdx.x;
    int lane = tid & 31, wid = tid >> 5;
    int g = lane >> 2, tig = lane & 3;
    int wmb = (wid >> 1) * 64;
    int wnb = (wid & 1) * 64;

    if (INDIRECT) {
        tokmap[tid] = (tid < rows) ? (g_rowmap[row_start + tid] / TOPK) : -1;
        __syncthreads();
    }

    uint32_t sb = (uint32_t)__cvta_generic_to_shared(smem_h);

    float acc[4][8][4];
    #pragma unroll
    for (int mi = 0; mi < 4; mi++)
        #pragma unroll
        for (int ni = 0; ni < 8; ni++)
            #pragma unroll
            for (int q = 0; q < 4; q++) acc[mi][ni][q] = 0.f;

    const int T = Kd >> 5;

    auto issue = [&](int stage, int it) {
        int kk = it * 32;
        uint32_t abase = sb + (uint32_t)(stage * A_SZ_H) * 2u;
        uint32_t bbase = sb + (uint32_t)(STAGES * A_SZ_H + stage * B_SZ_H) * 2u;
        // A tile: 128 rows x 4 chunks(16B) = 512 chunks, 4/thread
        #pragma unroll
        for (int i = 0; i < 4; i++) {
            int c = tid + i * 128;
            int r = c >> 2, j = c & 3;
            const __half* src;
            int vb = 16;
            if (INDIRECT) {
                int tok = tokmap[r];
                if (tok < 0) { vb = 0; src = A; }
                else src = A + (long long)tok * Kd + kk + j * 8;
            } else {
                src = Aptr + (long long)r * Kd + kk + j * 8;
                if (GROUPED && r >= rows) { vb = 0; src = Aptr; }
            }
            cp_async16(abase + (uint32_t)(r * A_STRIDE_H + j * 8) * 2u, src, vb);
        }
        // B tile: 32 rows x 16 chunks = 512 chunks, 4/thread
        #pragma unroll
        for (int i = 0; i < 4; i++) {
            int c = tid + i * 128;
            int r = c >> 4, j = c & 15;
            cp_async16(bbase + (uint32_t)(r * B_STRIDE_H + j * 8) * 2u,
                       Bptr + (long long)(kk + r) * Nb + j * 8, 16);
        }
        asm volatile("cp.async.commit_group;" ::: "memory");
    };

    issue(0, 0);
    issue(1, 1);
    issue(2, 2);

    int lhalf = lane & 15, lsel8 = (lane >> 4) << 3;
    for (int it = 0; it < T; it++) {
        int stage = it & 3;
        asm volatile("cp.async.wait_group 2;" ::: "memory");
        __syncthreads();
        if (it + 3 < T) issue((it + 3) & 3, it + 3);

        uint32_t abase = sb + (uint32_t)(stage * A_SZ_H) * 2u;
        uint32_t bbase = sb + (uint32_t)(STAGES * A_SZ_H + stage * B_SZ_H) * 2u;

        #pragma unroll
        for (int ks = 0; ks < 2; ks++) {
            int k0 = ks * 16;
            uint32_t af[4][4], bf[4][4];
            #pragma unroll
            for (int mi = 0; mi < 4; mi++)
                ldmatrix_x4(af[mi], abase +
                    (uint32_t)((wmb + mi * 16 + lhalf) * A_STRIDE_H + k0 + lsel8) * 2u);
            #pragma unroll
            for (int nc = 0; nc < 4; nc++)
                ldmatrix_x4_trans(bf[nc], bbase +
                    (uint32_t)((k0 + lhalf) * B_STRIDE_H + wnb + nc * 16 + lsel8) * 2u);
            #pragma unroll
            for (int mi = 0; mi < 4; mi++)
                #pragma unroll
                for (int nc = 0; nc < 4; nc++) {
                    mma_f16(acc[mi][2 * nc + 0], af[mi], &bf[nc][0]);
                    mma_f16(acc[mi][2 * nc + 1], af[mi], &bf[nc][2]);
                }
        }
    }

    // ---- epilogue ----
    #pragma unroll
    for (int mi = 0; mi < 4; mi++) {
        #pragma unroll
        for (int h = 0; h < 2; h++) {
            int rl = wmb + mi * 16 + g + 8 * h;
            if (GROUPED && rl >= rows) continue;
            if (MODE == 2) {
                int d = rowmap[row_start + rl];
                float scale = rowscale[d];
                float* dst = CoutF + (size_t)(d / TOPK) * N;
                #pragma unroll
                for (int ni = 0; ni < 8; ni++) {
                    int col = n0 + wnb + ni * 8 + 2 * tig;
                    atomicAdd(dst + col,     acc[mi][ni][2 * h + 0] * scale);
                    atomicAdd(dst + col + 1, acc[mi][ni][2 * h + 1] * scale);
                }
            } else if (MODE == 1) {
                __half* dst = CoutH + (size_t)(row_start + rl) * N;
                #pragma unroll
                for (int ni = 0; ni < 8; ni++) {
                    int col = n0 + wnb + ni * 8 + 2 * tig;
                    *(__half2*)(dst + col) =
                        __floats2half2_rn(acc[mi][ni][2 * h + 0], acc[mi][ni][2 * h + 1]);
                }
            } else {
                float* dst = CoutF + (size_t)(row_start + rl) * N;
                #pragma unroll
                for (int ni = 0; ni < 8; ni++) {
                    int col = n0 + wnb + ni * 8 + 2 * tig;
                    float2 v;
                    v.x = acc[mi][ni][2 * h + 0];
                    v.y = acc[mi][ni][2 * h + 1];
                    *(float2*)(dst + col) = v;
                }
            }
        }
    }
}

// ---------------- swiglu on fp16 gu buffer: h = silu(g) * u ----------------
__global__ void swiglu_h(const __half* __restrict__ gu, __half* __restrict__ h,
                         long long total8, int jshift, int guStride, int off) {
    long long i = (long long)blockIdx.x * blockDim.x + threadIdx.x;
    if (i >= total8) return;
    long long row = i >> jshift;
    int j = (int)(i & ((1LL << jshift) - 1)) * 8;
    const __half2* gp = (const __half2*)(gu + row * guStride + j);
    const __half2* up = (const __half2*)(gu + row * guStride + off + j);
    __half2* hp = (__half2*)(h + row * (long long)off + j);
    #pragma unroll
    for (int q = 0; q < 4; q++) {
        float2 g2 = __half22float2(gp[q]);
        float2 u2 = __half22float2(up[q]);
        float r0 = g2.x / (1.f + expf(-g2.x)) * u2.x;
        float r1 = g2.y / (1.f + expf(-g2.y)) * u2.y;
        hp[q] = __floats2half2_rn(r0, r1);
    }
}

// ---------------- launch ----------------
extern "C" void kernel_launch(void* const* d_in, const int* in_sizes, int n_in,
                              void* d_out, int out_size) {
    const float* x        = (const float*)d_in[0];
    const float* router_w = (const float*)d_in[1];
    const float* e_bias   = (const float*)d_in[2];
    const float* gate_w   = (const float*)d_in[3];
    const float* up_w     = (const float*)d_in[4];
    const float* down_w   = (const float*)d_in[5];
    const float* sh_gate  = (const float*)d_in[6];
    const float* sh_up    = (const float*)d_in[7];
    const float* sh_down  = (const float*)d_in[8];
    float* out = (float*)d_out;

    __half *p_gu_h, *p_hbuf, *p_sh_gu, *p_sh_h, *p_x_r;
    __half *p_w_gate, *p_w_up, *p_w_down, *p_w_shg, *p_w_shu, *p_w_shd;
    float *p_topk_w;
    int* p_rowmap;
    cudaGetSymbolAddress((void**)&p_gu_h,     g_gu_h);
    cudaGetSymbolAddress((void**)&p_hbuf,     g_hbuf);
    cudaGetSymbolAddress((void**)&p_sh_gu,    g_sh_gu);
    cudaGetSymbolAddress((void**)&p_sh_h,     g_sh_h);
    cudaGetSymbolAddress((void**)&p_topk_w,   g_topk_w);
    cudaGetSymbolAddress((void**)&p_rowmap,   g_rowmap);
    cudaGetSymbolAddress((void**)&p_x_r,      g_x_r);
    cudaGetSymbolAddress((void**)&p_w_gate,   g_w_gate);
    cudaGetSymbolAddress((void**)&p_w_up,     g_w_up);
    cudaGetSymbolAddress((void**)&p_w_down,   g_w_down);
    cudaGetSymbolAddress((void**)&p_w_shg,    g_w_shg);
    cudaGetSymbolAddress((void**)&p_w_shu,    g_w_shu);
    cudaGetSymbolAddress((void**)&p_w_shd,    g_w_shd);

    cudaFuncSetAttribute((const void*)mma_gemm<false, false, 0>,
                         cudaFuncAttributeMaxDynamicSharedMemorySize, GEMM_SMEM_BYTES);
    cudaFuncSetAttribute((const void*)mma_gemm<false, false, 1>,
                         cudaFuncAttributeMaxDynamicSharedMemorySize, GEMM_SMEM_BYTES);
    cudaFuncSetAttribute((const void*)mma_gemm<true, true, 1>,
                         cudaFuncAttributeMaxDynamicSharedMemorySize, GEMM_SMEM_BYTES);
    cudaFuncSetAttribute((const void*)mma_gemm<true, false, 2>,
                         cudaFuncAttributeMaxDynamicSharedMemorySize, GEMM_SMEM_BYTES);

    long long n4;

    // launches 0-2: prep for shared expert
    n4 = (long long)S_TOK * CDIM / 4;
    half_copy<<<(unsigned)((n4 + 255) / 256), 256>>>((const float4*)x, (__half2*)p_x_r, n4);
    n4 = (long long)CDIM * HSHARED / 4;
    half_copy<<<(unsigned)((n4 + 255) / 256), 256>>>((const float4*)sh_gate, (__half2*)p_w_shg, n4);
    half_copy<<<(unsigned)((n4 + 255) / 256), 256>>>((const float4*)sh_up,   (__half2*)p_w_shu, n4);

    // launches 3-4: routing part 1
    zero_counts_kernel<<<1, 64>>>();
    router_kernel<<<S_TOK, 256>>>(x, router_w, e_bias);

    // launch 5: shared gu GEMM (fp16 out, dual-B) — profiled
    mma_gemm<false, false, 1><<<dim3(4096 / 128, S_TOK / 128), GEMM_THREADS, GEMM_SMEM_BYTES>>>(
        p_x_r, p_w_shg, p_w_shu, nullptr, p_sh_gu, 1024, 2048, 4096, 0, nullptr, nullptr);
    {
        long long total8 = (long long)S_TOK * (HSHARED / 8);
        swiglu_h<<<(unsigned)((total8 + 255) / 256), 256>>>(
            p_sh_gu, p_sh_h, total8, 8, 4096, 2048);
    }
    n4 = (long long)CDIM * HSHARED / 4;
    half_copy<<<(unsigned)((n4 + 255) / 256), 256>>>((const float4*)sh_down, (__half2*)p_w_shd, n4);
    // shared down: fp32 straight into out (full coverage)
    mma_gemm<false, false, 0><<<dim3(CDIM / 128, S_TOK / 128), GEMM_THREADS, GEMM_SMEM_BYTES>>>(
        p_sh_h, p_w_shd, nullptr, out, nullptr, 2048, 1024, 1024, 0, nullptr, nullptr);

    // expert weight prep + routing part 2
    n4 = (long long)EXP * CDIM * HDIM / 4;
    half_copy<<<(unsigned)((n4 + 255) / 256), 256>>>((const float4*)gate_w, (__half2*)p_w_gate, n4);
    half_copy<<<(unsigned)((n4 + 255) / 256), 256>>>((const float4*)up_w,   (__half2*)p_w_up,   n4);
    half_copy<<<(unsigned)((n4 + 255) / 256), 256>>>((const float4*)down_w, (__half2*)p_w_down, n4);
    setup_kernel<<<1, 1>>>();
    assign_kernel<<<NROWS / 256, 256>>>();

    // routed gu GEMM (fp16 out, dual-B, grouped, indirect A from x_r)
    mma_gemm<true, true, 1><<<dim3(1024 / 128, MAX_TILES), GEMM_THREADS, GEMM_SMEM_BYTES>>>(
        p_x_r, p_w_gate, p_w_up, nullptr, p_gu_h, 1024, 512, 1024,
        (long long)CDIM * HDIM, nullptr, nullptr);
    {
        long long total8 = (long long)NROWS * (HDIM / 8);
        swiglu_h<<<(unsigned)((total8 + 255) / 256), 256>>>(
            p_gu_h, p_hbuf, total8, 6, 1024, 512);
    }
    // routed down: atomicAdd scaled rows directly into out
    mma_gemm<true, false, 2><<<dim3(CDIM / 128, MAX_TILES), GEMM_THREADS, GEMM_SMEM_BYTES>>>(
        p_hbuf, p_w_down, nullptr, out, nullptr, 512, 1024, 1024,
        (long long)HDIM * CDIM, p_rowmap, p_topk_w);
}

// round 10
// speedup vs baseline: 1.2103x; 1.0026x over previous
#include <cuda_runtime.h>
#include <cuda_fp16.h>
#include <math.h>
#include <stdint.h>

// ---------------- problem constants ----------------
#define S_TOK   4096
#define CDIM    1024
#define EXP     64
#define TOPK    8
#define NGRP    8
#define EPG     8
#define TGRP    4
#define HDIM    512
#define HSHARED 2048
#define NROWS   (S_TOK * TOPK)   // 32768
#define MAX_TILES 320

// ---------------- scratch (static device globals) ----------------
struct TileDesc { int e; int row_start; int rows; };

__device__ int      g_counts[EXP];
__device__ int      g_offsets[EXP + 1];
__device__ int      g_cursor[EXP];
__device__ TileDesc g_tiles[MAX_TILES];
__device__ int      g_ntiles;
__device__ int      g_rowmap[NROWS];
__device__ int      g_topk_idx[NROWS];
__device__ float    g_topk_w[NROWS];

__device__ __half   g_hbuf[(size_t)NROWS * HDIM];       // routed h (post-swiglu)
__device__ __half   g_sh_h[(size_t)S_TOK * HSHARED];    // shared h (post-swiglu)
__device__ __half   g_x_r[(size_t)S_TOK * CDIM];

// fp16 weight copies (native [K][N] layouts preserved)
__device__ __half   g_w_gate[(size_t)EXP * CDIM * HDIM];
__device__ __half   g_w_up[(size_t)EXP * CDIM * HDIM];
__device__ __half   g_w_down[(size_t)EXP * HDIM * CDIM];
__device__ __half   g_w_shg[(size_t)CDIM * HSHARED];
__device__ __half   g_w_shu[(size_t)CDIM * HSHARED];
__device__ __half   g_w_shd[(size_t)HSHARED * CDIM];

// ---------------- helpers ----------------
__device__ __forceinline__ void mma_f16(float* c, const uint32_t* a, const uint32_t* b) {
    asm volatile(
        "mma.sync.aligned.m16n8k16.row.col.f32.f16.f16.f32 "
        "{%0,%1,%2,%3}, {%4,%5,%6,%7}, {%8,%9}, {%0,%1,%2,%3};"
        : "+f"(c[0]), "+f"(c[1]), "+f"(c[2]), "+f"(c[3])
        : "r"(a[0]), "r"(a[1]), "r"(a[2]), "r"(a[3]), "r"(b[0]), "r"(b[1]));
}
__device__ __forceinline__ void ldmatrix_x4(uint32_t* r, uint32_t addr) {
    asm volatile("ldmatrix.sync.aligned.m8n8.x4.shared.b16 {%0,%1,%2,%3}, [%4];"
                 : "=r"(r[0]), "=r"(r[1]), "=r"(r[2]), "=r"(r[3]) : "r"(addr));
}
__device__ __forceinline__ void ldmatrix_x4_trans(uint32_t* r, uint32_t addr) {
    asm volatile("ldmatrix.sync.aligned.m8n8.x4.trans.shared.b16 {%0,%1,%2,%3}, [%4];"
                 : "=r"(r[0]), "=r"(r[1]), "=r"(r[2]), "=r"(r[3]) : "r"(addr));
}
__device__ __forceinline__ void cp_async16(uint32_t dst, const void* src, int srcbytes) {
    asm volatile("cp.async.cg.shared.global [%0], [%1], 16, %2;"
                 :: "r"(dst), "l"(src), "r"(srcbytes));
}

// ---------------- prep: f32 -> f16 convert copy ----------------
__global__ void half_copy(const float4* __restrict__ src, __half2* __restrict__ dst,
                          long long n4) {
    long long i = (long long)blockIdx.x * blockDim.x + threadIdx.x;
    if (i >= n4) return;
    float4 v = src[i];
    dst[i * 2 + 0] = __floats2half2_rn(v.x, v.y);
    dst[i * 2 + 1] = __floats2half2_rn(v.z, v.w);
}

// ---------------- routing ----------------
__global__ void zero_counts_kernel() {
    if (threadIdx.x < EXP) g_counts[threadIdx.x] = 0;
}

// router also emits fp16 x_r (x rounded to fp16) — saves a separate pass.
__global__ void router_kernel(const float* __restrict__ x,
                              const float* __restrict__ rw,
                              const float* __restrict__ ebias,
                              __half* __restrict__ x_r) {
    int t = blockIdx.x;
    __shared__ float xs[CDIM];
    __shared__ float sc[EXP];

    const float* xrow = x + (size_t)t * CDIM;
    for (int c = threadIdx.x * 4; c < CDIM; c += blockDim.x * 4)
        *(float4*)&xs[c] = *(const float4*)&xrow[c];
    __syncthreads();

    // write fp16 copy
    {
        int c = threadIdx.x * 4;
        __half2* dst = (__half2*)(x_r + (size_t)t * CDIM + c);
        dst[0] = __floats2half2_rn(xs[c], xs[c + 1]);
        dst[1] = __floats2half2_rn(xs[c + 2], xs[c + 3]);
    }

    int wid = threadIdx.x >> 5, lane = threadIdx.x & 31;
    for (int i = 0; i < 8; i++) {
        int e = wid * 8 + i;
        const float* w = rw + (size_t)e * CDIM;
        float s = 0.f;
        for (int c = lane; c < CDIM; c += 32) s += xs[c] * w[c];
        #pragma unroll
        for (int o = 16; o > 0; o >>= 1) s += __shfl_xor_sync(0xffffffffu, s, o);
        if (lane == 0) sc[e] = 1.f / (1.f + expf(-s));
    }
    __syncthreads();

    if (threadIdx.x == 0) {
        float sb[EXP];
        for (int e = 0; e < EXP; e++) sb[e] = sc[e] + ebias[e];
        float grp[NGRP];
        for (int g = 0; g < NGRP; g++) {
            float m1 = -1e30f, m2 = -1e30f;
            for (int j = 0; j < EPG; j++) {
                float v = sb[g * EPG + j];
                if (v > m1) { m2 = m1; m1 = v; }
                else if (v > m2) m2 = v;
            }
            grp[g] = m1 + m2;
        }
        bool gsel[NGRP] = {};
        for (int it = 0; it < TGRP; it++) {
            float best = -1e30f; int bi = 0;
            for (int g = 0; g < NGRP; g++)
                if (!gsel[g] && grp[g] > best) { best = grp[g]; bi = g; }
            gsel[bi] = true;
        }
        bool eused[EXP] = {};
        int idx[TOPK]; float wv[TOPK]; float wsum = 0.f;
        for (int it = 0; it < TOPK; it++) {
            float best = -1e30f; int bi = 0;
            for (int e = 0; e < EXP; e++)
                if (gsel[e / EPG] && !eused[e] && sb[e] > best) { best = sb[e]; bi = e; }
            eused[bi] = true; idx[it] = bi;
            wv[it] = sc[bi]; wsum += sc[bi];
        }
        float inv = 1.f / (wsum + 1e-20f);
        for (int it = 0; it < TOPK; it++) {
            g_topk_idx[t * TOPK + it] = idx[it];
            g_topk_w[t * TOPK + it]   = wv[it] * inv;
            atomicAdd(&g_counts[idx[it]], 1);
        }
    }
}

// 64-thread prefix + tile build
__global__ void setup_kernel() {
    __shared__ int s[EXP];
    __shared__ int s2[EXP];
    int t = threadIdx.x;
    int c = g_counts[t];
    int nt_e = (c + 127) >> 7;
    s[t] = c; s2[t] = nt_e;
    __syncthreads();
    for (int off = 1; off < EXP; off <<= 1) {
        int v = (t >= off) ? s[t - off] : 0;
        int v2 = (t >= off) ? s2[t - off] : 0;
        __syncthreads();
        s[t] += v; s2[t] += v2;
        __syncthreads();
    }
    int off_e = s[t] - c;            // exclusive row prefix
    int toff_e = s2[t] - nt_e;       // exclusive tile prefix
    g_offsets[t] = off_e;
    g_cursor[t]  = off_e;
    if (t == EXP - 1) { g_offsets[EXP] = s[t]; g_ntiles = s2[t]; }
    for (int r = 0, k = 0; r < c; r += 128, k++) {
        g_tiles[toff_e + k].e = t;
        g_tiles[toff_e + k].row_start = off_e + r;
        g_tiles[toff_e + k].rows = min(128, c - r);
    }
}

__global__ void assign_kernel() {
    int d = blockIdx.x * blockDim.x + threadIdx.x;
    if (d >= NROWS) return;
    int e = g_topk_idx[d];
    int pos = atomicAdd(&g_cursor[e], 1);
    g_rowmap[pos] = d;
}

// ---------------- GEMM tiling constants ----------------
#define GEMM_THREADS 128
#define STAGES 4
#define A_STRIDE_H 40
#define B_STRIDE_H 136
#define A_SZ_H (128 * A_STRIDE_H)           // 5120 halfs
#define B_SZ_H (32 * B_STRIDE_H)            // 4352 halfs
#define PIPE_H (STAGES * (A_SZ_H + B_SZ_H)) // 37888 halfs = 75776 B
#define GEMM_SMEM_BYTES (PIPE_H * 2 + 512)  // + tokmap

// ================= fused gate|up GEMM + in-register SwiGLU =================
// CTA covers 64 h-cols [h0, h0+64). B tile cols (128) arranged:
//   [gate h0..h0+31 | up h0..h0+31 | gate h0+32..h0+63 | up h0+32..h0+63]
// Each warp-tile thread then holds matching (g,u) pairs: acc[mi][ni] (ni<4) = gate,
// acc[mi][ni+4] = up of the SAME h column. Epilogue: fp16 silu(g)*u, no exchange.
// INDIRECT: A rows gathered via g_rowmap (tokens into A = x_r).
template <bool GROUPED, bool INDIRECT>
__global__ void __launch_bounds__(GEMM_THREADS, 2) gu_gemm(
    const __half* __restrict__ A, const __half* __restrict__ Bg,
    const __half* __restrict__ Bu, __half* __restrict__ Hout,
    int Kd, int Nh, long long strideB) {
    extern __shared__ __half smem_h[];
    int* tokmap = (int*)(smem_h + PIPE_H);

    int row_start, rows, e;
    if (GROUPED) {
        if ((int)blockIdx.y >= g_ntiles) return;
        TileDesc td = g_tiles[blockIdx.y];
        e = td.e; row_start = td.row_start; rows = td.rows;
    } else {
        e = 0; row_start = blockIdx.y * 128; rows = 128;
    }
    int h0 = blockIdx.x * 64;
    const __half* Bgp = Bg + (long long)e * strideB + h0;
    const __half* Bup = Bu + (long long)e * strideB + h0;
    const __half* Aptr = A + (long long)row_start * Kd;

    int tid = threadIdx.x;
    int lane = tid & 31, wid = tid >> 5;
    int g = lane >> 2, tig = lane & 3;
    int wmb = (wid >> 1) * 64;
    int wnb = (wid & 1) * 64;

    if (INDIRECT) {
        tokmap[tid] = (tid < rows) ? (g_rowmap[row_start + tid] / TOPK) : -1;
        __syncthreads();
    }

    uint32_t sb = (uint32_t)__cvta_generic_to_shared(smem_h);

    float acc[4][8][4];
    #pragma unroll
    for (int mi = 0; mi < 4; mi++)
        #pragma unroll
        for (int ni = 0; ni < 8; ni++)
            #pragma unroll
            for (int q = 0; q < 4; q++) acc[mi][ni][q] = 0.f;

    const int T = Kd >> 5;

    auto issue = [&](int stage, int it) {
        int kk = it * 32;
        uint32_t abase = sb + (uint32_t)(stage * A_SZ_H) * 2u;
        uint32_t bbase = sb + (uint32_t)(STAGES * A_SZ_H + stage * B_SZ_H) * 2u;
        #pragma unroll
        for (int i = 0; i < 4; i++) {
            int c = tid + i * 128;
            int r = c >> 2, j = c & 3;
            const __half* src;
            int vb = 16;
            if (INDIRECT) {
                int tok = tokmap[r];
                if (tok < 0) { vb = 0; src = A; }
                else src = A + (long long)tok * Kd + kk + j * 8;
            } else {
                src = Aptr + (long long)r * Kd + kk + j * 8;
                if (GROUPED && r >= rows) { vb = 0; src = Aptr; }
            }
            cp_async16(abase + (uint32_t)(r * A_STRIDE_H + j * 8) * 2u, src, vb);
        }
        // B tile: 32 rows x 16 chunks; chunk j -> seg = j>>2 (g,u,g,u), inner = (j&3)*8
        #pragma unroll
        for (int i = 0; i < 4; i++) {
            int c = tid + i * 128;
            int r = c >> 4, j = c & 15;
            int seg = j >> 2, inner = (j & 3) * 8;
            const __half* base = (seg & 1) ? Bup : Bgp;
            const __half* src = base + (long long)(kk + r) * Nh + (seg >> 1) * 32 + inner;
            cp_async16(bbase + (uint32_t)(r * B_STRIDE_H + j * 8) * 2u, src, 16);
        }
        asm volatile("cp.async.commit_group;" ::: "memory");
    };

    issue(0, 0);
    issue(1, 1);
    issue(2, 2);

    int lhalf = lane & 15, lsel8 = (lane >> 4) << 3;
    for (int it = 0; it < T; it++) {
        int stage = it & 3;
        asm volatile("cp.async.wait_group 2;" ::: "memory");
        __syncthreads();
        if (it + 3 < T) issue((it + 3) & 3, it + 3);

        uint32_t abase = sb + (uint32_t)(stage * A_SZ_H) * 2u;
        uint32_t bbase = sb + (uint32_t)(STAGES * A_SZ_H + stage * B_SZ_H) * 2u;

        #pragma unroll
        for (int ks = 0; ks < 2; ks++) {
            int k0 = ks * 16;
            uint32_t af[4][4], bf[4][4];
            #pragma unroll
            for (int mi = 0; mi < 4; mi++)
                ldmatrix_x4(af[mi], abase +
                    (uint32_t)((wmb + mi * 16 + lhalf) * A_STRIDE_H + k0 + lsel8) * 2u);
            #pragma unroll
            for (int nc = 0; nc < 4; nc++)
                ldmatrix_x4_trans(bf[nc], bbase +
                    (uint32_t)((k0 + lhalf) * B_STRIDE_H + wnb + nc * 16 + lsel8) * 2u);
            #pragma unroll
            for (int mi = 0; mi < 4; mi++)
                #pragma unroll
                for (int nc = 0; nc < 4; nc++) {
                    mma_f16(acc[mi][2 * nc + 0], af[mi], &bf[nc][0]);
                    mma_f16(acc[mi][2 * nc + 1], af[mi], &bf[nc][2]);
                }
        }
    }

    // ---- in-register SwiGLU epilogue ----
    int hbase = h0 + (wnb >> 1);
    #pragma unroll
    for (int mi = 0; mi < 4; mi++) {
        #pragma unroll
        for (int h = 0; h < 2; h++) {
            int rl = wmb + mi * 16 + g + 8 * h;
            if (GROUPED && rl >= rows) continue;
            __half* dst = Hout + (size_t)(row_start + rl) * Nh + hbase;
            #pragma unroll
            for (int ni = 0; ni < 4; ni++) {
                float g0 = acc[mi][ni][2 * h + 0];
                float g1 = acc[mi][ni][2 * h + 1];
                float u0 = acc[mi][ni + 4][2 * h + 0];
                float u1 = acc[mi][ni + 4][2 * h + 1];
                float r0 = g0 / (1.f + expf(-g0)) * u0;
                float r1 = g1 / (1.f + expf(-g1)) * u1;
                *(__half2*)(dst + ni * 8 + 2 * tig) = __floats2half2_rn(r0, r1);
            }
        }
    }
}

// ================= plain fp16 GEMM (down projections) =================
// MODE 0: fp32 store. MODE 2: atomicAdd scaled rows into CoutF[rowmap[row]/TOPK].
template <bool GROUPED, int MODE>
__global__ void __launch_bounds__(GEMM_THREADS, 2) mma_gemm(
    const __half* __restrict__ A, const __half* __restrict__ B0,
    float* __restrict__ CoutF,
    int Kd, int N, long long strideB,
    const int* __restrict__ rowmap, const float* __restrict__ rowscale) {
    extern __shared__ __half smem_h[];

    int row_start, rows, e;
    if (GROUPED) {
        if ((int)blockIdx.y >= g_ntiles) return;
        TileDesc td = g_tiles[blockIdx.y];
        e = td.e; row_start = td.row_start; rows = td.rows;
    } else {
        e = 0; row_start = blockIdx.y * 128; rows = 128;
    }
    int n0 = blockIdx.x * 128;
    const __half* Bptr = B0 + (long long)e * strideB + n0;
    const __half* Aptr = A + (long long)row_start * Kd;

    int tid = threadIdx.x;
    int lane = tid & 31, wid = tid >> 5;
    int g = lane >> 2, tig = lane & 3;
    int wmb = (wid >> 1) * 64;
    int wnb = (wid & 1) * 64;

    uint32_t sb = (uint32_t)__cvta_generic_to_shared(smem_h);

    float acc[4][8][4];
    #pragma unroll
    for (int mi = 0; mi < 4; mi++)
        #pragma unroll
        for (int ni = 0; ni < 8; ni++)
            #pragma unroll
            for (int q = 0; q < 4; q++) acc[mi][ni][q] = 0.f;

    const int T = Kd >> 5;

    auto issue = [&](int stage, int it) {
        int kk = it * 32;
        uint32_t abase = sb + (uint32_t)(stage * A_SZ_H) * 2u;
        uint32_t bbase = sb + (uint32_t)(STAGES * A_SZ_H + stage * B_SZ_H) * 2u;
        #pragma unroll
        for (int i = 0; i < 4; i++) {
            int c = tid + i * 128;
            int r = c >> 2, j = c & 3;
            const __half* src = Aptr + (long long)r * Kd + kk + j * 8;
            int vb = 16;
            if (GROUPED && r >= rows) { vb = 0; src = Aptr; }
            cp_async16(abase + (uint32_t)(r * A_STRIDE_H + j * 8) * 2u, src, vb);
        }
        #pragma unroll
        for (int i = 0; i < 4; i++) {
            int c = tid + i * 128;
            int r = c >> 4, j = c & 15;
            cp_async16(bbase + (uint32_t)(r * B_STRIDE_H + j * 8) * 2u,
                       Bptr + (long long)(kk + r) * N + j * 8, 16);
        }
        asm volatile("cp.async.commit_group;" ::: "memory");
    };

    issue(0, 0);
    issue(1, 1);
    issue(2, 2);

    int lhalf = lane & 15, lsel8 = (lane >> 4) << 3;
    for (int it = 0; it < T; it++) {
        int stage = it & 3;
        asm volatile("cp.async.wait_group 2;" ::: "memory");
        __syncthreads();
        if (it + 3 < T) issue((it + 3) & 3, it + 3);

        uint32_t abase = sb + (uint32_t)(stage * A_SZ_H) * 2u;
        uint32_t bbase = sb + (uint32_t)(STAGES * A_SZ_H + stage * B_SZ_H) * 2u;

        #pragma unroll
        for (int ks = 0; ks < 2; ks++) {
            int k0 = ks * 16;
            uint32_t af[4][4], bf[4][4];
            #pragma unroll
            for (int mi = 0; mi < 4; mi++)
                ldmatrix_x4(af[mi], abase +
                    (uint32_t)((wmb + mi * 16 + lhalf) * A_STRIDE_H + k0 + lsel8) * 2u);
            #pragma unroll
            for (int nc = 0; nc < 4; nc++)
                ldmatrix_x4_trans(bf[nc], bbase +
                    (uint32_t)((k0 + lhalf) * B_STRIDE_H + wnb + nc * 16 + lsel8) * 2u);
            #pragma unroll
            for (int mi = 0; mi < 4; mi++)
                #pragma unroll
                for (int nc = 0; nc < 4; nc++) {
                    mma_f16(acc[mi][2 * nc + 0], af[mi], &bf[nc][0]);
                    mma_f16(acc[mi][2 * nc + 1], af[mi], &bf[nc][2]);
                }
        }
    }

    #pragma unroll
    for (int mi = 0; mi < 4; mi++) {
        #pragma unroll
        for (int h = 0; h < 2; h++) {
            int rl = wmb + mi * 16 + g + 8 * h;
            if (GROUPED && rl >= rows) continue;
            if (MODE == 2) {
                int d = rowmap[row_start + rl];
                float scale = rowscale[d];
                float* dst = CoutF + (size_t)(d / TOPK) * N;
                #pragma unroll
                for (int ni = 0; ni < 8; ni++) {
                    int col = n0 + wnb + ni * 8 + 2 * tig;
                    atomicAdd(dst + col,     acc[mi][ni][2 * h + 0] * scale);
                    atomicAdd(dst + col + 1, acc[mi][ni][2 * h + 1] * scale);
                }
            } else {
                float* dst = CoutF + (size_t)(row_start + rl) * N;
                #pragma unroll
                for (int ni = 0; ni < 8; ni++) {
                    int col = n0 + wnb + ni * 8 + 2 * tig;
                    float2 v;
                    v.x = acc[mi][ni][2 * h + 0];
                    v.y = acc[mi][ni][2 * h + 1];
                    *(float2*)(dst + col) = v;
                }
            }
        }
    }
}

// ---------------- launch ----------------
extern "C" void kernel_launch(void* const* d_in, const int* in_sizes, int n_in,
                              void* d_out, int out_size) {
    const float* x        = (const float*)d_in[0];
    const float* router_w = (const float*)d_in[1];
    const float* e_bias   = (const float*)d_in[2];
    const float* gate_w   = (const float*)d_in[3];
    const float* up_w     = (const float*)d_in[4];
    const float* down_w   = (const float*)d_in[5];
    const float* sh_gate  = (const float*)d_in[6];
    const float* sh_up    = (const float*)d_in[7];
    const float* sh_down  = (const float*)d_in[8];
    float* out = (float*)d_out;

    __half *p_hbuf, *p_sh_h, *p_x_r;
    __half *p_w_gate, *p_w_up, *p_w_down, *p_w_shg, *p_w_shu, *p_w_shd;
    float *p_topk_w;
    int* p_rowmap;
    cudaGetSymbolAddress((void**)&p_hbuf,     g_hbuf);
    cudaGetSymbolAddress((void**)&p_sh_h,     g_sh_h);
    cudaGetSymbolAddress((void**)&p_topk_w,   g_topk_w);
    cudaGetSymbolAddress((void**)&p_rowmap,   g_rowmap);
    cudaGetSymbolAddress((void**)&p_x_r,      g_x_r);
    cudaGetSymbolAddress((void**)&p_w_gate,   g_w_gate);
    cudaGetSymbolAddress((void**)&p_w_up,     g_w_up);
    cudaGetSymbolAddress((void**)&p_w_down,   g_w_down);
    cudaGetSymbolAddress((void**)&p_w_shg,    g_w_shg);
    cudaGetSymbolAddress((void**)&p_w_shu,    g_w_shu);
    cudaGetSymbolAddress((void**)&p_w_shd,    g_w_shd);

    cudaFuncSetAttribute((const void*)gu_gemm<false, false>,
                         cudaFuncAttributeMaxDynamicSharedMemorySize, GEMM_SMEM_BYTES);
    cudaFuncSetAttribute((const void*)gu_gemm<true, true>,
                         cudaFuncAttributeMaxDynamicSharedMemorySize, GEMM_SMEM_BYTES);
    cudaFuncSetAttribute((const void*)mma_gemm<false, 0>,
                         cudaFuncAttributeMaxDynamicSharedMemorySize, GEMM_SMEM_BYTES);
    cudaFuncSetAttribute((const void*)mma_gemm<true, 2>,
                         cudaFuncAttributeMaxDynamicSharedMemorySize, GEMM_SMEM_BYTES);

    long long n4;

    // launches 0-1: shared gate/up weight conversion
    n4 = (long long)CDIM * HSHARED / 4;
    half_copy<<<(unsigned)((n4 + 255) / 256), 256>>>((const float4*)sh_gate, (__half2*)p_w_shg, n4);
    half_copy<<<(unsigned)((n4 + 255) / 256), 256>>>((const float4*)sh_up,   (__half2*)p_w_shu, n4);

    // launches 2-3: routing part 1 (router also emits x_r fp16)
    zero_counts_kernel<<<1, 64>>>();
    router_kernel<<<S_TOK, 256>>>(x, router_w, e_bias, p_x_r);

    // launch 4: shared down weight conversion
    n4 = (long long)CDIM * HSHARED / 4;
    half_copy<<<(unsigned)((n4 + 255) / 256), 256>>>((const float4*)sh_down, (__half2*)p_w_shd, n4);

    // launch 5: shared gu GEMM + fused swiglu (profiled)
    gu_gemm<false, false><<<dim3(HSHARED / 64, S_TOK / 128), GEMM_THREADS, GEMM_SMEM_BYTES>>>(
        p_x_r, p_w_shg, p_w_shu, p_sh_h, CDIM, HSHARED, 0);

    // launch 6: shared down GEMM -> out (fp32, full coverage)
    mma_gemm<false, 0><<<dim3(CDIM / 128, S_TOK / 128), GEMM_THREADS, GEMM_SMEM_BYTES>>>(
        p_sh_h, p_w_shd, out, HSHARED, CDIM, 0, nullptr, nullptr);

    // expert weight conversion + routing part 2
    n4 = (long long)EXP * CDIM * HDIM / 4;
    half_copy<<<(unsigned)((n4 + 255) / 256), 256>>>((const float4*)gate_w, (__half2*)p_w_gate, n4);
    half_copy<<<(unsigned)((n4 + 255) / 256), 256>>>((const float4*)up_w,   (__half2*)p_w_up,   n4);
    half_copy<<<(unsigned)((n4 + 255) / 256), 256>>>((const float4*)down_w, (__half2*)p_w_down, n4);
    setup_kernel<<<1, 64>>>();
    assign_kernel<<<NROWS / 256, 256>>>();

    // routed gu GEMM + fused swiglu (grouped, indirect A from x_r)
    gu_gemm<true, true><<<dim3(HDIM / 64, MAX_TILES), GEMM_THREADS, GEMM_SMEM_BYTES>>>(
        p_x_r, p_w_gate, p_w_up, p_hbuf, CDIM, HDIM, (long long)CDIM * HDIM);

    // routed down: atomicAdd scaled rows into out
    mma_gemm<true, 2><<<dim3(CDIM / 128, MAX_TILES), GEMM_THREADS, GEMM_SMEM_BYTES>>>(
        p_hbuf, p_w_down, out, HDIM, CDIM, (long long)HDIM * CDIM,
        p_rowmap, p_topk_w);
}

// round 11
// speedup vs baseline: 1.3603x; 1.1239x over previous
#include <cuda_runtime.h>
#include <cuda_fp16.h>
#include <math.h>
#include <stdint.h>

// ---------------- problem constants ----------------
#define S_TOK   4096
#define CDIM    1024
#define EXP     64
#define TOPK    8
#define NGRP    8
#define EPG     8
#define TGRP    4
#define HDIM    512
#define HSHARED 2048
#define NROWS   (S_TOK * TOPK)   // 32768
#define MAX_TILES 320

// ---------------- scratch (static device globals) ----------------
struct TileDesc { int e; int row_start; int rows; };

__device__ int      g_counts[EXP];
__device__ int      g_offsets[EXP + 1];
__device__ int      g_cursor[EXP];
__device__ TileDesc g_tiles[MAX_TILES];
__device__ int      g_ntiles;
__device__ int      g_rowmap[NROWS];
__device__ int      g_topk_idx[NROWS];
__device__ float    g_topk_w[NROWS];
__device__ float    g_scores[(size_t)S_TOK * EXP];

__device__ __half   g_hbuf[(size_t)NROWS * HDIM];       // routed h (post-swiglu)
__device__ __half   g_sh_h[(size_t)S_TOK * HSHARED];    // shared h (post-swiglu)
__device__ __half   g_x_r[(size_t)S_TOK * CDIM];

// fp16 weight copies (native [K][N] layouts preserved)
__device__ __half   g_w_gate[(size_t)EXP * CDIM * HDIM];
__device__ __half   g_w_up[(size_t)EXP * CDIM * HDIM];
__device__ __half   g_w_down[(size_t)EXP * HDIM * CDIM];
__device__ __half   g_w_shg[(size_t)CDIM * HSHARED];
__device__ __half   g_w_shu[(size_t)CDIM * HSHARED];
__device__ __half   g_w_shd[(size_t)HSHARED * CDIM];

// ---------------- helpers ----------------
__device__ __forceinline__ void mma_f16(float* c, const uint32_t* a, const uint32_t* b) {
    asm volatile(
        "mma.sync.aligned.m16n8k16.row.col.f32.f16.f16.f32 "
        "{%0,%1,%2,%3}, {%4,%5,%6,%7}, {%8,%9}, {%0,%1,%2,%3};"
        : "+f"(c[0]), "+f"(c[1]), "+f"(c[2]), "+f"(c[3])
        : "r"(a[0]), "r"(a[1]), "r"(a[2]), "r"(a[3]), "r"(b[0]), "r"(b[1]));
}
__device__ __forceinline__ void ldmatrix_x4(uint32_t* r, uint32_t addr) {
    asm volatile("ldmatrix.sync.aligned.m8n8.x4.shared.b16 {%0,%1,%2,%3}, [%4];"
                 : "=r"(r[0]), "=r"(r[1]), "=r"(r[2]), "=r"(r[3]) : "r"(addr));
}
__device__ __forceinline__ void ldmatrix_x4_trans(uint32_t* r, uint32_t addr) {
    asm volatile("ldmatrix.sync.aligned.m8n8.x4.trans.shared.b16 {%0,%1,%2,%3}, [%4];"
                 : "=r"(r[0]), "=r"(r[1]), "=r"(r[2]), "=r"(r[3]) : "r"(addr));
}
__device__ __forceinline__ void cp_async16(uint32_t dst, const void* src, int srcbytes) {
    asm volatile("cp.async.cg.shared.global [%0], [%1], 16, %2;"
                 :: "r"(dst), "l"(src), "r"(srcbytes));
}

// ---------------- prep: f32 -> f16 convert copy ----------------
__global__ void half_copy(const float4* __restrict__ src, __half2* __restrict__ dst,
                          long long n4) {
    long long i = (long long)blockIdx.x * blockDim.x + threadIdx.x;
    if (i >= n4) return;
    float4 v = src[i];
    dst[i * 2 + 0] = __floats2half2_rn(v.x, v.y);
    dst[i * 2 + 1] = __floats2half2_rn(v.z, v.w);
}

// ---------------- routing ----------------
__global__ void zero_counts_kernel() {
    if (threadIdx.x < EXP) g_counts[threadIdx.x] = 0;
}

// scores[t][e] = sigmoid(x[t] . rw[e]) — blocked: 16 tokens x 16 experts per CTA.
// Each warp keeps 2 experts' weight chunks in registers, reused across 16 tokens.
#define SCORE_TOK 16
#define XS_STRIDE 1028
__global__ void __launch_bounds__(256) score_kernel(
    const float* __restrict__ x, const float* __restrict__ rw,
    float* __restrict__ scores) {
    extern __shared__ float xs[];   // [SCORE_TOK][XS_STRIDE]
    int t0 = blockIdx.y * SCORE_TOK;
    int tid = threadIdx.x, lane = tid & 31, wid = tid >> 5;

    for (int idx = tid; idx < SCORE_TOK * 256; idx += 256) {
        int t = idx >> 8, j = idx & 255;
        *(float4*)&xs[t * XS_STRIDE + j * 4] =
            *(const float4*)(x + (size_t)(t0 + t) * CDIM + j * 4);
    }
    __syncthreads();

    int e0 = blockIdx.x * 16 + wid * 2;
    const float* w0 = rw + (size_t)e0 * CDIM;
    const float* w1 = rw + (size_t)(e0 + 1) * CDIM;
    float acc0[SCORE_TOK], acc1[SCORE_TOK];
    #pragma unroll
    for (int t = 0; t < SCORE_TOK; t++) { acc0[t] = 0.f; acc1[t] = 0.f; }

    #pragma unroll
    for (int i = 0; i < 8; i++) {
        int c = lane * 4 + i * 128;
        float4 a = *(const float4*)(w0 + c);
        float4 b = *(const float4*)(w1 + c);
        #pragma unroll
        for (int t = 0; t < SCORE_TOK; t++) {
            float4 xv = *(const float4*)&xs[t * XS_STRIDE + c];
            acc0[t] += a.x * xv.x + a.y * xv.y + a.z * xv.z + a.w * xv.w;
            acc1[t] += b.x * xv.x + b.y * xv.y + b.z * xv.z + b.w * xv.w;
        }
    }
    #pragma unroll
    for (int t = 0; t < SCORE_TOK; t++) {
        float s0 = acc0[t], s1 = acc1[t];
        #pragma unroll
        for (int o = 16; o > 0; o >>= 1) {
            s0 += __shfl_xor_sync(0xffffffffu, s0, o);
            s1 += __shfl_xor_sync(0xffffffffu, s1, o);
        }
        if (lane == 0) {
            scores[(size_t)(t0 + t) * EXP + e0]     = 1.f / (1.f + expf(-s0));
            scores[(size_t)(t0 + t) * EXP + e0 + 1] = 1.f / (1.f + expf(-s1));
        }
    }
}

// one thread per token: grouped top-k selection (same algorithm as verified router)
__global__ void __launch_bounds__(256) select_kernel(
    const float* __restrict__ scores, const float* __restrict__ ebias) {
    __shared__ int cnt[EXP];
    if (threadIdx.x < EXP) cnt[threadIdx.x] = 0;
    __syncthreads();

    int t = blockIdx.x * blockDim.x + threadIdx.x;
    {
        float sc[EXP], sb[EXP];
        for (int e = 0; e < EXP; e++) {
            sc[e] = scores[(size_t)t * EXP + e];
            sb[e] = sc[e] + ebias[e];
        }
        float grp[NGRP];
        for (int g = 0; g < NGRP; g++) {
            float m1 = -1e30f, m2 = -1e30f;
            for (int j = 0; j < EPG; j++) {
                float v = sb[g * EPG + j];
                if (v > m1) { m2 = m1; m1 = v; }
                else if (v > m2) m2 = v;
            }
            grp[g] = m1 + m2;
        }
        bool gsel[NGRP] = {};
        for (int it = 0; it < TGRP; it++) {
            float best = -1e30f; int bi = 0;
            for (int g = 0; g < NGRP; g++)
                if (!gsel[g] && grp[g] > best) { best = grp[g]; bi = g; }
            gsel[bi] = true;
        }
        bool eused[EXP] = {};
        int idx[TOPK]; float wv[TOPK]; float wsum = 0.f;
        for (int it = 0; it < TOPK; it++) {
            float best = -1e30f; int bi = 0;
            for (int e = 0; e < EXP; e++)
                if (gsel[e / EPG] && !eused[e] && sb[e] > best) { best = sb[e]; bi = e; }
            eused[bi] = true; idx[it] = bi;
            wv[it] = sc[bi]; wsum += sc[bi];
        }
        float inv = 1.f / (wsum + 1e-20f);
        for (int it = 0; it < TOPK; it++) {
            g_topk_idx[t * TOPK + it] = idx[it];
            g_topk_w[t * TOPK + it]   = wv[it] * inv;
            atomicAdd(&cnt[idx[it]], 1);
        }
    }
    __syncthreads();
    if (threadIdx.x < EXP && cnt[threadIdx.x] > 0)
        atomicAdd(&g_counts[threadIdx.x], cnt[threadIdx.x]);
}

// 64-thread prefix + tile build
__global__ void setup_kernel() {
    __shared__ int s[EXP];
    __shared__ int s2[EXP];
    int t = threadIdx.x;
    int c = g_counts[t];
    int nt_e = (c + 127) >> 7;
    s[t] = c; s2[t] = nt_e;
    __syncthreads();
    for (int off = 1; off < EXP; off <<= 1) {
        int v = (t >= off) ? s[t - off] : 0;
        int v2 = (t >= off) ? s2[t - off] : 0;
        __syncthreads();
        s[t] += v; s2[t] += v2;
        __syncthreads();
    }
    int off_e = s[t] - c;
    int toff_e = s2[t] - nt_e;
    g_offsets[t] = off_e;
    g_cursor[t]  = off_e;
    if (t == EXP - 1) { g_offsets[EXP] = s[t]; g_ntiles = s2[t]; }
    for (int r = 0, k = 0; r < c; r += 128, k++) {
        g_tiles[toff_e + k].e = t;
        g_tiles[toff_e + k].row_start = off_e + r;
        g_tiles[toff_e + k].rows = min(128, c - r);
    }
}

__global__ void assign_kernel() {
    int d = blockIdx.x * blockDim.x + threadIdx.x;
    if (d >= NROWS) return;
    int e = g_topk_idx[d];
    int pos = atomicAdd(&g_cursor[e], 1);
    g_rowmap[pos] = d;
}

// ---------------- GEMM tiling constants ----------------
#define GEMM_THREADS 128
#define STAGES 4
#define A_STRIDE_H 40
#define B_STRIDE_H 136
#define A_SZ_H (128 * A_STRIDE_H)           // 5120 halfs
#define B_SZ_H (32 * B_STRIDE_H)            // 4352 halfs
#define PIPE_H (STAGES * (A_SZ_H + B_SZ_H)) // 37888 halfs = 75776 B
#define GEMM_SMEM_BYTES (PIPE_H * 2 + 512)  // + tokmap

// ================= fused gate|up GEMM + in-register SwiGLU =================
// CTA covers 64 h-cols; B tile cols: [g h0..31 | u h0..31 | g h32..63 | u h32..63].
// acc[mi][ni] (ni<4) = gate, acc[mi][ni+4] = up of the same h column.
template <bool GROUPED, bool INDIRECT>
__global__ void __launch_bounds__(GEMM_THREADS, 2) gu_gemm(
    const __half* __restrict__ A, const __half* __restrict__ Bg,
    const __half* __restrict__ Bu, __half* __restrict__ Hout,
    int Kd, int Nh, long long strideB) {
    extern __shared__ __half smem_h[];
    int* tokmap = (int*)(smem_h + PIPE_H);

    int row_start, rows, e;
    if (GROUPED) {
        if ((int)blockIdx.y >= g_ntiles) return;
        TileDesc td = g_tiles[blockIdx.y];
        e = td.e; row_start = td.row_start; rows = td.rows;
    } else {
        e = 0; row_start = blockIdx.y * 128; rows = 128;
    }
    int h0 = blockIdx.x * 64;
    const __half* Bgp = Bg + (long long)e * strideB + h0;
    const __half* Bup = Bu + (long long)e * strideB + h0;
    const __half* Aptr = A + (long long)row_start * Kd;

    int tid = threadIdx.x;
    int lane = tid & 31, wid = tid >> 5;
    int g = lane >> 2, tig = lane & 3;
    int wmb = (wid >> 1) * 64;
    int wnb = (wid & 1) * 64;

    if (INDIRECT) {
        tokmap[tid] = (tid < rows) ? (g_rowmap[row_start + tid] / TOPK) : -1;
        __syncthreads();
    }

    uint32_t sb = (uint32_t)__cvta_generic_to_shared(smem_h);

    float acc[4][8][4];
    #pragma unroll
    for (int mi = 0; mi < 4; mi++)
        #pragma unroll
        for (int ni = 0; ni < 8; ni++)
            #pragma unroll
            for (int q = 0; q < 4; q++) acc[mi][ni][q] = 0.f;

    const int T = Kd >> 5;

    auto issue = [&](int stage, int it) {
        int kk = it * 32;
        uint32_t abase = sb + (uint32_t)(stage * A_SZ_H) * 2u;
        uint32_t bbase = sb + (uint32_t)(STAGES * A_SZ_H + stage * B_SZ_H) * 2u;
        #pragma unroll
        for (int i = 0; i < 4; i++) {
            int c = tid + i * 128;
            int r = c >> 2, j = c & 3;
            const __half* src;
            int vb = 16;
            if (INDIRECT) {
                int tok = tokmap[r];
                if (tok < 0) { vb = 0; src = A; }
                else src = A + (long long)tok * Kd + kk + j * 8;
            } else {
                src = Aptr + (long long)r * Kd + kk + j * 8;
                if (GROUPED && r >= rows) { vb = 0; src = Aptr; }
            }
            cp_async16(abase + (uint32_t)(r * A_STRIDE_H + j * 8) * 2u, src, vb);
        }
        #pragma unroll
        for (int i = 0; i < 4; i++) {
            int c = tid + i * 128;
            int r = c >> 4, j = c & 15;
            int seg = j >> 2, inner = (j & 3) * 8;
            const __half* base = (seg & 1) ? Bup : Bgp;
            const __half* src = base + (long long)(kk + r) * Nh + (seg >> 1) * 32 + inner;
            cp_async16(bbase + (uint32_t)(r * B_STRIDE_H + j * 8) * 2u, src, 16);
        }
        asm volatile("cp.async.commit_group;" ::: "memory");
    };

    issue(0, 0);
    issue(1, 1);
    issue(2, 2);

    int lhalf = lane & 15, lsel8 = (lane >> 4) << 3;
    for (int it = 0; it < T; it++) {
        int stage = it & 3;
        asm volatile("cp.async.wait_group 2;" ::: "memory");
        __syncthreads();
        if (it + 3 < T) issue((it + 3) & 3, it + 3);

        uint32_t abase = sb + (uint32_t)(stage * A_SZ_H) * 2u;
        uint32_t bbase = sb + (uint32_t)(STAGES * A_SZ_H + stage * B_SZ_H) * 2u;

        #pragma unroll
        for (int ks = 0; ks < 2; ks++) {
            int k0 = ks * 16;
            uint32_t af[4][4], bf[4][4];
            #pragma unroll
            for (int mi = 0; mi < 4; mi++)
                ldmatrix_x4(af[mi], abase +
                    (uint32_t)((wmb + mi * 16 + lhalf) * A_STRIDE_H + k0 + lsel8) * 2u);
            #pragma unroll
            for (int nc = 0; nc < 4; nc++)
                ldmatrix_x4_trans(bf[nc], bbase +
                    (uint32_t)((k0 + lhalf) * B_STRIDE_H + wnb + nc * 16 + lsel8) * 2u);
            #pragma unroll
            for (int mi = 0; mi < 4; mi++)
                #pragma unroll
                for (int nc = 0; nc < 4; nc++) {
                    mma_f16(acc[mi][2 * nc + 0], af[mi], &bf[nc][0]);
                    mma_f16(acc[mi][2 * nc + 1], af[mi], &bf[nc][2]);
                }
        }
    }

    // ---- in-register SwiGLU epilogue ----
    int hbase = h0 + (wnb >> 1);
    #pragma unroll
    for (int mi = 0; mi < 4; mi++) {
        #pragma unroll
        for (int h = 0; h < 2; h++) {
            int rl = wmb + mi * 16 + g + 8 * h;
            if (GROUPED && rl >= rows) continue;
            __half* dst = Hout + (size_t)(row_start + rl) * Nh + hbase;
            #pragma unroll
            for (int ni = 0; ni < 4; ni++) {
                float g0 = acc[mi][ni][2 * h + 0];
                float g1 = acc[mi][ni][2 * h + 1];
                float u0 = acc[mi][ni + 4][2 * h + 0];
                float u1 = acc[mi][ni + 4][2 * h + 1];
                float r0 = g0 / (1.f + expf(-g0)) * u0;
                float r1 = g1 / (1.f + expf(-g1)) * u1;
                *(__half2*)(dst + ni * 8 + 2 * tig) = __floats2half2_rn(r0, r1);
            }
        }
    }
}

// ================= plain fp16 GEMM (down projections) =================
template <bool GROUPED, int MODE>
__global__ void __launch_bounds__(GEMM_THREADS, 2) mma_gemm(
    const __half* __restrict__ A, const __half* __restrict__ B0,
    float* __restrict__ CoutF,
    int Kd, int N, long long strideB,
    const int* __restrict__ rowmap, const float* __restrict__ rowscale) {
    extern __shared__ __half smem_h[];

    int row_start, rows, e;
    if (GROUPED) {
        if ((int)blockIdx.y >= g_ntiles) return;
        TileDesc td = g_tiles[blockIdx.y];
        e = td.e; row_start = td.row_start; rows = td.rows;
    } else {
        e = 0; row_start = blockIdx.y * 128; rows = 128;
    }
    int n0 = blockIdx.x * 128;
    const __half* Bptr = B0 + (long long)e * strideB + n0;
    const __half* Aptr = A + (long long)row_start * Kd;

    int tid = threadIdx.x;
    int lane = tid & 31, wid = tid >> 5;
    int g = lane >> 2, tig = lane & 3;
    int wmb = (wid >> 1) * 64;
    int wnb = (wid & 1) * 64;

    uint32_t sb = (uint32_t)__cvta_generic_to_shared(smem_h);

    float acc[4][8][4];
    #pragma unroll
    for (int mi = 0; mi < 4; mi++)
        #pragma unroll
        for (int ni = 0; ni < 8; ni++)
            #pragma unroll
            for (int q = 0; q < 4; q++) acc[mi][ni][q] = 0.f;

    const int T = Kd >> 5;

    auto issue = [&](int stage, int it) {
        int kk = it * 32;
        uint32_t abase = sb + (uint32_t)(stage * A_SZ_H) * 2u;
        uint32_t bbase = sb + (uint32_t)(STAGES * A_SZ_H + stage * B_SZ_H) * 2u;
        #pragma unroll
        for (int i = 0; i < 4; i++) {
            int c = tid + i * 128;
            int r = c >> 2, j = c & 3;
            const __half* src = Aptr + (long long)r * Kd + kk + j * 8;
            int vb = 16;
            if (GROUPED && r >= rows) { vb = 0; src = Aptr; }
            cp_async16(abase + (uint32_t)(r * A_STRIDE_H + j * 8) * 2u, src, vb);
        }
        #pragma unroll
        for (int i = 0; i < 4; i++) {
            int c = tid + i * 128;
            int r = c >> 4, j = c & 15;
            cp_async16(bbase + (uint32_t)(r * B_STRIDE_H + j * 8) * 2u,
                       Bptr + (long long)(kk + r) * N + j * 8, 16);
        }
        asm volatile("cp.async.commit_group;" ::: "memory");
    };

    issue(0, 0);
    issue(1, 1);
    issue(2, 2);

    int lhalf = lane & 15, lsel8 = (lane >> 4) << 3;
    for (int it = 0; it < T; it++) {
        int stage = it & 3;
        asm volatile("cp.async.wait_group 2;" ::: "memory");
        __syncthreads();
        if (it + 3 < T) issue((it + 3) & 3, it + 3);

        uint32_t abase = sb + (uint32_t)(stage * A_SZ_H) * 2u;
        uint32_t bbase = sb + (uint32_t)(STAGES * A_SZ_H + stage * B_SZ_H) * 2u;

        #pragma unroll
        for (int ks = 0; ks < 2; ks++) {
            int k0 = ks * 16;
            uint32_t af[4][4], bf[4][4];
            #pragma unroll
            for (int mi = 0; mi < 4; mi++)
                ldmatrix_x4(af[mi], abase +
                    (uint32_t)((wmb + mi * 16 + lhalf) * A_STRIDE_H + k0 + lsel8) * 2u);
            #pragma unroll
            for (int nc = 0; nc < 4; nc++)
                ldmatrix_x4_trans(bf[nc], bbase +
                    (uint32_t)((k0 + lhalf) * B_STRIDE_H + wnb + nc * 16 + lsel8) * 2u);
            #pragma unroll
            for (int mi = 0; mi < 4; mi++)
                #pragma unroll
                for (int nc = 0; nc < 4; nc++) {
                    mma_f16(acc[mi][2 * nc + 0], af[mi], &bf[nc][0]);
                    mma_f16(acc[mi][2 * nc + 1], af[mi], &bf[nc][2]);
                }
        }
    }

    #pragma unroll
    for (int mi = 0; mi < 4; mi++) {
        #pragma unroll
        for (int h = 0; h < 2; h++) {
            int rl = wmb + mi * 16 + g + 8 * h;
            if (GROUPED && rl >= rows) continue;
            if (MODE == 2) {
                int d = rowmap[row_start + rl];
                float scale = rowscale[d];
                float* dst = CoutF + (size_t)(d / TOPK) * N;
                #pragma unroll
                for (int ni = 0; ni < 8; ni++) {
                    int col = n0 + wnb + ni * 8 + 2 * tig;
                    atomicAdd(dst + col,     acc[mi][ni][2 * h + 0] * scale);
                    atomicAdd(dst + col + 1, acc[mi][ni][2 * h + 1] * scale);
                }
            } else {
                float* dst = CoutF + (size_t)(row_start + rl) * N;
                #pragma unroll
                for (int ni = 0; ni < 8; ni++) {
                    int col = n0 + wnb + ni * 8 + 2 * tig;
                    float2 v;
                    v.x = acc[mi][ni][2 * h + 0];
                    v.y = acc[mi][ni][2 * h + 1];
                    *(float2*)(dst + col) = v;
                }
            }
        }
    }
}

// ---------------- launch ----------------
extern "C" void kernel_launch(void* const* d_in, const int* in_sizes, int n_in,
                              void* d_out, int out_size) {
    const float* x        = (const float*)d_in[0];
    const float* router_w = (const float*)d_in[1];
    const float* e_bias   = (const float*)d_in[2];
    const float* gate_w   = (const float*)d_in[3];
    const float* up_w     = (const float*)d_in[4];
    const float* down_w   = (const float*)d_in[5];
    const float* sh_gate  = (const float*)d_in[6];
    const float* sh_up    = (const float*)d_in[7];
    const float* sh_down  = (const float*)d_in[8];
    float* out = (float*)d_out;

    __half *p_hbuf, *p_sh_h, *p_x_r;
    __half *p_w_gate, *p_w_up, *p_w_down, *p_w_shg, *p_w_shu, *p_w_shd;
    float *p_topk_w, *p_scores;
    int* p_rowmap;
    cudaGetSymbolAddress((void**)&p_hbuf,     g_hbuf);
    cudaGetSymbolAddress((void**)&p_sh_h,     g_sh_h);
    cudaGetSymbolAddress((void**)&p_topk_w,   g_topk_w);
    cudaGetSymbolAddress((void**)&p_rowmap,   g_rowmap);
    cudaGetSymbolAddress((void**)&p_x_r,      g_x_r);
    cudaGetSymbolAddress((void**)&p_scores,   g_scores);
    cudaGetSymbolAddress((void**)&p_w_gate,   g_w_gate);
    cudaGetSymbolAddress((void**)&p_w_up,     g_w_up);
    cudaGetSymbolAddress((void**)&p_w_down,   g_w_down);
    cudaGetSymbolAddress((void**)&p_w_shg,    g_w_shg);
    cudaGetSymbolAddress((void**)&p_w_shu,    g_w_shu);
    cudaGetSymbolAddress((void**)&p_w_shd,    g_w_shd);

    cudaFuncSetAttribute((const void*)gu_gemm<false, false>,
                         cudaFuncAttributeMaxDynamicSharedMemorySize, GEMM_SMEM_BYTES);
    cudaFuncSetAttribute((const void*)gu_gemm<true, true>,
                         cudaFuncAttributeMaxDynamicSharedMemorySize, GEMM_SMEM_BYTES);
    cudaFuncSetAttribute((const void*)mma_gemm<false, 0>,
                         cudaFuncAttributeMaxDynamicSharedMemorySize, GEMM_SMEM_BYTES);
    cudaFuncSetAttribute((const void*)mma_gemm<true, 2>,
                         cudaFuncAttributeMaxDynamicSharedMemorySize, GEMM_SMEM_BYTES);
    int score_smem = SCORE_TOK * XS_STRIDE * 4;
    cudaFuncSetAttribute((const void*)score_kernel,
                         cudaFuncAttributeMaxDynamicSharedMemorySize, score_smem);

    long long n4;

    // launches 0-3: weight/x conversions
    n4 = (long long)CDIM * HSHARED / 4;
    half_copy<<<(unsigned)((n4 + 255) / 256), 256>>>((const float4*)sh_gate, (__half2*)p_w_shg, n4);
    half_copy<<<(unsigned)((n4 + 255) / 256), 256>>>((const float4*)sh_up,   (__half2*)p_w_shu, n4);
    n4 = (long long)S_TOK * CDIM / 4;
    half_copy<<<(unsigned)((n4 + 255) / 256), 256>>>((const float4*)x, (__half2*)p_x_r, n4);
    n4 = (long long)CDIM * HSHARED / 4;
    half_copy<<<(unsigned)((n4 + 255) / 256), 256>>>((const float4*)sh_down, (__half2*)p_w_shd, n4);

    // launch 4: zero counts
    zero_counts_kernel<<<1, 64>>>();

    // launch 5: score GEMM (profiled)
    score_kernel<<<dim3(EXP / 16, S_TOK / SCORE_TOK), 256, score_smem>>>(
        x, router_w, p_scores);

    // launch 6: selection
    select_kernel<<<S_TOK / 256, 256>>>(p_scores, e_bias);

    // launch 7: shared gu GEMM + fused swiglu
    gu_gemm<false, false><<<dim3(HSHARED / 64, S_TOK / 128), GEMM_THREADS, GEMM_SMEM_BYTES>>>(
        p_x_r, p_w_shg, p_w_shu, p_sh_h, CDIM, HSHARED, 0);

    // launch 8: shared down GEMM -> out (fp32, full coverage)
    mma_gemm<false, 0><<<dim3(CDIM / 128, S_TOK / 128), GEMM_THREADS, GEMM_SMEM_BYTES>>>(
        p_sh_h, p_w_shd, out, HSHARED, CDIM, 0, nullptr, nullptr);

    // expert weight conversion + routing part 2
    n4 = (long long)EXP * CDIM * HDIM / 4;
    half_copy<<<(unsigned)((n4 + 255) / 256), 256>>>((const float4*)gate_w, (__half2*)p_w_gate, n4);
    half_copy<<<(unsigned)((n4 + 255) / 256), 256>>>((const float4*)up_w,   (__half2*)p_w_up,   n4);
    half_copy<<<(unsigned)((n4 + 255) / 256), 256>>>((const float4*)down_w, (__half2*)p_w_down, n4);
    setup_kernel<<<1, 64>>>();
    assign_kernel<<<NROWS / 256, 256>>>();

    // routed gu GEMM + fused swiglu (grouped, indirect A from x_r)
    gu_gemm<true, true><<<dim3(HDIM / 64, MAX_TILES), GEMM_THREADS, GEMM_SMEM_BYTES>>>(
        p_x_r, p_w_gate, p_w_up, p_hbuf, CDIM, HDIM, (long long)CDIM * HDIM);

    // routed down: atomicAdd scaled rows into out
    mma_gemm<true, 2><<<dim3(CDIM / 128, MAX_TILES), GEMM_THREADS, GEMM_SMEM_BYTES>>>(
        p_hbuf, p_w_down, out, HDIM, CDIM, (long long)HDIM * CDIM,
        p_rowmap, p_topk_w);
}

// round 12
// speedup vs baseline: 1.3911x; 1.0226x over previous
#include <cuda_runtime.h>
#include <cuda_fp16.h>
#include <math.h>
#include <stdint.h>

// ---------------- problem constants ----------------
#define S_TOK   4096
#define CDIM    1024
#define EXP     64
#define TOPK    8
#define NGRP    8
#define EPG     8
#define TGRP    4
#define HDIM    512
#define HSHARED 2048
#define NROWS   (S_TOK * TOPK)   // 32768
#define MAX_TILES 320
#define SEL_BLK 128
#define SEL_NBLK (S_TOK / SEL_BLK)   // 32

// ---------------- scratch (static device globals) ----------------
struct TileDesc { int e; int row_start; int rows; };

__device__ int      g_cnt_part[SEL_NBLK * EXP];
__device__ int      g_cursor[EXP];
__device__ TileDesc g_tiles[MAX_TILES];
__device__ int      g_ntiles;
__device__ int      g_rowmap[NROWS];
__device__ int      g_topk_idx[NROWS];
__device__ float    g_topk_w[NROWS];
__device__ float    g_scores[(size_t)S_TOK * EXP];

__device__ __half   g_hbuf[(size_t)NROWS * HDIM];       // routed h (post-swiglu)
__device__ __half   g_sh_h[(size_t)S_TOK * HSHARED];    // shared h (post-swiglu)
__device__ __half   g_x_r[(size_t)S_TOK * CDIM];

// fp16 weight copies (native [K][N] layouts preserved)
__device__ __half   g_w_gate[(size_t)EXP * CDIM * HDIM];
__device__ __half   g_w_up[(size_t)EXP * CDIM * HDIM];
__device__ __half   g_w_down[(size_t)EXP * HDIM * CDIM];
__device__ __half   g_w_shg[(size_t)CDIM * HSHARED];
__device__ __half   g_w_shu[(size_t)CDIM * HSHARED];
__device__ __half   g_w_shd[(size_t)HSHARED * CDIM];

// ---------------- helpers ----------------
__device__ __forceinline__ void mma_f16(float* c, const uint32_t* a, const uint32_t* b) {
    asm volatile(
        "mma.sync.aligned.m16n8k16.row.col.f32.f16.f16.f32 "
        "{%0,%1,%2,%3}, {%4,%5,%6,%7}, {%8,%9}, {%0,%1,%2,%3};"
        : "+f"(c[0]), "+f"(c[1]), "+f"(c[2]), "+f"(c[3])
        : "r"(a[0]), "r"(a[1]), "r"(a[2]), "r"(a[3]), "r"(b[0]), "r"(b[1]));
}
__device__ __forceinline__ void ldmatrix_x4(uint32_t* r, uint32_t addr) {
    asm volatile("ldmatrix.sync.aligned.m8n8.x4.shared.b16 {%0,%1,%2,%3}, [%4];"
                 : "=r"(r[0]), "=r"(r[1]), "=r"(r[2]), "=r"(r[3]) : "r"(addr));
}
__device__ __forceinline__ void ldmatrix_x4_trans(uint32_t* r, uint32_t addr) {
    asm volatile("ldmatrix.sync.aligned.m8n8.x4.trans.shared.b16 {%0,%1,%2,%3}, [%4];"
                 : "=r"(r[0]), "=r"(r[1]), "=r"(r[2]), "=r"(r[3]) : "r"(addr));
}
__device__ __forceinline__ void cp_async16(uint32_t dst, const void* src, int srcbytes) {
    asm volatile("cp.async.cg.shared.global [%0], [%1], 16, %2;"
                 :: "r"(dst), "l"(src), "r"(srcbytes));
}

// ---------------- prep: f32 -> f16 convert copies ----------------
__global__ void half_copy(const float4* __restrict__ src, __half2* __restrict__ dst,
                          long long n4) {
    long long i = (long long)blockIdx.x * blockDim.x + threadIdx.x;
    if (i >= n4) return;
    float4 v = src[i];
    dst[i * 2 + 0] = __floats2half2_rn(v.x, v.y);
    dst[i * 2 + 1] = __floats2half2_rn(v.z, v.w);
}

// merged convert of the 3 expert weight tensors (each exactly 2^23 float4s)
#define EW_N4_SHIFT 23
__global__ void half_copy3(const float4* __restrict__ s0, const float4* __restrict__ s1,
                           const float4* __restrict__ s2,
                           __half2* __restrict__ d0, __half2* __restrict__ d1,
                           __half2* __restrict__ d2) {
    long long i = (long long)blockIdx.x * blockDim.x + threadIdx.x;
    int sel = (int)(i >> EW_N4_SHIFT);
    long long idx = i & ((1LL << EW_N4_SHIFT) - 1);
    const float4* s = (sel == 0) ? s0 : (sel == 1) ? s1 : s2;
    __half2* d = (sel == 0) ? d0 : (sel == 1) ? d1 : d2;
    float4 v = s[idx];
    d[idx * 2 + 0] = __floats2half2_rn(v.x, v.y);
    d[idx * 2 + 1] = __floats2half2_rn(v.z, v.w);
}

// ---------------- routing ----------------
// scores[t][e] = sigmoid(x[t] . rw[e]) — blocked: 16 tokens x 16 experts per CTA.
#define SCORE_TOK 16
#define XS_STRIDE 1028
__global__ void __launch_bounds__(256) score_kernel(
    const float* __restrict__ x, const float* __restrict__ rw,
    float* __restrict__ scores) {
    extern __shared__ float xs[];   // [SCORE_TOK][XS_STRIDE]
    int t0 = blockIdx.y * SCORE_TOK;
    int tid = threadIdx.x, lane = tid & 31, wid = tid >> 5;

    for (int idx = tid; idx < SCORE_TOK * 256; idx += 256) {
        int t = idx >> 8, j = idx & 255;
        *(float4*)&xs[t * XS_STRIDE + j * 4] =
            *(const float4*)(x + (size_t)(t0 + t) * CDIM + j * 4);
    }
    __syncthreads();

    int e0 = blockIdx.x * 16 + wid * 2;
    const float* w0 = rw + (size_t)e0 * CDIM;
    const float* w1 = rw + (size_t)(e0 + 1) * CDIM;
    float acc0[SCORE_TOK], acc1[SCORE_TOK];
    #pragma unroll
    for (int t = 0; t < SCORE_TOK; t++) { acc0[t] = 0.f; acc1[t] = 0.f; }

    #pragma unroll
    for (int i = 0; i < 8; i++) {
        int c = lane * 4 + i * 128;
        float4 a = *(const float4*)(w0 + c);
        float4 b = *(const float4*)(w1 + c);
        #pragma unroll
        for (int t = 0; t < SCORE_TOK; t++) {
            float4 xv = *(const float4*)&xs[t * XS_STRIDE + c];
            acc0[t] += a.x * xv.x + a.y * xv.y + a.z * xv.z + a.w * xv.w;
            acc1[t] += b.x * xv.x + b.y * xv.y + b.z * xv.z + b.w * xv.w;
        }
    }
    #pragma unroll
    for (int t = 0; t < SCORE_TOK; t++) {
        float s0 = acc0[t], s1 = acc1[t];
        #pragma unroll
        for (int o = 16; o > 0; o >>= 1) {
            s0 += __shfl_xor_sync(0xffffffffu, s0, o);
            s1 += __shfl_xor_sync(0xffffffffu, s1, o);
        }
        if (lane == 0) {
            scores[(size_t)(t0 + t) * EXP + e0]     = 1.f / (1.f + expf(-s0));
            scores[(size_t)(t0 + t) * EXP + e0 + 1] = 1.f / (1.f + expf(-s1));
        }
    }
}

// one thread per token; sb in smem (stride 65, conflict-free); per-block counts
// to g_cnt_part (no global atomics, no pre-zero kernel).
__global__ void __launch_bounds__(SEL_BLK) select_kernel(
    const float* __restrict__ scores, const float* __restrict__ ebias) {
    __shared__ float sbs[SEL_BLK * 65];
    __shared__ float eb[EXP];
    __shared__ int cnt[EXP];
    int tid = threadIdx.x;
    if (tid < EXP) { cnt[tid] = 0; eb[tid] = ebias[tid]; }
    __syncthreads();

    int t = blockIdx.x * SEL_BLK + tid;
    float* sb = &sbs[tid * 65];
    const float* srow = scores + (size_t)t * EXP;
    for (int e = 0; e < EXP; e++) sb[e] = srow[e] + eb[e];

    float grp[NGRP];
    for (int g = 0; g < NGRP; g++) {
        float m1 = -1e30f, m2 = -1e30f;
        for (int j = 0; j < EPG; j++) {
            float v = sb[g * EPG + j];
            if (v > m1) { m2 = m1; m1 = v; }
            else if (v > m2) m2 = v;
        }
        grp[g] = m1 + m2;
    }
    bool gsel[NGRP] = {};
    for (int it = 0; it < TGRP; it++) {
        float best = -1e30f; int bi = 0;
        for (int g = 0; g < NGRP; g++)
            if (!gsel[g] && grp[g] > best) { best = grp[g]; bi = g; }
        gsel[bi] = true;
    }
    bool eused[EXP] = {};
    int idx[TOPK]; float wv[TOPK]; float wsum = 0.f;
    for (int it = 0; it < TOPK; it++) {
        float best = -1e30f; int bi = 0;
        for (int e = 0; e < EXP; e++)
            if (gsel[e / EPG] && !eused[e] && sb[e] > best) { best = sb[e]; bi = e; }
        eused[bi] = true; idx[it] = bi;
        float s = srow[bi];
        wv[it] = s; wsum += s;
    }
    float inv = 1.f / (wsum + 1e-20f);
    for (int it = 0; it < TOPK; it++) {
        g_topk_idx[t * TOPK + it] = idx[it];
        g_topk_w[t * TOPK + it]   = wv[it] * inv;
        atomicAdd(&cnt[idx[it]], 1);
    }
    __syncthreads();
    if (tid < EXP) g_cnt_part[blockIdx.x * EXP + tid] = cnt[tid];
}

// 64-thread: sum partial counts, prefix, tile build
__global__ void setup_kernel() {
    __shared__ int s[EXP];
    __shared__ int s2[EXP];
    int t = threadIdx.x;
    int c = 0;
    for (int b = 0; b < SEL_NBLK; b++) c += g_cnt_part[b * EXP + t];
    int nt_e = (c + 127) >> 7;
    s[t] = c; s2[t] = nt_e;
    __syncthreads();
    for (int off = 1; off < EXP; off <<= 1) {
        int v = (t >= off) ? s[t - off] : 0;
        int v2 = (t >= off) ? s2[t - off] : 0;
        __syncthreads();
        s[t] += v; s2[t] += v2;
        __syncthreads();
    }
    int off_e = s[t] - c;
    int toff_e = s2[t] - nt_e;
    g_cursor[t] = off_e;
    if (t == EXP - 1) g_ntiles = s2[t];
    for (int r = 0, k = 0; r < c; r += 128, k++) {
        g_tiles[toff_e + k].e = t;
        g_tiles[toff_e + k].row_start = off_e + r;
        g_tiles[toff_e + k].rows = min(128, c - r);
    }
}

__global__ void assign_kernel() {
    int d = blockIdx.x * blockDim.x + threadIdx.x;
    if (d >= NROWS) return;
    int e = g_topk_idx[d];
    int pos = atomicAdd(&g_cursor[e], 1);
    g_rowmap[pos] = d;
}

// ---------------- GEMM tiling constants ----------------
#define GEMM_THREADS 128
#define STAGES 5
#define A_STRIDE_H 40
#define B_STRIDE_H 136
#define A_SZ_H (128 * A_STRIDE_H)           // 5120 halfs
#define B_SZ_H (32 * B_STRIDE_H)            // 4352 halfs
#define PIPE_H (STAGES * (A_SZ_H + B_SZ_H)) // 47360 halfs = 94720 B
#define GEMM_SMEM_BYTES (PIPE_H * 2 + 512)  // + tokmap

// ================= fused gate|up GEMM + in-register SwiGLU =================
// CTA covers 64 h-cols; B tile cols: [g h0..31 | u h0..31 | g h32..63 | u h32..63].
// acc[mi][ni] (ni<4) = gate, acc[mi][ni+4] = up of the same h column.
template <bool GROUPED, bool INDIRECT>
__global__ void __launch_bounds__(GEMM_THREADS, 2) gu_gemm(
    const __half* __restrict__ A, const __half* __restrict__ Bg,
    const __half* __restrict__ Bu, __half* __restrict__ Hout,
    int Kd, int Nh, long long strideB) {
    extern __shared__ __half smem_h[];
    int* tokmap = (int*)(smem_h + PIPE_H);

    int row_start, rows, e;
    if (GROUPED) {
        if ((int)blockIdx.y >= g_ntiles) return;
        TileDesc td = g_tiles[blockIdx.y];
        e = td.e; row_start = td.row_start; rows = td.rows;
    } else {
        e = 0; row_start = blockIdx.y * 128; rows = 128;
    }
    int h0 = blockIdx.x * 64;
    const __half* Bgp = Bg + (long long)e * strideB + h0;
    const __half* Bup = Bu + (long long)e * strideB + h0;
    const __half* Aptr = A + (long long)row_start * Kd;

    int tid = threadIdx.x;
    int lane = tid & 31, wid = tid >> 5;
    int g = lane >> 2, tig = lane & 3;
    int wmb = (wid >> 1) * 64;
    int wnb = (wid & 1) * 64;

    if (INDIRECT) {
        tokmap[tid] = (tid < rows) ? (g_rowmap[row_start + tid] / TOPK) : -1;
        __syncthreads();
    }

    uint32_t sb = (uint32_t)__cvta_generic_to_shared(smem_h);

    float acc[4][8][4];
    #pragma unroll
    for (int mi = 0; mi < 4; mi++)
        #pragma unroll
        for (int ni = 0; ni < 8; ni++)
            #pragma unroll
            for (int q = 0; q < 4; q++) acc[mi][ni][q] = 0.f;

    const int T = Kd >> 5;

    auto issue = [&](int stage, int it) {
        int kk = it * 32;
        uint32_t abase = sb + (uint32_t)(stage * A_SZ_H) * 2u;
        uint32_t bbase = sb + (uint32_t)(STAGES * A_SZ_H + stage * B_SZ_H) * 2u;
        #pragma unroll
        for (int i = 0; i < 4; i++) {
            int c = tid + i * 128;
            int r = c >> 2, j = c & 3;
            const __half* src;
            int vb = 16;
            if (INDIRECT) {
                int tok = tokmap[r];
                if (tok < 0) { vb = 0; src = A; }
                else src = A + (long long)tok * Kd + kk + j * 8;
            } else {
                src = Aptr + (long long)r * Kd + kk + j * 8;
                if (GROUPED && r >= rows) { vb = 0; src = Aptr; }
            }
            cp_async16(abase + (uint32_t)(r * A_STRIDE_H + j * 8) * 2u, src, vb);
        }
        #pragma unroll
        for (int i = 0; i < 4; i++) {
            int c = tid + i * 128;
            int r = c >> 4, j = c & 15;
            int seg = j >> 2, inner = (j & 3) * 8;
            const __half* base = (seg & 1) ? Bup : Bgp;
            const __half* src = base + (long long)(kk + r) * Nh + (seg >> 1) * 32 + inner;
            cp_async16(bbase + (uint32_t)(r * B_STRIDE_H + j * 8) * 2u, src, 16);
        }
        asm volatile("cp.async.commit_group;" ::: "memory");
    };

    issue(0, 0);
    issue(1, 1);
    issue(2, 2);
    issue(3, 3);

    int lhalf = lane & 15, lsel8 = (lane >> 4) << 3;
    int stage = 0, wstage = 4;
    for (int it = 0; it < T; it++) {
        asm volatile("cp.async.wait_group 3;" ::: "memory");
        __syncthreads();
        if (it + 4 < T) issue(wstage, it + 4);

        uint32_t abase = sb + (uint32_t)(stage * A_SZ_H) * 2u;
        uint32_t bbase = sb + (uint32_t)(STAGES * A_SZ_H + stage * B_SZ_H) * 2u;

        #pragma unroll
        for (int ks = 0; ks < 2; ks++) {
            int k0 = ks * 16;
            uint32_t af[4][4], bf[4][4];
            #pragma unroll
            for (int mi = 0; mi < 4; mi++)
                ldmatrix_x4(af[mi], abase +
                    (uint32_t)((wmb + mi * 16 + lhalf) * A_STRIDE_H + k0 + lsel8) * 2u);
            #pragma unroll
            for (int nc = 0; nc < 4; nc++)
                ldmatrix_x4_trans(bf[nc], bbase +
                    (uint32_t)((k0 + lhalf) * B_STRIDE_H + wnb + nc * 16 + lsel8) * 2u);
            #pragma unroll
            for (int mi = 0; mi < 4; mi++)
                #pragma unroll
                for (int nc = 0; nc < 4; nc++) {
                    mma_f16(acc[mi][2 * nc + 0], af[mi], &bf[nc][0]);
                    mma_f16(acc[mi][2 * nc + 1], af[mi], &bf[nc][2]);
                }
        }
        if (++stage == STAGES) stage = 0;
        if (++wstage == STAGES) wstage = 0;
    }

    // ---- in-register SwiGLU epilogue ----
    int hbase = h0 + (wnb >> 1);
    #pragma unroll
    for (int mi = 0; mi < 4; mi++) {
        #pragma unroll
        for (int h = 0; h < 2; h++) {
            int rl = wmb + mi * 16 + g + 8 * h;
            if (GROUPED && rl >= rows) continue;
            __half* dst = Hout + (size_t)(row_start + rl) * Nh + hbase;
            #pragma unroll
            for (int ni = 0; ni < 4; ni++) {
                float g0 = acc[mi][ni][2 * h + 0];
                float g1 = acc[mi][ni][2 * h + 1];
                float u0 = acc[mi][ni + 4][2 * h + 0];
                float u1 = acc[mi][ni + 4][2 * h + 1];
                float r0 = g0 / (1.f + expf(-g0)) * u0;
                float r1 = g1 / (1.f + expf(-g1)) * u1;
                *(__half2*)(dst + ni * 8 + 2 * tig) = __floats2half2_rn(r0, r1);
            }
        }
    }
}

// ================= plain fp16 GEMM (down projections) =================
// MODE 0: fp32 store. MODE 2: atomicAdd scaled rows into CoutF[rowmap[row]/TOPK].
template <bool GROUPED, int MODE>
__global__ void __launch_bounds__(GEMM_THREADS, 2) mma_gemm(
    const __half* __restrict__ A, const __half* __restrict__ B0,
    float* __restrict__ CoutF,
    int Kd, int N, long long strideB,
    const int* __restrict__ rowmap, const float* __restrict__ rowscale) {
    extern __shared__ __half smem_h[];

    int row_start, rows, e;
    if (GROUPED) {
        if ((int)blockIdx.y >= g_ntiles) return;
        TileDesc td = g_tiles[blockIdx.y];
        e = td.e; row_start = td.row_start; rows = td.rows;
    } else {
        e = 0; row_start = blockIdx.y * 128; rows = 128;
    }
    int n0 = blockIdx.x * 128;
    const __half* Bptr = B0 + (long long)e * strideB + n0;
    const __half* Aptr = A + (long long)row_start * Kd;

    int tid = threadIdx.x;
    int lane = tid & 31, wid = tid >> 5;
    int g = lane >> 2, tig = lane & 3;
    int wmb = (wid >> 1) * 64;
    int wnb = (wid & 1) * 64;

    uint32_t sb = (uint32_t)__cvta_generic_to_shared(smem_h);

    float acc[4][8][4];
    #pragma unroll
    for (int mi = 0; mi < 4; mi++)
        #pragma unroll
        for (int ni = 0; ni < 8; ni++)
            #pragma unroll
            for (int q = 0; q < 4; q++) acc[mi][ni][q] = 0.f;

    const int T = Kd >> 5;

    auto issue = [&](int stage, int it) {
        int kk = it * 32;
        uint32_t abase = sb + (uint32_t)(stage * A_SZ_H) * 2u;
        uint32_t bbase = sb + (uint32_t)(STAGES * A_SZ_H + stage * B_SZ_H) * 2u;
        #pragma unroll
        for (int i = 0; i < 4; i++) {
            int c = tid + i * 128;
            int r = c >> 2, j = c & 3;
            const __half* src = Aptr + (long long)r * Kd + kk + j * 8;
            int vb = 16;
            if (GROUPED && r >= rows) { vb = 0; src = Aptr; }
            cp_async16(abase + (uint32_t)(r * A_STRIDE_H + j * 8) * 2u, src, vb);
        }
        #pragma unroll
        for (int i = 0; i < 4; i++) {
            int c = tid + i * 128;
            int r = c >> 4, j = c & 15;
            cp_async16(bbase + (uint32_t)(r * B_STRIDE_H + j * 8) * 2u,
                       Bptr + (long long)(kk + r) * N + j * 8, 16);
        }
        asm volatile("cp.async.commit_group;" ::: "memory");
    };

    issue(0, 0);
    issue(1, 1);
    issue(2, 2);
    issue(3, 3);

    int lhalf = lane & 15, lsel8 = (lane >> 4) << 3;
    int stage = 0, wstage = 4;
    for (int it = 0; it < T; it++) {
        asm volatile("cp.async.wait_group 3;" ::: "memory");
        __syncthreads();
        if (it + 4 < T) issue(wstage, it + 4);

        uint32_t abase = sb + (uint32_t)(stage * A_SZ_H) * 2u;
        uint32_t bbase = sb + (uint32_t)(STAGES * A_SZ_H + stage * B_SZ_H) * 2u;

        #pragma unroll
        for (int ks = 0; ks < 2; ks++) {
            int k0 = ks * 16;
            uint32_t af[4][4], bf[4][4];
            #pragma unroll
            for (int mi = 0; mi < 4; mi++)
                ldmatrix_x4(af[mi], abase +
                    (uint32_t)((wmb + mi * 16 + lhalf) * A_STRIDE_H + k0 + lsel8) * 2u);
            #pragma unroll
            for (int nc = 0; nc < 4; nc++)
                ldmatrix_x4_trans(bf[nc], bbase +
                    (uint32_t)((k0 + lhalf) * B_STRIDE_H + wnb + nc * 16 + lsel8) * 2u);
            #pragma unroll
            for (int mi = 0; mi < 4; mi++)
                #pragma unroll
                for (int nc = 0; nc < 4; nc++) {
                    mma_f16(acc[mi][2 * nc + 0], af[mi], &bf[nc][0]);
                    mma_f16(acc[mi][2 * nc + 1], af[mi], &bf[nc][2]);
                }
        }
        if (++stage == STAGES) stage = 0;
        if (++wstage == STAGES) wstage = 0;
    }

    #pragma unroll
    for (int mi = 0; mi < 4; mi++) {
        #pragma unroll
        for (int h = 0; h < 2; h++) {
            int rl = wmb + mi * 16 + g + 8 * h;
            if (GROUPED && rl >= rows) continue;
            if (MODE == 2) {
                int d = rowmap[row_start + rl];
                float scale = rowscale[d];
                float* dst = CoutF + (size_t)(d / TOPK) * N;
                #pragma unroll
                for (int ni = 0; ni < 8; ni++) {
                    int col = n0 + wnb + ni * 8 + 2 * tig;
                    atomicAdd(dst + col,     acc[mi][ni][2 * h + 0] * scale);
                    atomicAdd(dst + col + 1, acc[mi][ni][2 * h + 1] * scale);
                }
            } else {
                float* dst = CoutF + (size_t)(row_start + rl) * N;
                #pragma unroll
                for (int ni = 0; ni < 8; ni++) {
                    int col = n0 + wnb + ni * 8 + 2 * tig;
                    float2 v;
                    v.x = acc[mi][ni][2 * h + 0];
                    v.y = acc[mi][ni][2 * h + 1];
                    *(float2*)(dst + col) = v;
                }
            }
        }
    }
}

// ---------------- launch ----------------
extern "C" void kernel_launch(void* const* d_in, const int* in_sizes, int n_in,
                              void* d_out, int out_size) {
    const float* x        = (const float*)d_in[0];
    const float* router_w = (const float*)d_in[1];
    const float* e_bias   = (const float*)d_in[2];
    const float* gate_w   = (const float*)d_in[3];
    const float* up_w     = (const float*)d_in[4];
    const float* down_w   = (const float*)d_in[5];
    const float* sh_gate  = (const float*)d_in[6];
    const float* sh_up    = (const float*)d_in[7];
    const float* sh_down  = (const float*)d_in[8];
    float* out = (float*)d_out;

    __half *p_hbuf, *p_sh_h, *p_x_r;
    __half *p_w_gate, *p_w_up, *p_w_down, *p_w_shg, *p_w_shu, *p_w_shd;
    float *p_topk_w, *p_scores;
    int* p_rowmap;
    cudaGetSymbolAddress((void**)&p_hbuf,     g_hbuf);
    cudaGetSymbolAddress((void**)&p_sh_h,     g_sh_h);
    cudaGetSymbolAddress((void**)&p_topk_w,   g_topk_w);
    cudaGetSymbolAddress((void**)&p_rowmap,   g_rowmap);
    cudaGetSymbolAddress((void**)&p_x_r,      g_x_r);
    cudaGetSymbolAddress((void**)&p_scores,   g_scores);
    cudaGetSymbolAddress((void**)&p_w_gate,   g_w_gate);
    cudaGetSymbolAddress((void**)&p_w_up,     g_w_up);
    cudaGetSymbolAddress((void**)&p_w_down,   g_w_down);
    cudaGetSymbolAddress((void**)&p_w_shg,    g_w_shg);
    cudaGetSymbolAddress((void**)&p_w_shu,    g_w_shu);
    cudaGetSymbolAddress((void**)&p_w_shd,    g_w_shd);

    cudaFuncSetAttribute((const void*)gu_gemm<false, false>,
                         cudaFuncAttributeMaxDynamicSharedMemorySize, GEMM_SMEM_BYTES);
    cudaFuncSetAttribute((const void*)gu_gemm<true, true>,
                         cudaFuncAttributeMaxDynamicSharedMemorySize, GEMM_SMEM_BYTES);
    cudaFuncSetAttribute((const void*)mma_gemm<false, 0>,
                         cudaFuncAttributeMaxDynamicSharedMemorySize, GEMM_SMEM_BYTES);
    cudaFuncSetAttribute((const void*)mma_gemm<true, 2>,
                         cudaFuncAttributeMaxDynamicSharedMemorySize, GEMM_SMEM_BYTES);
    int score_smem = SCORE_TOK * XS_STRIDE * 4;
    cudaFuncSetAttribute((const void*)score_kernel,
                         cudaFuncAttributeMaxDynamicSharedMemorySize, score_smem);

    long long n4;

    // launches 0-3: shared/x conversions
    n4 = (long long)CDIM * HSHARED / 4;
    half_copy<<<(unsigned)((n4 + 255) / 256), 256>>>((const float4*)sh_gate, (__half2*)p_w_shg, n4);
    half_copy<<<(unsigned)((n4 + 255) / 256), 256>>>((const float4*)sh_up,   (__half2*)p_w_shu, n4);
    n4 = (long long)S_TOK * CDIM / 4;
    half_copy<<<(unsigned)((n4 + 255) / 256), 256>>>((const float4*)x, (__half2*)p_x_r, n4);
    n4 = (long long)CDIM * HSHARED / 4;
    half_copy<<<(unsigned)((n4 + 255) / 256), 256>>>((const float4*)sh_down, (__half2*)p_w_shd, n4);

    // launch 4: score GEMM
    score_kernel<<<dim3(EXP / 16, S_TOK / SCORE_TOK), 256, score_smem>>>(
        x, router_w, p_scores);

    // launch 5: selection (profiled)
    select_kernel<<<SEL_NBLK, SEL_BLK>>>(p_scores, e_bias);

    // launch 6: shared gu GEMM + fused swiglu
    gu_gemm<false, false><<<dim3(HSHARED / 64, S_TOK / 128), GEMM_THREADS, GEMM_SMEM_BYTES>>>(
        p_x_r, p_w_shg, p_w_shu, p_sh_h, CDIM, HSHARED, 0);

    // launch 7: shared down GEMM -> out (fp32, full coverage)
    mma_gemm<false, 0><<<dim3(CDIM / 128, S_TOK / 128), GEMM_THREADS, GEMM_SMEM_BYTES>>>(
        p_sh_h, p_w_shd, out, HSHARED, CDIM, 0, nullptr, nullptr);

    // launch 8: merged expert weight conversion (3 tensors x 2^23 float4s)
    {
        long long total = 3LL << EW_N4_SHIFT;
        half_copy3<<<(unsigned)(total / 256), 256>>>(
            (const float4*)gate_w, (const float4*)up_w, (const float4*)down_w,
            (__half2*)p_w_gate, (__half2*)p_w_up, (__half2*)p_w_down);
    }

    // launches 9-10: routing part 2
    setup_kernel<<<1, 64>>>();
    assign_kernel<<<NROWS / 256, 256>>>();

    // routed gu GEMM + fused swiglu (grouped, indirect A from x_r)
    gu_gemm<true, true><<<dim3(HDIM / 64, MAX_TILES), GEMM_THREADS, GEMM_SMEM_BYTES>>>(
        p_x_r, p_w_gate, p_w_up, p_hbuf, CDIM, HDIM, (long long)CDIM * HDIM);

    // routed down: atomicAdd scaled rows into out
    mma_gemm<true, 2><<<dim3(CDIM / 128, MAX_TILES), GEMM_THREADS, GEMM_SMEM_BYTES>>>(
        p_hbuf, p_w_down, out, HDIM, CDIM, (long long)HDIM * CDIM,
        p_rowmap, p_topk_w);
}

// round 13
// speedup vs baseline: 1.4345x; 1.0312x over previous
#include <cuda_runtime.h>
#include <cuda_fp16.h>
#include <math.h>
#include <stdint.h>

// ---------------- problem constants ----------------
#define S_TOK   4096
#define CDIM    1024
#define EXP     64
#define TOPK    8
#define NGRP    8
#define EPG     8
#define TGRP    4
#define HDIM    512
#define HSHARED 2048
#define NROWS   (S_TOK * TOPK)   // 32768
#define MAX_TILES 320
#define SEL_BLK 128
#define SEL_NBLK (S_TOK / SEL_BLK)   // 32

// ---------------- scratch (static device globals) ----------------
struct TileDesc { int e; int row_start; int rows; };

__device__ int      g_cnt_part[SEL_NBLK * EXP];
__device__ int      g_cursor[EXP];
__device__ TileDesc g_tiles[MAX_TILES];
__device__ int      g_ntiles;
__device__ int      g_rowmap[NROWS];
__device__ int      g_topk_idx[NROWS];
__device__ float    g_topk_w[NROWS];
__device__ float    g_scores[(size_t)S_TOK * EXP];

__device__ __half   g_hbuf[(size_t)NROWS * HDIM];       // routed h (post-swiglu)
__device__ __half   g_sh_h[(size_t)S_TOK * HSHARED];    // shared h (post-swiglu)
__device__ __half   g_x_r[(size_t)S_TOK * CDIM];

// fp16 weight copies (native [K][N] layouts preserved)
__device__ __half   g_w_gate[(size_t)EXP * CDIM * HDIM];
__device__ __half   g_w_up[(size_t)EXP * CDIM * HDIM];
__device__ __half   g_w_down[(size_t)EXP * HDIM * CDIM];
__device__ __half   g_w_shg[(size_t)CDIM * HSHARED];
__device__ __half   g_w_shu[(size_t)CDIM * HSHARED];
__device__ __half   g_w_shd[(size_t)HSHARED * CDIM];

// ---------------- helpers ----------------
__device__ __forceinline__ void mma_f16(float* c, const uint32_t* a, const uint32_t* b) {
    asm volatile(
        "mma.sync.aligned.m16n8k16.row.col.f32.f16.f16.f32 "
        "{%0,%1,%2,%3}, {%4,%5,%6,%7}, {%8,%9}, {%0,%1,%2,%3};"
        : "+f"(c[0]), "+f"(c[1]), "+f"(c[2]), "+f"(c[3])
        : "r"(a[0]), "r"(a[1]), "r"(a[2]), "r"(a[3]), "r"(b[0]), "r"(b[1]));
}
__device__ __forceinline__ void ldmatrix_x4(uint32_t* r, uint32_t addr) {
    asm volatile("ldmatrix.sync.aligned.m8n8.x4.shared.b16 {%0,%1,%2,%3}, [%4];"
                 : "=r"(r[0]), "=r"(r[1]), "=r"(r[2]), "=r"(r[3]) : "r"(addr));
}
__device__ __forceinline__ void ldmatrix_x4_trans(uint32_t* r, uint32_t addr) {
    asm volatile("ldmatrix.sync.aligned.m8n8.x4.trans.shared.b16 {%0,%1,%2,%3}, [%4];"
                 : "=r"(r[0]), "=r"(r[1]), "=r"(r[2]), "=r"(r[3]) : "r"(addr));
}
__device__ __forceinline__ void cp_async16(uint32_t dst, const void* src, int srcbytes) {
    asm volatile("cp.async.cg.shared.global [%0], [%1], 16, %2;"
                 :: "r"(dst), "l"(src), "r"(srcbytes));
}

// ---------------- prep: f32 -> f16 convert copies ----------------
__global__ void half_copy(const float4* __restrict__ src, __half2* __restrict__ dst,
                          long long n4) {
    long long i = (long long)blockIdx.x * blockDim.x + threadIdx.x;
    if (i >= n4) return;
    float4 v = src[i];
    dst[i * 2 + 0] = __floats2half2_rn(v.x, v.y);
    dst[i * 2 + 1] = __floats2half2_rn(v.z, v.w);
}

// merged convert of the 3 expert weight tensors (each exactly 2^23 float4s)
#define EW_N4_SHIFT 23
__global__ void half_copy3(const float4* __restrict__ s0, const float4* __restrict__ s1,
                           const float4* __restrict__ s2,
                           __half2* __restrict__ d0, __half2* __restrict__ d1,
                           __half2* __restrict__ d2) {
    long long i = (long long)blockIdx.x * blockDim.x + threadIdx.x;
    int sel = (int)(i >> EW_N4_SHIFT);
    long long idx = i & ((1LL << EW_N4_SHIFT) - 1);
    const float4* s = (sel == 0) ? s0 : (sel == 1) ? s1 : s2;
    __half2* d = (sel == 0) ? d0 : (sel == 1) ? d1 : d2;
    float4 v = s[idx];
    d[idx * 2 + 0] = __floats2half2_rn(v.x, v.y);
    d[idx * 2 + 1] = __floats2half2_rn(v.z, v.w);
}

// ---------------- routing ----------------
#define SCORE_TOK 16
#define XS_STRIDE 1028
__global__ void __launch_bounds__(256) score_kernel(
    const float* __restrict__ x, const float* __restrict__ rw,
    float* __restrict__ scores) {
    extern __shared__ float xs[];   // [SCORE_TOK][XS_STRIDE]
    int t0 = blockIdx.y * SCORE_TOK;
    int tid = threadIdx.x, lane = tid & 31, wid = tid >> 5;

    for (int idx = tid; idx < SCORE_TOK * 256; idx += 256) {
        int t = idx >> 8, j = idx & 255;
        *(float4*)&xs[t * XS_STRIDE + j * 4] =
            *(const float4*)(x + (size_t)(t0 + t) * CDIM + j * 4);
    }
    __syncthreads();

    int e0 = blockIdx.x * 16 + wid * 2;
    const float* w0 = rw + (size_t)e0 * CDIM;
    const float* w1 = rw + (size_t)(e0 + 1) * CDIM;
    float acc0[SCORE_TOK], acc1[SCORE_TOK];
    #pragma unroll
    for (int t = 0; t < SCORE_TOK; t++) { acc0[t] = 0.f; acc1[t] = 0.f; }

    #pragma unroll
    for (int i = 0; i < 8; i++) {
        int c = lane * 4 + i * 128;
        float4 a = *(const float4*)(w0 + c);
        float4 b = *(const float4*)(w1 + c);
        #pragma unroll
        for (int t = 0; t < SCORE_TOK; t++) {
            float4 xv = *(const float4*)&xs[t * XS_STRIDE + c];
            acc0[t] += a.x * xv.x + a.y * xv.y + a.z * xv.z + a.w * xv.w;
            acc1[t] += b.x * xv.x + b.y * xv.y + b.z * xv.z + b.w * xv.w;
        }
    }
    #pragma unroll
    for (int t = 0; t < SCORE_TOK; t++) {
        float s0 = acc0[t], s1 = acc1[t];
        #pragma unroll
        for (int o = 16; o > 0; o >>= 1) {
            s0 += __shfl_xor_sync(0xffffffffu, s0, o);
            s1 += __shfl_xor_sync(0xffffffffu, s1, o);
        }
        if (lane == 0) {
            scores[(size_t)(t0 + t) * EXP + e0]     = 1.f / (1.f + expf(-s0));
            scores[(size_t)(t0 + t) * EXP + e0 + 1] = 1.f / (1.f + expf(-s1));
        }
    }
}

__global__ void __launch_bounds__(SEL_BLK) select_kernel(
    const float* __restrict__ scores, const float* __restrict__ ebias) {
    __shared__ float sbs[SEL_BLK * 65];
    __shared__ float eb[EXP];
    __shared__ int cnt[EXP];
    int tid = threadIdx.x;
    if (tid < EXP) { cnt[tid] = 0; eb[tid] = ebias[tid]; }
    __syncthreads();

    int t = blockIdx.x * SEL_BLK + tid;
    float* sb = &sbs[tid * 65];
    const float* srow = scores + (size_t)t * EXP;
    for (int e = 0; e < EXP; e++) sb[e] = srow[e] + eb[e];

    float grp[NGRP];
    for (int g = 0; g < NGRP; g++) {
        float m1 = -1e30f, m2 = -1e30f;
        for (int j = 0; j < EPG; j++) {
            float v = sb[g * EPG + j];
            if (v > m1) { m2 = m1; m1 = v; }
            else if (v > m2) m2 = v;
        }
        grp[g] = m1 + m2;
    }
    bool gsel[NGRP] = {};
    for (int it = 0; it < TGRP; it++) {
        float best = -1e30f; int bi = 0;
        for (int g = 0; g < NGRP; g++)
            if (!gsel[g] && grp[g] > best) { best = grp[g]; bi = g; }
        gsel[bi] = true;
    }
    bool eused[EXP] = {};
    int idx[TOPK]; float wv[TOPK]; float wsum = 0.f;
    for (int it = 0; it < TOPK; it++) {
        float best = -1e30f; int bi = 0;
        for (int e = 0; e < EXP; e++)
            if (gsel[e / EPG] && !eused[e] && sb[e] > best) { best = sb[e]; bi = e; }
        eused[bi] = true; idx[it] = bi;
        float s = srow[bi];
        wv[it] = s; wsum += s;
    }
    float inv = 1.f / (wsum + 1e-20f);
    for (int it = 0; it < TOPK; it++) {
        g_topk_idx[t * TOPK + it] = idx[it];
        g_topk_w[t * TOPK + it]   = wv[it] * inv;
        atomicAdd(&cnt[idx[it]], 1);
    }
    __syncthreads();
    if (tid < EXP) g_cnt_part[blockIdx.x * EXP + tid] = cnt[tid];
}

__global__ void setup_kernel() {
    __shared__ int s[EXP];
    __shared__ int s2[EXP];
    int t = threadIdx.x;
    int c = 0;
    for (int b = 0; b < SEL_NBLK; b++) c += g_cnt_part[b * EXP + t];
    int nt_e = (c + 127) >> 7;
    s[t] = c; s2[t] = nt_e;
    __syncthreads();
    for (int off = 1; off < EXP; off <<= 1) {
        int v = (t >= off) ? s[t - off] : 0;
        int v2 = (t >= off) ? s2[t - off] : 0;
        __syncthreads();
        s[t] += v; s2[t] += v2;
        __syncthreads();
    }
    int off_e = s[t] - c;
    int toff_e = s2[t] - nt_e;
    g_cursor[t] = off_e;
    if (t == EXP - 1) g_ntiles = s2[t];
    for (int r = 0, k = 0; r < c; r += 128, k++) {
        g_tiles[toff_e + k].e = t;
        g_tiles[toff_e + k].row_start = off_e + r;
        g_tiles[toff_e + k].rows = min(128, c - r);
    }
}

__global__ void assign_kernel() {
    int d = blockIdx.x * blockDim.x + threadIdx.x;
    if (d >= NROWS) return;
    int e = g_topk_idx[d];
    int pos = atomicAdd(&g_cursor[e], 1);
    g_rowmap[pos] = d;
}

// ---------------- GEMM tiling constants ----------------
#define GEMM_THREADS 128
#define STAGES 5
#define A_STRIDE_H 40
#define B_STRIDE_H 136
#define A_SZ_H (128 * A_STRIDE_H)           // 5120 halfs
#define B_SZ_H (32 * B_STRIDE_H)            // 4352 halfs
#define PIPE_H (STAGES * (A_SZ_H + B_SZ_H)) // 47360 halfs = 94720 B
#define GEMM_SMEM_BYTES (PIPE_H * 2 + 512)  // + tokmap

// ================= fused gate|up GEMM + in-register SwiGLU =================
template <bool GROUPED, bool INDIRECT>
__global__ void __launch_bounds__(GEMM_THREADS, 2) gu_gemm(
    const __half* __restrict__ A, const __half* __restrict__ Bg,
    const __half* __restrict__ Bu, __half* __restrict__ Hout,
    int Kd, int Nh, long long strideB) {
    extern __shared__ __half smem_h[];
    int* tokmap = (int*)(smem_h + PIPE_H);

    int row_start, rows, e;
    if (GROUPED) {
        if ((int)blockIdx.y >= g_ntiles) return;
        TileDesc td = g_tiles[blockIdx.y];
        e = td.e; row_start = td.row_start; rows = td.rows;
    } else {
        e = 0; row_start = blockIdx.y * 128; rows = 128;
    }
    int h0 = blockIdx.x * 64;
    const __half* Bgp = Bg + (long long)e * strideB + h0;
    const __half* Bup = Bu + (long long)e * strideB + h0;
    const __half* Aptr = A + (long long)row_start * Kd;

    int tid = threadIdx.x;
    int lane = tid & 31, wid = tid >> 5;
    int g = lane >> 2, tig = lane & 3;
    int wmb = (wid >> 1) * 64;
    int wnb = (wid & 1) * 64;

    if (INDIRECT) {
        tokmap[tid] = (tid < rows) ? (g_rowmap[row_start + tid] / TOPK) : -1;
        __syncthreads();
    }

    uint32_t sb = (uint32_t)__cvta_generic_to_shared(smem_h);

    float acc[4][8][4];
    #pragma unroll
    for (int mi = 0; mi < 4; mi++)
        #pragma unroll
        for (int ni = 0; ni < 8; ni++)
            #pragma unroll
            for (int q = 0; q < 4; q++) acc[mi][ni][q] = 0.f;

    const int T = Kd >> 5;

    auto issue = [&](int stage, int it) {
        int kk = it * 32;
        uint32_t abase = sb + (uint32_t)(stage * A_SZ_H) * 2u;
        uint32_t bbase = sb + (uint32_t)(STAGES * A_SZ_H + stage * B_SZ_H) * 2u;
        #pragma unroll
        for (int i = 0; i < 4; i++) {
            int c = tid + i * 128;
            int r = c >> 2, j = c & 3;
            const __half* src;
            int vb = 16;
            if (INDIRECT) {
                int tok = tokmap[r];
                if (tok < 0) { vb = 0; src = A; }
                else src = A + (long long)tok * Kd + kk + j * 8;
            } else {
                src = Aptr + (long long)r * Kd + kk + j * 8;
                if (GROUPED && r >= rows) { vb = 0; src = Aptr; }
            }
            cp_async16(abase + (uint32_t)(r * A_STRIDE_H + j * 8) * 2u, src, vb);
        }
        #pragma unroll
        for (int i = 0; i < 4; i++) {
            int c = tid + i * 128;
            int r = c >> 4, j = c & 15;
            int seg = j >> 2, inner = (j & 3) * 8;
            const __half* base = (seg & 1) ? Bup : Bgp;
            const __half* src = base + (long long)(kk + r) * Nh + (seg >> 1) * 32 + inner;
            cp_async16(bbase + (uint32_t)(r * B_STRIDE_H + j * 8) * 2u, src, 16);
        }
        asm volatile("cp.async.commit_group;" ::: "memory");
    };

    issue(0, 0);
    issue(1, 1);
    issue(2, 2);
    issue(3, 3);

    int lhalf = lane & 15, lsel8 = (lane >> 4) << 3;
    int stage = 0, wstage = 4;
    for (int it = 0; it < T; it++) {
        asm volatile("cp.async.wait_group 3;" ::: "memory");
        __syncthreads();
        if (it + 4 < T) issue(wstage, it + 4);

        uint32_t abase = sb + (uint32_t)(stage * A_SZ_H) * 2u;
        uint32_t bbase = sb + (uint32_t)(STAGES * A_SZ_H + stage * B_SZ_H) * 2u;

        #pragma unroll
        for (int ks = 0; ks < 2; ks++) {
            int k0 = ks * 16;
            uint32_t af[4][4], bf[4][4];
            #pragma unroll
            for (int mi = 0; mi < 4; mi++)
                ldmatrix_x4(af[mi], abase +
                    (uint32_t)((wmb + mi * 16 + lhalf) * A_STRIDE_H + k0 + lsel8) * 2u);
            #pragma unroll
            for (int nc = 0; nc < 4; nc++)
                ldmatrix_x4_trans(bf[nc], bbase +
                    (uint32_t)((k0 + lhalf) * B_STRIDE_H + wnb + nc * 16 + lsel8) * 2u);
            #pragma unroll
            for (int mi = 0; mi < 4; mi++)
                #pragma unroll
                for (int nc = 0; nc < 4; nc++) {
                    mma_f16(acc[mi][2 * nc + 0], af[mi], &bf[nc][0]);
                    mma_f16(acc[mi][2 * nc + 1], af[mi], &bf[nc][2]);
                }
        }
        if (++stage == STAGES) stage = 0;
        if (++wstage == STAGES) wstage = 0;
    }

    // ---- in-register SwiGLU epilogue ----
    int hbase = h0 + (wnb >> 1);
    #pragma unroll
    for (int mi = 0; mi < 4; mi++) {
        #pragma unroll
        for (int h = 0; h < 2; h++) {
            int rl = wmb + mi * 16 + g + 8 * h;
            if (GROUPED && rl >= rows) continue;
            __half* dst = Hout + (size_t)(row_start + rl) * Nh + hbase;
            #pragma unroll
            for (int ni = 0; ni < 4; ni++) {
                float g0 = acc[mi][ni][2 * h + 0];
                float g1 = acc[mi][ni][2 * h + 1];
                float u0 = acc[mi][ni + 4][2 * h + 0];
                float u1 = acc[mi][ni + 4][2 * h + 1];
                float r0 = g0 / (1.f + expf(-g0)) * u0;
                float r1 = g1 / (1.f + expf(-g1)) * u1;
                *(__half2*)(dst + ni * 8 + 2 * tig) = __floats2half2_rn(r0, r1);
            }
        }
    }
}

// ================= plain fp16 GEMM (down projections) =================
template <bool GROUPED, int MODE>
__global__ void __launch_bounds__(GEMM_THREADS, 2) mma_gemm(
    const __half* __restrict__ A, const __half* __restrict__ B0,
    float* __restrict__ CoutF,
    int Kd, int N, long long strideB,
    const int* __restrict__ rowmap, const float* __restrict__ rowscale) {
    extern __shared__ __half smem_h[];

    int row_start, rows, e;
    if (GROUPED) {
        if ((int)blockIdx.y >= g_ntiles) return;
        TileDesc td = g_tiles[blockIdx.y];
        e = td.e; row_start = td.row_start; rows = td.rows;
    } else {
        e = 0; row_start = blockIdx.y * 128; rows = 128;
    }
    int n0 = blockIdx.x * 128;
    const __half* Bptr = B0 + (long long)e * strideB + n0;
    const __half* Aptr = A + (long long)row_start * Kd;

    int tid = threadIdx.x;
    int lane = tid & 31, wid = tid >> 5;
    int g = lane >> 2, tig = lane & 3;
    int wmb = (wid >> 1) * 64;
    int wnb = (wid & 1) * 64;

    uint32_t sb = (uint32_t)__cvta_generic_to_shared(smem_h);

    float acc[4][8][4];
    #pragma unroll
    for (int mi = 0; mi < 4; mi++)
        #pragma unroll
        for (int ni = 0; ni < 8; ni++)
            #pragma unroll
            for (int q = 0; q < 4; q++) acc[mi][ni][q] = 0.f;

    const int T = Kd >> 5;

    auto issue = [&](int stage, int it) {
        int kk = it * 32;
        uint32_t abase = sb + (uint32_t)(stage * A_SZ_H) * 2u;
        uint32_t bbase = sb + (uint32_t)(STAGES * A_SZ_H + stage * B_SZ_H) * 2u;
        #pragma unroll
        for (int i = 0; i < 4; i++) {
            int c = tid + i * 128;
            int r = c >> 2, j = c & 3;
            const __half* src = Aptr + (long long)r * Kd + kk + j * 8;
            int vb = 16;
            if (GROUPED && r >= rows) { vb = 0; src = Aptr; }
            cp_async16(abase + (uint32_t)(r * A_STRIDE_H + j * 8) * 2u, src, vb);
        }
        #pragma unroll
        for (int i = 0; i < 4; i++) {
            int c = tid + i * 128;
            int r = c >> 4, j = c & 15;
            cp_async16(bbase + (uint32_t)(r * B_STRIDE_H + j * 8) * 2u,
                       Bptr + (long long)(kk + r) * N + j * 8, 16);
        }
        asm volatile("cp.async.commit_group;" ::: "memory");
    };

    issue(0, 0);
    issue(1, 1);
    issue(2, 2);
    issue(3, 3);

    int lhalf = lane & 15, lsel8 = (lane >> 4) << 3;
    int stage = 0, wstage = 4;
    for (int it = 0; it < T; it++) {
        asm volatile("cp.async.wait_group 3;" ::: "memory");
        __syncthreads();
        if (it + 4 < T) issue(wstage, it + 4);

        uint32_t abase = sb + (uint32_t)(stage * A_SZ_H) * 2u;
        uint32_t bbase = sb + (uint32_t)(STAGES * A_SZ_H + stage * B_SZ_H) * 2u;

        #pragma unroll
        for (int ks = 0; ks < 2; ks++) {
            int k0 = ks * 16;
            uint32_t af[4][4], bf[4][4];
            #pragma unroll
            for (int mi = 0; mi < 4; mi++)
                ldmatrix_x4(af[mi], abase +
                    (uint32_t)((wmb + mi * 16 + lhalf) * A_STRIDE_H + k0 + lsel8) * 2u);
            #pragma unroll
            for (int nc = 0; nc < 4; nc++)
                ldmatrix_x4_trans(bf[nc], bbase +
                    (uint32_t)((k0 + lhalf) * B_STRIDE_H + wnb + nc * 16 + lsel8) * 2u);
            #pragma unroll
            for (int mi = 0; mi < 4; mi++)
                #pragma unroll
                for (int nc = 0; nc < 4; nc++) {
                    mma_f16(acc[mi][2 * nc + 0], af[mi], &bf[nc][0]);
                    mma_f16(acc[mi][2 * nc + 1], af[mi], &bf[nc][2]);
                }
        }
        if (++stage == STAGES) stage = 0;
        if (++wstage == STAGES) wstage = 0;
    }

    #pragma unroll
    for (int mi = 0; mi < 4; mi++) {
        #pragma unroll
        for (int h = 0; h < 2; h++) {
            int rl = wmb + mi * 16 + g + 8 * h;
            if (GROUPED && rl >= rows) continue;
            if (MODE == 2) {
                int d = rowmap[row_start + rl];
                float scale = rowscale[d];
                float* dst = CoutF + (size_t)(d / TOPK) * N;
                #pragma unroll
                for (int ni = 0; ni < 8; ni++) {
                    int col = n0 + wnb + ni * 8 + 2 * tig;
                    atomicAdd(dst + col,     acc[mi][ni][2 * h + 0] * scale);
                    atomicAdd(dst + col + 1, acc[mi][ni][2 * h + 1] * scale);
                }
            } else {
                float* dst = CoutF + (size_t)(row_start + rl) * N;
                #pragma unroll
                for (int ni = 0; ni < 8; ni++) {
                    int col = n0 + wnb + ni * 8 + 2 * tig;
                    float2 v;
                    v.x = acc[mi][ni][2 * h + 0];
                    v.y = acc[mi][ni][2 * h + 1];
                    *(float2*)(dst + col) = v;
                }
            }
        }
    }
}

// ---------------- launch ----------------
extern "C" void kernel_launch(void* const* d_in, const int* in_sizes, int n_in,
                              void* d_out, int out_size) {
    const float* x        = (const float*)d_in[0];
    const float* router_w = (const float*)d_in[1];
    const float* e_bias   = (const float*)d_in[2];
    const float* gate_w   = (const float*)d_in[3];
    const float* up_w     = (const float*)d_in[4];
    const float* down_w   = (const float*)d_in[5];
    const float* sh_gate  = (const float*)d_in[6];
    const float* sh_up    = (const float*)d_in[7];
    const float* sh_down  = (const float*)d_in[8];
    float* out = (float*)d_out;

    __half *p_hbuf, *p_sh_h, *p_x_r;
    __half *p_w_gate, *p_w_up, *p_w_down, *p_w_shg, *p_w_shu, *p_w_shd;
    float *p_topk_w, *p_scores;
    int* p_rowmap;
    cudaGetSymbolAddress((void**)&p_hbuf,     g_hbuf);
    cudaGetSymbolAddress((void**)&p_sh_h,     g_sh_h);
    cudaGetSymbolAddress((void**)&p_topk_w,   g_topk_w);
    cudaGetSymbolAddress((void**)&p_rowmap,   g_rowmap);
    cudaGetSymbolAddress((void**)&p_x_r,      g_x_r);
    cudaGetSymbolAddress((void**)&p_scores,   g_scores);
    cudaGetSymbolAddress((void**)&p_w_gate,   g_w_gate);
    cudaGetSymbolAddress((void**)&p_w_up,     g_w_up);
    cudaGetSymbolAddress((void**)&p_w_down,   g_w_down);
    cudaGetSymbolAddress((void**)&p_w_shg,    g_w_shg);
    cudaGetSymbolAddress((void**)&p_w_shu,    g_w_shu);
    cudaGetSymbolAddress((void**)&p_w_shd,    g_w_shd);

    cudaFuncSetAttribute((const void*)gu_gemm<false, false>,
                         cudaFuncAttributeMaxDynamicSharedMemorySize, GEMM_SMEM_BYTES);
    cudaFuncSetAttribute((const void*)gu_gemm<true, true>,
                         cudaFuncAttributeMaxDynamicSharedMemorySize, GEMM_SMEM_BYTES);
    cudaFuncSetAttribute((const void*)mma_gemm<false, 0>,
                         cudaFuncAttributeMaxDynamicSharedMemorySize, GEMM_SMEM_BYTES);
    cudaFuncSetAttribute((const void*)mma_gemm<true, 2>,
                         cudaFuncAttributeMaxDynamicSharedMemorySize, GEMM_SMEM_BYTES);
    int score_smem = SCORE_TOK * XS_STRIDE * 4;
    cudaFuncSetAttribute((const void*)score_kernel,
                         cudaFuncAttributeMaxDynamicSharedMemorySize, score_smem);

    // one-time side stream + events (created OUTSIDE graph capture on the
    // correctness call; reused identically on every call — deterministic work)
    static cudaStream_t s_side = nullptr;
    static cudaEvent_t s_fork, s_join;
    if (!s_side) {
        cudaStreamCreateWithFlags(&s_side, cudaStreamNonBlocking);
        cudaEventCreateWithFlags(&s_fork, cudaEventDisableTiming);
        cudaEventCreateWithFlags(&s_join, cudaEventDisableTiming);
    }

    long long n4;

    // ---- fork: side stream joins the capture via event dependency ----
    cudaEventRecord(s_fork, 0);
    cudaStreamWaitEvent(s_side, s_fork, 0);

    // ===== SIDE STREAM: routing + expert weight conversion (memory-bound) =====
    score_kernel<<<dim3(EXP / 16, S_TOK / SCORE_TOK), 256, score_smem, s_side>>>(
        x, router_w, p_scores);
    select_kernel<<<SEL_NBLK, SEL_BLK, 0, s_side>>>(p_scores, e_bias);
    {
        long long total = 3LL << EW_N4_SHIFT;
        half_copy3<<<(unsigned)(total / 256), 256, 0, s_side>>>(
            (const float4*)gate_w, (const float4*)up_w, (const float4*)down_w,
            (__half2*)p_w_gate, (__half2*)p_w_up, (__half2*)p_w_down);
    }
    setup_kernel<<<1, 64, 0, s_side>>>();
    assign_kernel<<<NROWS / 256, 256, 0, s_side>>>();
    cudaEventRecord(s_join, s_side);

    // ===== MAIN STREAM: shared expert (compute-bound) =====
    n4 = (long long)CDIM * HSHARED / 4;
    half_copy<<<(unsigned)((n4 + 255) / 256), 256>>>((const float4*)sh_gate, (__half2*)p_w_shg, n4);
    half_copy<<<(unsigned)((n4 + 255) / 256), 256>>>((const float4*)sh_up,   (__half2*)p_w_shu, n4);
    n4 = (long long)S_TOK * CDIM / 4;
    half_copy<<<(unsigned)((n4 + 255) / 256), 256>>>((const float4*)x, (__half2*)p_x_r, n4);
    n4 = (long long)CDIM * HSHARED / 4;
    half_copy<<<(unsigned)((n4 + 255) / 256), 256>>>((const float4*)sh_down, (__half2*)p_w_shd, n4);

    gu_gemm<false, false><<<dim3(HSHARED / 64, S_TOK / 128), GEMM_THREADS, GEMM_SMEM_BYTES>>>(
        p_x_r, p_w_shg, p_w_shu, p_sh_h, CDIM, HSHARED, 0);
    mma_gemm<false, 0><<<dim3(CDIM / 128, S_TOK / 128), GEMM_THREADS, GEMM_SMEM_BYTES>>>(
        p_sh_h, p_w_shd, out, HSHARED, CDIM, 0, nullptr, nullptr);

    // ---- join: routed experts need side-stream results ----
    cudaStreamWaitEvent(0, s_join, 0);

    // routed gu GEMM + fused swiglu (grouped, indirect A from x_r)
    gu_gemm<true, true><<<dim3(HDIM / 64, MAX_TILES), GEMM_THREADS, GEMM_SMEM_BYTES>>>(
        p_x_r, p_w_gate, p_w_up, p_hbuf, CDIM, HDIM, (long long)CDIM * HDIM);

    // routed down: atomicAdd scaled rows into out
    mma_gemm<true, 2><<<dim3(CDIM / 128, MAX_TILES), GEMM_THREADS, GEMM_SMEM_BYTES>>>(
        p_hbuf, p_w_down, out, HDIM, CDIM, (long long)HDIM * CDIM,
        p_rowmap, p_topk_w);
}

// round 14
// speedup vs baseline: 1.4428x; 1.0058x over previous
#include <cuda_runtime.h>
#include <cuda_fp16.h>
#include <math.h>
#include <stdint.h>

// ---------------- problem constants ----------------
#define S_TOK   4096
#define CDIM    1024
#define EXP     64
#define TOPK    8
#define NGRP    8
#define EPG     8
#define TGRP    4
#define HDIM    512
#define HSHARED 2048
#define NROWS   (S_TOK * TOPK)   // 32768
#define MAX_TILES 320
#define SEL_BLK 128
#define SEL_NBLK (S_TOK / SEL_BLK)   // 32

// ---------------- scratch (static device globals) ----------------
struct TileDesc { int e; int row_start; int rows; };

__device__ int      g_cnt_part[SEL_NBLK * EXP];
__device__ int      g_cursor[EXP];
__device__ TileDesc g_tiles[MAX_TILES];
__device__ int      g_ntiles;
__device__ int      g_rowmap[NROWS];
__device__ int      g_topk_idx[NROWS];
__device__ float    g_topk_w[NROWS];
__device__ float    g_scores[(size_t)S_TOK * EXP];

__device__ __half   g_hbuf[(size_t)NROWS * HDIM];       // routed h (post-swiglu)
__device__ __half   g_sh_h[(size_t)S_TOK * HSHARED];    // shared h (post-swiglu)
__device__ __half   g_x_r[(size_t)S_TOK * CDIM];

// fp16 weight copies (native [K][N] layouts preserved)
__device__ __half   g_w_gate[(size_t)EXP * CDIM * HDIM];
__device__ __half   g_w_up[(size_t)EXP * CDIM * HDIM];
__device__ __half   g_w_down[(size_t)EXP * HDIM * CDIM];
__device__ __half   g_w_shg[(size_t)CDIM * HSHARED];
__device__ __half   g_w_shu[(size_t)CDIM * HSHARED];
__device__ __half   g_w_shd[(size_t)HSHARED * CDIM];

// ---------------- helpers ----------------
__device__ __forceinline__ void mma_f16(float* c, const uint32_t* a, const uint32_t* b) {
    asm volatile(
        "mma.sync.aligned.m16n8k16.row.col.f32.f16.f16.f32 "
        "{%0,%1,%2,%3}, {%4,%5,%6,%7}, {%8,%9}, {%0,%1,%2,%3};"
        : "+f"(c[0]), "+f"(c[1]), "+f"(c[2]), "+f"(c[3])
        : "r"(a[0]), "r"(a[1]), "r"(a[2]), "r"(a[3]), "r"(b[0]), "r"(b[1]));
}
__device__ __forceinline__ void ldmatrix_x4(uint32_t* r, uint32_t addr) {
    asm volatile("ldmatrix.sync.aligned.m8n8.x4.shared.b16 {%0,%1,%2,%3}, [%4];"
                 : "=r"(r[0]), "=r"(r[1]), "=r"(r[2]), "=r"(r[3]) : "r"(addr));
}
__device__ __forceinline__ void ldmatrix_x4_trans(uint32_t* r, uint32_t addr) {
    asm volatile("ldmatrix.sync.aligned.m8n8.x4.trans.shared.b16 {%0,%1,%2,%3}, [%4];"
                 : "=r"(r[0]), "=r"(r[1]), "=r"(r[2]), "=r"(r[3]) : "r"(addr));
}
__device__ __forceinline__ void cp_async16(uint32_t dst, const void* src, int srcbytes) {
    asm volatile("cp.async.cg.shared.global [%0], [%1], 16, %2;"
                 :: "r"(dst), "l"(src), "r"(srcbytes));
}
__device__ __forceinline__ void red_add_v2(float* ptr, float a, float b) {
    asm volatile("red.global.add.v2.f32 [%0], {%1, %2};"
                 :: "l"(ptr), "f"(a), "f"(b) : "memory");
}

// ---------------- prep: f32 -> f16 convert copies ----------------
__global__ void half_copy(const float4* __restrict__ src, __half2* __restrict__ dst,
                          long long n4) {
    long long i = (long long)blockIdx.x * blockDim.x + threadIdx.x;
    if (i >= n4) return;
    float4 v = src[i];
    dst[i * 2 + 0] = __floats2half2_rn(v.x, v.y);
    dst[i * 2 + 1] = __floats2half2_rn(v.z, v.w);
}

#define EW_N4_SHIFT 23
__global__ void half_copy3(const float4* __restrict__ s0, const float4* __restrict__ s1,
                           const float4* __restrict__ s2,
                           __half2* __restrict__ d0, __half2* __restrict__ d1,
                           __half2* __restrict__ d2) {
    long long i = (long long)blockIdx.x * blockDim.x + threadIdx.x;
    int sel = (int)(i >> EW_N4_SHIFT);
    long long idx = i & ((1LL << EW_N4_SHIFT) - 1);
    const float4* s = (sel == 0) ? s0 : (sel == 1) ? s1 : s2;
    __half2* d = (sel == 0) ? d0 : (sel == 1) ? d1 : d2;
    float4 v = s[idx];
    d[idx * 2 + 0] = __floats2half2_rn(v.x, v.y);
    d[idx * 2 + 1] = __floats2half2_rn(v.z, v.w);
}

// ---------------- routing ----------------
#define SCORE_TOK 16
#define XS_STRIDE 1028
__global__ void __launch_bounds__(256) score_kernel(
    const float* __restrict__ x, const float* __restrict__ rw,
    float* __restrict__ scores) {
    extern __shared__ float xs[];   // [SCORE_TOK][XS_STRIDE]
    int t0 = blockIdx.y * SCORE_TOK;
    int tid = threadIdx.x, lane = tid & 31, wid = tid >> 5;

    for (int idx = tid; idx < SCORE_TOK * 256; idx += 256) {
        int t = idx >> 8, j = idx & 255;
        *(float4*)&xs[t * XS_STRIDE + j * 4] =
            *(const float4*)(x + (size_t)(t0 + t) * CDIM + j * 4);
    }
    __syncthreads();

    int e0 = blockIdx.x * 16 + wid * 2;
    const float* w0 = rw + (size_t)e0 * CDIM;
    const float* w1 = rw + (size_t)(e0 + 1) * CDIM;
    float acc0[SCORE_TOK], acc1[SCORE_TOK];
    #pragma unroll
    for (int t = 0; t < SCORE_TOK; t++) { acc0[t] = 0.f; acc1[t] = 0.f; }

    #pragma unroll
    for (int i = 0; i < 8; i++) {
        int c = lane * 4 + i * 128;
        float4 a = *(const float4*)(w0 + c);
        float4 b = *(const float4*)(w1 + c);
        #pragma unroll
        for (int t = 0; t < SCORE_TOK; t++) {
            float4 xv = *(const float4*)&xs[t * XS_STRIDE + c];
            acc0[t] += a.x * xv.x + a.y * xv.y + a.z * xv.z + a.w * xv.w;
            acc1[t] += b.x * xv.x + b.y * xv.y + b.z * xv.z + b.w * xv.w;
        }
    }
    #pragma unroll
    for (int t = 0; t < SCORE_TOK; t++) {
        float s0 = acc0[t], s1 = acc1[t];
        #pragma unroll
        for (int o = 16; o > 0; o >>= 1) {
            s0 += __shfl_xor_sync(0xffffffffu, s0, o);
            s1 += __shfl_xor_sync(0xffffffffu, s1, o);
        }
        if (lane == 0) {
            scores[(size_t)(t0 + t) * EXP + e0]     = 1.f / (1.f + expf(-s0));
            scores[(size_t)(t0 + t) * EXP + e0 + 1] = 1.f / (1.f + expf(-s1));
        }
    }
}

__global__ void __launch_bounds__(SEL_BLK) select_kernel(
    const float* __restrict__ scores, const float* __restrict__ ebias) {
    __shared__ float sbs[SEL_BLK * 65];
    __shared__ float eb[EXP];
    __shared__ int cnt[EXP];
    int tid = threadIdx.x;
    if (tid < EXP) { cnt[tid] = 0; eb[tid] = ebias[tid]; }
    __syncthreads();

    int t = blockIdx.x * SEL_BLK + tid;
    float* sb = &sbs[tid * 65];
    const float* srow = scores + (size_t)t * EXP;
    for (int e = 0; e < EXP; e++) sb[e] = srow[e] + eb[e];

    float grp[NGRP];
    for (int g = 0; g < NGRP; g++) {
        float m1 = -1e30f, m2 = -1e30f;
        for (int j = 0; j < EPG; j++) {
            float v = sb[g * EPG + j];
            if (v > m1) { m2 = m1; m1 = v; }
            else if (v > m2) m2 = v;
        }
        grp[g] = m1 + m2;
    }
    bool gsel[NGRP] = {};
    for (int it = 0; it < TGRP; it++) {
        float best = -1e30f; int bi = 0;
        for (int g = 0; g < NGRP; g++)
            if (!gsel[g] && grp[g] > best) { best = grp[g]; bi = g; }
        gsel[bi] = true;
    }
    bool eused[EXP] = {};
    int idx[TOPK]; float wv[TOPK]; float wsum = 0.f;
    for (int it = 0; it < TOPK; it++) {
        float best = -1e30f; int bi = 0;
        for (int e = 0; e < EXP; e++)
            if (gsel[e / EPG] && !eused[e] && sb[e] > best) { best = sb[e]; bi = e; }
        eused[bi] = true; idx[it] = bi;
        float s = srow[bi];
        wv[it] = s; wsum += s;
    }
    float inv = 1.f / (wsum + 1e-20f);
    for (int it = 0; it < TOPK; it++) {
        g_topk_idx[t * TOPK + it] = idx[it];
        g_topk_w[t * TOPK + it]   = wv[it] * inv;
        atomicAdd(&cnt[idx[it]], 1);
    }
    __syncthreads();
    if (tid < EXP) g_cnt_part[blockIdx.x * EXP + tid] = cnt[tid];
}

__global__ void setup_kernel() {
    __shared__ int s[EXP];
    __shared__ int s2[EXP];
    int t = threadIdx.x;
    int c = 0;
    for (int b = 0; b < SEL_NBLK; b++) c += g_cnt_part[b * EXP + t];
    int nt_e = (c + 127) >> 7;
    s[t] = c; s2[t] = nt_e;
    __syncthreads();
    for (int off = 1; off < EXP; off <<= 1) {
        int v = (t >= off) ? s[t - off] : 0;
        int v2 = (t >= off) ? s2[t - off] : 0;
        __syncthreads();
        s[t] += v; s2[t] += v2;
        __syncthreads();
    }
    int off_e = s[t] - c;
    int toff_e = s2[t] - nt_e;
    g_cursor[t] = off_e;
    if (t == EXP - 1) g_ntiles = s2[t];
    for (int r = 0, k = 0; r < c; r += 128, k++) {
        g_tiles[toff_e + k].e = t;
        g_tiles[toff_e + k].row_start = off_e + r;
        g_tiles[toff_e + k].rows = min(128, c - r);
    }
}

__global__ void assign_kernel() {
    int d = blockIdx.x * blockDim.x + threadIdx.x;
    if (d >= NROWS) return;
    int e = g_topk_idx[d];
    int pos = atomicAdd(&g_cursor[e], 1);
    g_rowmap[pos] = d;
}

// ---------------- GEMM tiling constants ----------------
#define GEMM_THREADS 128
#define STAGES 5
#define A_STRIDE_H 40
#define B_STRIDE_H 136
#define A_SZ_H (128 * A_STRIDE_H)           // 5120 halfs
#define B_SZ_H (32 * B_STRIDE_H)            // 4352 halfs
#define PIPE_H (STAGES * (A_SZ_H + B_SZ_H)) // 47360 halfs = 94720 B
#define GEMM_SMEM_BYTES (PIPE_H * 2 + 512)  // + tokmap

// ================= fused gate|up GEMM + in-register SwiGLU =================
template <bool GROUPED, bool INDIRECT>
__global__ void __launch_bounds__(GEMM_THREADS, 2) gu_gemm(
    const __half* __restrict__ A, const __half* __restrict__ Bg,
    const __half* __restrict__ Bu, __half* __restrict__ Hout,
    int Kd, int Nh, long long strideB) {
    extern __shared__ __half smem_h[];
    int* tokmap = (int*)(smem_h + PIPE_H);

    int row_start, rows, e;
    if (GROUPED) {
        if ((int)blockIdx.y >= g_ntiles) return;
        TileDesc td = g_tiles[blockIdx.y];
        e = td.e; row_start = td.row_start; rows = td.rows;
    } else {
        e = 0; row_start = blockIdx.y * 128; rows = 128;
    }
    int h0 = blockIdx.x * 64;
    const __half* Bgp = Bg + (long long)e * strideB + h0;
    const __half* Bup = Bu + (long long)e * strideB + h0;
    const __half* Aptr = A + (long long)row_start * Kd;

    int tid = threadIdx.x;
    int lane = tid & 31, wid = tid >> 5;
    int g = lane >> 2, tig = lane & 3;
    int wmb = (wid >> 1) * 64;
    int wnb = (wid & 1) * 64;

    if (INDIRECT) {
        tokmap[tid] = (tid < rows) ? (g_rowmap[row_start + tid] / TOPK) : -1;
        __syncthreads();
    }

    uint32_t sb = (uint32_t)__cvta_generic_to_shared(smem_h);

    float acc[4][8][4];
    #pragma unroll
    for (int mi = 0; mi < 4; mi++)
        #pragma unroll
        for (int ni = 0; ni < 8; ni++)
            #pragma unroll
            for (int q = 0; q < 4; q++) acc[mi][ni][q] = 0.f;

    const int T = Kd >> 5;

    auto issue = [&](int stage, int it) {
        int kk = it * 32;
        uint32_t abase = sb + (uint32_t)(stage * A_SZ_H) * 2u;
        uint32_t bbase = sb + (uint32_t)(STAGES * A_SZ_H + stage * B_SZ_H) * 2u;
        #pragma unroll
        for (int i = 0; i < 4; i++) {
            int c = tid + i * 128;
            int r = c >> 2, j = c & 3;
            const __half* src;
            int vb = 16;
            if (INDIRECT) {
                int tok = tokmap[r];
                if (tok < 0) { vb = 0; src = A; }
                else src = A + (long long)tok * Kd + kk + j * 8;
            } else {
                src = Aptr + (long long)r * Kd + kk + j * 8;
                if (GROUPED && r >= rows) { vb = 0; src = Aptr; }
            }
            cp_async16(abase + (uint32_t)(r * A_STRIDE_H + j * 8) * 2u, src, vb);
        }
        #pragma unroll
        for (int i = 0; i < 4; i++) {
            int c = tid + i * 128;
            int r = c >> 4, j = c & 15;
            int seg = j >> 2, inner = (j & 3) * 8;
            const __half* base = (seg & 1) ? Bup : Bgp;
            const __half* src = base + (long long)(kk + r) * Nh + (seg >> 1) * 32 + inner;
            cp_async16(bbase + (uint32_t)(r * B_STRIDE_H + j * 8) * 2u, src, 16);
        }
        asm volatile("cp.async.commit_group;" ::: "memory");
    };

    issue(0, 0);
    issue(1, 1);
    issue(2, 2);
    issue(3, 3);

    int lhalf = lane & 15, lsel8 = (lane >> 4) << 3;
    int stage = 0, wstage = 4;
    for (int it = 0; it < T; it++) {
        asm volatile("cp.async.wait_group 3;" ::: "memory");
        __syncthreads();
        if (it + 4 < T) issue(wstage, it + 4);

        uint32_t abase = sb + (uint32_t)(stage * A_SZ_H) * 2u;
        uint32_t bbase = sb + (uint32_t)(STAGES * A_SZ_H + stage * B_SZ_H) * 2u;

        #pragma unroll
        for (int ks = 0; ks < 2; ks++) {
            int k0 = ks * 16;
            uint32_t af[4][4], bf[4][4];
            #pragma unroll
            for (int mi = 0; mi < 4; mi++)
                ldmatrix_x4(af[mi], abase +
                    (uint32_t)((wmb + mi * 16 + lhalf) * A_STRIDE_H + k0 + lsel8) * 2u);
            #pragma unroll
            for (int nc = 0; nc < 4; nc++)
                ldmatrix_x4_trans(bf[nc], bbase +
                    (uint32_t)((k0 + lhalf) * B_STRIDE_H + wnb + nc * 16 + lsel8) * 2u);
            #pragma unroll
            for (int mi = 0; mi < 4; mi++)
                #pragma unroll
                for (int nc = 0; nc < 4; nc++) {
                    mma_f16(acc[mi][2 * nc + 0], af[mi], &bf[nc][0]);
                    mma_f16(acc[mi][2 * nc + 1], af[mi], &bf[nc][2]);
                }
        }
        if (++stage == STAGES) stage = 0;
        if (++wstage == STAGES) wstage = 0;
    }

    // ---- in-register SwiGLU epilogue ----
    int hbase = h0 + (wnb >> 1);
    #pragma unroll
    for (int mi = 0; mi < 4; mi++) {
        #pragma unroll
        for (int h = 0; h < 2; h++) {
            int rl = wmb + mi * 16 + g + 8 * h;
            if (GROUPED && rl >= rows) continue;
            __half* dst = Hout + (size_t)(row_start + rl) * Nh + hbase;
            #pragma unroll
            for (int ni = 0; ni < 4; ni++) {
                float g0 = acc[mi][ni][2 * h + 0];
                float g1 = acc[mi][ni][2 * h + 1];
                float u0 = acc[mi][ni + 4][2 * h + 0];
                float u1 = acc[mi][ni + 4][2 * h + 1];
                float r0 = g0 / (1.f + expf(-g0)) * u0;
                float r1 = g1 / (1.f + expf(-g1)) * u1;
                *(__half2*)(dst + ni * 8 + 2 * tig) = __floats2half2_rn(r0, r1);
            }
        }
    }
}

// ================= plain fp16 GEMM (down projections) =================
// MODE 0: fp32 store. MODE 2: red.v2 scaled rows into CoutF[rowmap[row]/TOPK].
template <bool GROUPED, int MODE>
__global__ void __launch_bounds__(GEMM_THREADS, 2) mma_gemm(
    const __half* __restrict__ A, const __half* __restrict__ B0,
    float* __restrict__ CoutF,
    int Kd, int N, long long strideB,
    const int* __restrict__ rowmap, const float* __restrict__ rowscale) {
    extern __shared__ __half smem_h[];

    int row_start, rows, e;
    if (GROUPED) {
        if ((int)blockIdx.y >= g_ntiles) return;
        TileDesc td = g_tiles[blockIdx.y];
        e = td.e; row_start = td.row_start; rows = td.rows;
    } else {
        e = 0; row_start = blockIdx.y * 128; rows = 128;
    }
    int n0 = blockIdx.x * 128;
    const __half* Bptr = B0 + (long long)e * strideB + n0;
    const __half* Aptr = A + (long long)row_start * Kd;

    int tid = threadIdx.x;
    int lane = tid & 31, wid = tid >> 5;
    int g = lane >> 2, tig = lane & 3;
    int wmb = (wid >> 1) * 64;
    int wnb = (wid & 1) * 64;

    uint32_t sb = (uint32_t)__cvta_generic_to_shared(smem_h);

    float acc[4][8][4];
    #pragma unroll
    for (int mi = 0; mi < 4; mi++)
        #pragma unroll
        for (int ni = 0; ni < 8; ni++)
            #pragma unroll
            for (int q = 0; q < 4; q++) acc[mi][ni][q] = 0.f;

    const int T = Kd >> 5;

    auto issue = [&](int stage, int it) {
        int kk = it * 32;
        uint32_t abase = sb + (uint32_t)(stage * A_SZ_H) * 2u;
        uint32_t bbase = sb + (uint32_t)(STAGES * A_SZ_H + stage * B_SZ_H) * 2u;
        #pragma unroll
        for (int i = 0; i < 4; i++) {
            int c = tid + i * 128;
            int r = c >> 2, j = c & 3;
            const __half* src = Aptr + (long long)r * Kd + kk + j * 8;
            int vb = 16;
            if (GROUPED && r >= rows) { vb = 0; src = Aptr; }
            cp_async16(abase + (uint32_t)(r * A_STRIDE_H + j * 8) * 2u, src, vb);
        }
        #pragma unroll
        for (int i = 0; i < 4; i++) {
            int c = tid + i * 128;
            int r = c >> 4, j = c & 15;
            cp_async16(bbase + (uint32_t)(r * B_STRIDE_H + j * 8) * 2u,
                       Bptr + (long long)(kk + r) * N + j * 8, 16);
        }
        asm volatile("cp.async.commit_group;" ::: "memory");
    };

    issue(0, 0);
    issue(1, 1);
    issue(2, 2);
    issue(3, 3);

    int lhalf = lane & 15, lsel8 = (lane >> 4) << 3;
    int stage = 0, wstage = 4;
    for (int it = 0; it < T; it++) {
        asm volatile("cp.async.wait_group 3;" ::: "memory");
        __syncthreads();
        if (it + 4 < T) issue(wstage, it + 4);

        uint32_t abase = sb + (uint32_t)(stage * A_SZ_H) * 2u;
        uint32_t bbase = sb + (uint32_t)(STAGES * A_SZ_H + stage * B_SZ_H) * 2u;

        #pragma unroll
        for (int ks = 0; ks < 2; ks++) {
            int k0 = ks * 16;
            uint32_t af[4][4], bf[4][4];
            #pragma unroll
            for (int mi = 0; mi < 4; mi++)
                ldmatrix_x4(af[mi], abase +
                    (uint32_t)((wmb + mi * 16 + lhalf) * A_STRIDE_H + k0 + lsel8) * 2u);
            #pragma unroll
            for (int nc = 0; nc < 4; nc++)
                ldmatrix_x4_trans(bf[nc], bbase +
                    (uint32_t)((k0 + lhalf) * B_STRIDE_H + wnb + nc * 16 + lsel8) * 2u);
            #pragma unroll
            for (int mi = 0; mi < 4; mi++)
                #pragma unroll
                for (int nc = 0; nc < 4; nc++) {
                    mma_f16(acc[mi][2 * nc + 0], af[mi], &bf[nc][0]);
                    mma_f16(acc[mi][2 * nc + 1], af[mi], &bf[nc][2]);
                }
        }
        if (++stage == STAGES) stage = 0;
        if (++wstage == STAGES) wstage = 0;
    }

    #pragma unroll
    for (int mi = 0; mi < 4; mi++) {
        #pragma unroll
        for (int h = 0; h < 2; h++) {
            int rl = wmb + mi * 16 + g + 8 * h;
            if (GROUPED && rl >= rows) continue;
            if (MODE == 2) {
                int d = rowmap[row_start + rl];
                float scale = rowscale[d];
                float* dst = CoutF + (size_t)(d / TOPK) * N;
                #pragma unroll
                for (int ni = 0; ni < 8; ni++) {
                    int col = n0 + wnb + ni * 8 + 2 * tig;
                    red_add_v2(dst + col,
                               acc[mi][ni][2 * h + 0] * scale,
                               acc[mi][ni][2 * h + 1] * scale);
                }
            } else {
                float* dst = CoutF + (size_t)(row_start + rl) * N;
                #pragma unroll
                for (int ni = 0; ni < 8; ni++) {
                    int col = n0 + wnb + ni * 8 + 2 * tig;
                    float2 v;
                    v.x = acc[mi][ni][2 * h + 0];
                    v.y = acc[mi][ni][2 * h + 1];
                    *(float2*)(dst + col) = v;
                }
            }
        }
    }
}

// ---------------- launch ----------------
extern "C" void kernel_launch(void* const* d_in, const int* in_sizes, int n_in,
                              void* d_out, int out_size) {
    const float* x        = (const float*)d_in[0];
    const float* router_w = (const float*)d_in[1];
    const float* e_bias   = (const float*)d_in[2];
    const float* gate_w   = (const float*)d_in[3];
    const float* up_w     = (const float*)d_in[4];
    const float* down_w   = (const float*)d_in[5];
    const float* sh_gate  = (const float*)d_in[6];
    const float* sh_up    = (const float*)d_in[7];
    const float* sh_down  = (const float*)d_in[8];
    float* out = (float*)d_out;

    __half *p_hbuf, *p_sh_h, *p_x_r;
    __half *p_w_gate, *p_w_up, *p_w_down, *p_w_shg, *p_w_shu, *p_w_shd;
    float *p_topk_w, *p_scores;
    int* p_rowmap;
    cudaGetSymbolAddress((void**)&p_hbuf,     g_hbuf);
    cudaGetSymbolAddress((void**)&p_sh_h,     g_sh_h);
    cudaGetSymbolAddress((void**)&p_topk_w,   g_topk_w);
    cudaGetSymbolAddress((void**)&p_rowmap,   g_rowmap);
    cudaGetSymbolAddress((void**)&p_x_r,      g_x_r);
    cudaGetSymbolAddress((void**)&p_scores,   g_scores);
    cudaGetSymbolAddress((void**)&p_w_gate,   g_w_gate);
    cudaGetSymbolAddress((void**)&p_w_up,     g_w_up);
    cudaGetSymbolAddress((void**)&p_w_down,   g_w_down);
    cudaGetSymbolAddress((void**)&p_w_shg,    g_w_shg);
    cudaGetSymbolAddress((void**)&p_w_shu,    g_w_shu);
    cudaGetSymbolAddress((void**)&p_w_shd,    g_w_shd);

    cudaFuncSetAttribute((const void*)gu_gemm<false, false>,
                         cudaFuncAttributeMaxDynamicSharedMemorySize, GEMM_SMEM_BYTES);
    cudaFuncSetAttribute((const void*)gu_gemm<true, true>,
                         cudaFuncAttributeMaxDynamicSharedMemorySize, GEMM_SMEM_BYTES);
    cudaFuncSetAttribute((const void*)mma_gemm<false, 0>,
                         cudaFuncAttributeMaxDynamicSharedMemorySize, GEMM_SMEM_BYTES);
    cudaFuncSetAttribute((const void*)mma_gemm<true, 2>,
                         cudaFuncAttributeMaxDynamicSharedMemorySize, GEMM_SMEM_BYTES);
    int score_smem = SCORE_TOK * XS_STRIDE * 4;
    cudaFuncSetAttribute((const void*)score_kernel,
                         cudaFuncAttributeMaxDynamicSharedMemorySize, score_smem);

    // one-time side stream + events (created OUTSIDE graph capture)
    static cudaStream_t s_side = nullptr;
    static cudaEvent_t s_fork, s_xr, s_join;
    if (!s_side) {
        cudaStreamCreateWithFlags(&s_side, cudaStreamNonBlocking);
        cudaEventCreateWithFlags(&s_fork, cudaEventDisableTiming);
        cudaEventCreateWithFlags(&s_xr,   cudaEventDisableTiming);
        cudaEventCreateWithFlags(&s_join, cudaEventDisableTiming);
    }

    long long n4;

    // ---- fork ----
    cudaEventRecord(s_fork, 0);
    cudaStreamWaitEvent(s_side, s_fork, 0);

    // ===== SIDE STREAM: routing + expert weight conversion =====
    score_kernel<<<dim3(EXP / 16, S_TOK / SCORE_TOK), 256, score_smem, s_side>>>(
        x, router_w, p_scores);
    select_kernel<<<SEL_NBLK, SEL_BLK, 0, s_side>>>(p_scores, e_bias);
    {
        long long total = 3LL << EW_N4_SHIFT;
        half_copy3<<<(unsigned)(total / 256), 256, 0, s_side>>>(
            (const float4*)gate_w, (const float4*)up_w, (const float4*)down_w,
            (__half2*)p_w_gate, (__half2*)p_w_up, (__half2*)p_w_down);
    }
    setup_kernel<<<1, 64, 0, s_side>>>();
    assign_kernel<<<NROWS / 256, 256, 0, s_side>>>();

    // ===== MAIN STREAM: conversions for the shared expert =====
    n4 = (long long)CDIM * HSHARED / 4;
    half_copy<<<(unsigned)((n4 + 255) / 256), 256>>>((const float4*)sh_gate, (__half2*)p_w_shg, n4);
    half_copy<<<(unsigned)((n4 + 255) / 256), 256>>>((const float4*)sh_up,   (__half2*)p_w_shu, n4);
    n4 = (long long)S_TOK * CDIM / 4;
    half_copy<<<(unsigned)((n4 + 255) / 256), 256>>>((const float4*)x, (__half2*)p_x_r, n4);
    cudaEventRecord(s_xr, 0);
    n4 = (long long)CDIM * HSHARED / 4;
    half_copy<<<(unsigned)((n4 + 255) / 256), 256>>>((const float4*)sh_down, (__half2*)p_w_shd, n4);

    // side: routed gu GEMM (needs x_r from main + weights/assign from side)
    cudaStreamWaitEvent(s_side, s_xr, 0);
    gu_gemm<true, true><<<dim3(HDIM / 64, MAX_TILES), GEMM_THREADS, GEMM_SMEM_BYTES, s_side>>>(
        p_x_r, p_w_gate, p_w_up, p_hbuf, CDIM, HDIM, (long long)CDIM * HDIM);
    cudaEventRecord(s_join, s_side);

    // main: shared expert GEMMs (overlap with routed gu on side)
    gu_gemm<false, false><<<dim3(HSHARED / 64, S_TOK / 128), GEMM_THREADS, GEMM_SMEM_BYTES>>>(
        p_x_r, p_w_shg, p_w_shu, p_sh_h, CDIM, HSHARED, 0);
    mma_gemm<false, 0><<<dim3(CDIM / 128, S_TOK / 128), GEMM_THREADS, GEMM_SMEM_BYTES>>>(
        p_sh_h, p_w_shd, out, HSHARED, CDIM, 0, nullptr, nullptr);

    // ---- join: routed down needs hbuf (side) and out written (main) ----
    cudaStreamWaitEvent(0, s_join, 0);
    mma_gemm<true, 2><<<dim3(CDIM / 128, MAX_TILES), GEMM_THREADS, GEMM_SMEM_BYTES>>>(
        p_hbuf, p_w_down, out, HDIM, CDIM, (long long)HDIM * CDIM,
        p_rowmap, p_topk_w);
}